// round 7
// baseline (speedup 1.0000x reference)
#include <cuda_runtime.h>
#include <math.h>

typedef unsigned long long u64;

__device__ __forceinline__ u64 pk2(float v) {
    u64 r; asm("mov.b64 %0, {%1,%1};" : "=l"(r) : "f"(v)); return r;
}
__device__ __forceinline__ void fma2(u64& d, u64 a, u64 b) {
    asm("fma.rn.f32x2 %0, %1, %2, %0;" : "+l"(d) : "l"(a), "l"(b));
}
__device__ __forceinline__ float2 upk(u64 v) {
    float2 r; asm("mov.b64 {%0,%1}, %2;" : "=f"(r.x), "=f"(r.y) : "l"(v)); return r;
}
__device__ __forceinline__ u64 add2(u64 a, u64 b) {
    u64 r; asm("add.rn.f32x2 %0, %1, %2;" : "=l"(r) : "l"(a), "l"(b)); return r;
}

// ---------------- scratch (device globals: allocation-free) ------------------
__device__ float g_A [16*64*128*128];   // 67 MB
__device__ float g_B [16*128*64*64];    // 33.5 MB
__device__ float g_B2[16*128*64*64];    // 33.5 MB
__device__ float g_C [16*128*64*64];    // 33.5 MB
__device__ float g_D [16*32*64*64];     // 8.4 MB
__device__ float g_E [16*64*64*64];     // 16.8 MB (z_e)
__device__ float g_F [16*64*64*64];     // 16.8 MB (z_q)
__device__ float g_part[1024];

// ---------------- generic direct conv (f32x2, sliding window, PX px/thread) ---
// thread: PX out-x x 8 out-channels (4 c-pairs). block 128 threads covers
// 64 out-x by (128*PX/64) rows. smem weights: [(ci*KK+kk)*8 + c].
template<int K, int STRIDE, bool RELU_IN, bool TRANSPOSED, int PX>
__global__ void __launch_bounds__(128) conv_fwd(
    const float* __restrict__ in, const float* __restrict__ w,
    const float* __restrict__ bias, const float* __restrict__ resid,
    float* __restrict__ out,
    int CIN, int COUT, int H, int W, int OH, int OW, int PAD, int cgroups,
    int relu_out)
{
    constexpr int KK = K * K;
    constexpr int CICH = (K == 4) ? 64 : 128;
    constexpr int SPAN = (PX - 1) * STRIDE + K;   // input window per ky
    constexpr int XG   = 64 / PX;                 // thread-groups in x
    constexpr int ROWS = 128 / XG;                // rows per block
    __shared__ __align__(16) float sw[CICH * KK * 8];

    int t   = threadIdx.x;
    int tx  = t & (XG - 1), ty = t / XG;
    int ox0 = blockIdx.x * 64 + tx * PX;
    int oy  = blockIdx.y * ROWS + ty;
    int n   = blockIdx.z / cgroups;
    int co0 = (blockIdx.z % cgroups) * 8;
    int ixbase = ox0 * STRIDE - PAD;

    u64 acc2[4][PX];
#pragma unroll
    for (int cp = 0; cp < 4; cp++)
#pragma unroll
        for (int p = 0; p < PX; p++) acc2[cp][p] = 0ull;

    for (int ci0 = 0; ci0 < CIN; ci0 += CICH) {
        int cich = min(CICH, CIN - ci0);
        int nw = cich * KK * 8;
        __syncthreads();
        for (int i = t; i < nw; i += 128) {
            int c  = i & 7;
            int r  = i >> 3;            // ci*KK + kk
            int ci = r / KK;
            int kk = r - ci * KK;
            int ky = kk / K, kx = kk - ky * K;
            int co = co0 + c;
            float v = 0.f;
            if (co < COUT) {
                if (TRANSPOSED)
                    v = w[(((ci0 + ci) * COUT + co) * K + (K - 1 - ky)) * K + (K - 1 - kx)];
                else
                    v = w[((co * CIN + (ci0 + ci)) * K + ky) * K + kx];
            }
            sw[i] = v;
        }
        __syncthreads();

        const float* inb = in + (n * CIN + ci0) * H * W;
        for (int ci = 0; ci < cich; ci++) {
            const float* inc = inb + ci * H * W;
            const float* wci = sw + ci * KK * 8;
#pragma unroll
            for (int ky = 0; ky < K; ky++) {
                int iy = oy * STRIDE - PAD + ky;
                if ((unsigned)iy >= (unsigned)H) continue;
                const float* rowp = inc + iy * W + ixbase;
                u64 ivs[SPAN];
#pragma unroll
                for (int q = 0; q < SPAN; q++) {
                    int ix = ixbase + q;
                    float v = ((unsigned)ix < (unsigned)W) ? __ldg(rowp + q) : 0.f;
                    if (RELU_IN) v = fmaxf(v, 0.f);
                    ivs[q] = pk2(v);
                }
#pragma unroll
                for (int kx = 0; kx < K; kx++) {
                    const float* wp = wci + (ky * K + kx) * 8;
#pragma unroll
                    for (int cp = 0; cp < 4; cp++) {
                        u64 wv2 = *(const u64*)(wp + cp * 2);
#pragma unroll
                        for (int p = 0; p < PX; p++)
                            fma2(acc2[cp][p], ivs[p * STRIDE + kx], wv2);
                    }
                }
            }
        }
    }

#pragma unroll
    for (int cp = 0; cp < 4; cp++) {
        float2 v[PX];
#pragma unroll
        for (int p = 0; p < PX; p++) v[p] = upk(acc2[cp][p]);
#pragma unroll
        for (int h2 = 0; h2 < 2; h2++) {
            int co = co0 + cp * 2 + h2;
            if (co >= COUT) continue;
            float b = bias ? __ldg(bias + co) : 0.f;
            int ob = ((n * COUT + co) * OH + oy) * OW + ox0;
#pragma unroll
            for (int p = 0; p < PX; p++) {
                float val = (h2 ? v[p].y : v[p].x) + b;
                if (resid) val += resid[ob + p];
                if (relu_out) val = fmaxf(val, 0.f);
                out[ob + p] = val;
            }
        }
    }
}

// ---------------- transposed conv, stride 2, K=4, pad 1 (f32x2, 8 px) ---------
// gather form, parity-direct taps. weight [ci][co][ky][kx] (unflipped).
// thread: 8 out-x of one parity (16 consecutive cols), 8 couts.
__global__ void __launch_bounds__(128) convt_s2(
    const float* __restrict__ in, const float* __restrict__ w,
    const float* __restrict__ bias, float* __restrict__ out,
    int CIN, int COUT, int H, int W, int cgroups, int relu_in, int relu_out)
{
    __shared__ __align__(16) float sw[64 * 16 * 8];  // [(ci*16+kk)*8 + c]
    int t = threadIdx.x;
    int tx = t & 7, tyv = t >> 3;                    // 8 x-groups, 16 rows
    int parity = blockIdx.x & 1;
    int xch    = blockIdx.x >> 1;
    int OH = 2 * H, OW = 2 * W;
    int ox0 = xch * 128 + 16 * tx + parity;          // outputs ox0 + 2p, p=0..7
    int oy  = blockIdx.y * 16 + tyv;
    int n   = blockIdx.z / cgroups;
    int co0 = (blockIdx.z % cgroups) * 8;

    int kyp = (oy + 1) & 1;        // valid ky: kyp, kyp+2
    int kxp = (ox0 + 1) & 1;       // valid kx: kxp, kxp+2
    int ixw = ((ox0 + 1 - kxp) >> 1) - 1;  // window start (9 floats)

    u64 acc2[4][8];
#pragma unroll
    for (int cp = 0; cp < 4; cp++)
#pragma unroll
        for (int p = 0; p < 8; p++) acc2[cp][p] = 0ull;

    for (int ci0 = 0; ci0 < CIN; ci0 += 64) {
        int cich = min(64, CIN - ci0);
        int nw = cich * 16 * 8;
        __syncthreads();
        for (int i = t; i < nw; i += 128) {
            int c  = i & 7;
            int r  = i >> 3;
            int ci = r >> 4;
            int kk = r & 15;
            int co = co0 + c;
            sw[i] = (co < COUT) ? w[((ci0 + ci) * COUT + co) * 16 + kk] : 0.f;
        }
        __syncthreads();

        for (int ci = 0; ci < cich; ci++) {
            const float* inc = in + (n * CIN + ci0 + ci) * H * W;
            const float* wci = sw + ci * 16 * 8;
#pragma unroll
            for (int ky2 = 0; ky2 < 2; ky2++) {
                int ky = kyp + 2 * ky2;
                int iy = (oy + 1 - ky) >> 1;
                if ((unsigned)iy >= (unsigned)H) continue;
                const float* rowp = inc + iy * W + ixw;
                u64 ivs[9];
#pragma unroll
                for (int q = 0; q < 9; q++) {
                    int ix = ixw + q;
                    float v = ((unsigned)ix < (unsigned)W) ? __ldg(rowp + q) : 0.f;
                    if (relu_in) v = fmaxf(v, 0.f);
                    ivs[q] = pk2(v);
                }
#pragma unroll
                for (int kx2 = 0; kx2 < 2; kx2++) {
                    int kx  = kxp + 2 * kx2;
                    int ofs = 1 - kx2;
                    const float* wp = wci + (ky * 4 + kx) * 8;
#pragma unroll
                    for (int cp = 0; cp < 4; cp++) {
                        u64 wv2 = *(const u64*)(wp + cp * 2);
#pragma unroll
                        for (int p = 0; p < 8; p++)
                            fma2(acc2[cp][p], ivs[ofs + p], wv2);
                    }
                }
            }
        }
    }

#pragma unroll
    for (int cp = 0; cp < 4; cp++) {
        float2 v[8];
#pragma unroll
        for (int p = 0; p < 8; p++) v[p] = upk(acc2[cp][p]);
#pragma unroll
        for (int h2 = 0; h2 < 2; h2++) {
            int co = co0 + cp * 2 + h2;
            if (co >= COUT) continue;
            float b = bias ? __ldg(bias + co) : 0.f;
#pragma unroll
            for (int p = 0; p < 8; p++) {
                int ox = ox0 + 2 * p;
                int o = ((n * COUT + co) * OH + oy) * OW + ox;
                float val = (h2 ? v[p].y : v[p].x) + b;
                if (relu_out) val = fmaxf(val, 0.f);
                out[o] = val;
            }
        }
    }
}

// ---------------- fused decoder residual iteration ----------------------------
// x_out = x_in + W2 * relu(W1 (*) relu(x_in)), W1:[2,128,3,3], W2:[128,2,1,1]
__global__ void __launch_bounds__(256) decres_fused(
    const float* __restrict__ xin, const float* __restrict__ w1,
    const float* __restrict__ w2, float* __restrict__ xout)
{
    __shared__ __align__(8) float sw1[2304];     // [(ci*9+k)*2 + ch]
    __shared__ float sw2[256];
    __shared__ u64  part[1024];                  // [half][wg][p]
    __shared__ __align__(16) float h_s[2][8][64];

    int t    = threadIdx.x;
    int half = t >> 7, wg = t & 127;
    int by = blockIdx.x;            // 0..7 (8-row stripe)
    int n  = blockIdx.y;            // 0..15
    for (int i = t; i < 2304; i += 256) {
        int ch = i & 1, r = i >> 1;              // r = ci*9+k
        sw1[i] = w1[ch * 1152 + r];
    }
    if (t < 256) sw2[t] = w2[t];
    __syncthreads();

    int tx = wg & 15, tyv = wg >> 4;
    int ox0 = tx * 4;
    int oy  = by * 8 + tyv;
    u64 a2[4] = {0ull, 0ull, 0ull, 0ull};
    const float* xb = xin + (n * 128 + half * 64) * 4096;
    for (int ci = 0; ci < 64; ci++) {
        const float* inc = xb + ci * 4096;
        const float* wci = sw1 + (half * 64 + ci) * 18;
#pragma unroll
        for (int ky = 0; ky < 3; ky++) {
            int iy = oy - 1 + ky;
            if ((unsigned)iy >= 64u) continue;
            const float* rowp = inc + iy * 64 + ox0 - 1;
            u64 ivs[6];
#pragma unroll
            for (int q = 0; q < 6; q++) {
                int ix = ox0 - 1 + q;
                float v = ((unsigned)ix < 64u) ? __ldg(rowp + q) : 0.f;
                ivs[q] = pk2(fmaxf(v, 0.f));
            }
#pragma unroll
            for (int kx = 0; kx < 3; kx++) {
                u64 wv2 = *(const u64*)(wci + (ky * 3 + kx) * 2);
#pragma unroll
                for (int p = 0; p < 4; p++)
                    fma2(a2[p], ivs[p + kx], wv2);
            }
        }
    }
#pragma unroll
    for (int p = 0; p < 4; p++) part[(half * 128 + wg) * 4 + p] = a2[p];
    __syncthreads();

    for (int i = t; i < 512; i += 256) {
        u64 s = add2(part[i], part[512 + i]);
        float2 v = upk(s);
        int wi = i >> 2, p = i & 3;
        int row = wi >> 4, x = (wi & 15) * 4 + p;
        h_s[0][row][x] = fmaxf(v.x, 0.f);
        h_s[1][row][x] = fmaxf(v.y, 0.f);
    }
    __syncthreads();

    int rowbase = by * 8;
    const float4* xin4 = (const float4*)xin;
    float4* xout4 = (float4*)xout;
#pragma unroll 4
    for (int it = 0; it < 64; it++) {
        int e = it * 256 + t;
        int x4 = e & 15, row = (e >> 4) & 7, co = e >> 7;
        int gi = ((n * 128 + co) * 64 + rowbase + row) * 16 + x4;
        float4 v = xin4[gi];
        float w0 = sw2[co * 2], w1v = sw2[co * 2 + 1];
        const float* h0 = &h_s[0][row][x4 * 4];
        const float* h1 = &h_s[1][row][x4 * 4];
        v.x += w0 * h0[0] + w1v * h1[0];
        v.y += w0 * h0[1] + w1v * h1[1];
        v.z += w0 * h0[2] + w1v * h1[2];
        v.w += w0 * h0[3] + w1v * h1[3];
        xout4[gi] = v;
    }
}

// ---------------- vector quantizer -------------------------------------------
__global__ void __launch_bounds__(256) vq_kernel(
    const float* __restrict__ ze, const float* __restrict__ cb,
    float* __restrict__ zq, float* __restrict__ partials)
{
    __shared__ __align__(16) float f_s[64 * 64];    // [d][x]
    __shared__ __align__(16) float cb_s[64 * 68];   // [d][code] padded
    __shared__ float norm_s[512];
    __shared__ int   idx_s[64];
    __shared__ float red_s[64];

    int t = threadIdx.x;
    int b = blockIdx.x;
    int n = b >> 6, y = b & 63;

    for (int i = t; i < 4096; i += 256) {
        int d = i >> 6, x = i & 63;
        f_s[i] = ze[((n * 64 + d) * 64 + y) * 64 + x];
    }
    for (int c = t; c < 512; c += 256) {
        float s = 0.f;
        const float* cp = cb + c * 64;
#pragma unroll 8
        for (int d = 0; d < 64; d++) { float v = __ldg(cp + d); s = fmaf(v, v, s); }
        norm_s[c] = s;
    }
    __syncthreads();

    int cxT = t & 15, pyT = t >> 4;
    float best[4] = {3.4e38f, 3.4e38f, 3.4e38f, 3.4e38f};
    int   bidx[4] = {0, 0, 0, 0};

    for (int ch = 0; ch < 8; ch++) {
        __syncthreads();
        for (int i = t; i < 4096; i += 256) {
            int d = i & 63, c = i >> 6;
            cb_s[d * 68 + c] = __ldg(&cb[(ch * 64 + c) * 64 + d]);
        }
        __syncthreads();

        float dot[4][4];
#pragma unroll
        for (int pp = 0; pp < 4; pp++)
#pragma unroll
            for (int cc = 0; cc < 4; cc++) dot[pp][cc] = 0.f;

        for (int d = 0; d < 64; d++) {
            float4 fv4 = *(const float4*)&f_s[d * 64 + pyT * 4];
            float4 cv4 = *(const float4*)&cb_s[d * 68 + cxT * 4];
            float fv[4] = {fv4.x, fv4.y, fv4.z, fv4.w};
            float cv[4] = {cv4.x, cv4.y, cv4.z, cv4.w};
#pragma unroll
            for (int pp = 0; pp < 4; pp++)
#pragma unroll
                for (int cc = 0; cc < 4; cc++)
                    dot[pp][cc] = fmaf(fv[pp], cv[cc], dot[pp][cc]);
        }
#pragma unroll
        for (int cc = 0; cc < 4; cc++) {
            int code = ch * 64 + cxT * 4 + cc;
            float nrm = norm_s[code];
#pragma unroll
            for (int pp = 0; pp < 4; pp++) {
                float dist = fmaf(-2.f, dot[pp][cc], nrm);
                if (dist < best[pp]) { best[pp] = dist; bidx[pp] = code; }
            }
        }
    }

    for (int off = 1; off < 16; off <<= 1) {
#pragma unroll
        for (int pp = 0; pp < 4; pp++) {
            float ob = __shfl_xor_sync(0xffffffffu, best[pp], off);
            int   oi = __shfl_xor_sync(0xffffffffu, bidx[pp], off);
            if (ob < best[pp] || (ob == best[pp] && oi < bidx[pp])) {
                best[pp] = ob; bidx[pp] = oi;
            }
        }
    }
    if (cxT == 0)
#pragma unroll
        for (int pp = 0; pp < 4; pp++) idx_s[pyT * 4 + pp] = bidx[pp];
    __syncthreads();

    for (int i = t; i < 4096; i += 256) {
        int d = i >> 6, x = i & 63;
        zq[((n * 64 + d) * 64 + y) * 64 + x] = __ldg(&cb[idx_s[x] * 64 + d]);
    }

    if (t < 64) {
        int id = idx_s[t];
        const float* cp = cb + id * 64;
        float s = 0.f;
#pragma unroll 8
        for (int d = 0; d < 64; d++) {
            float diff = __ldg(cp + d) - f_s[d * 64 + t];
            s = fmaf(diff, diff, s);
        }
        red_s[t] = s;
    }
    __syncthreads();
    if (t == 0) {
        float s = 0.f;
        for (int i = 0; i < 64; i++) s += red_s[i];
        partials[b] = s;
    }
}

__global__ void __launch_bounds__(256) finalize_loss(
    const float* __restrict__ partials, float* __restrict__ dst)
{
    __shared__ float s[256];
    int t = threadIdx.x;
    float v = 0.f;
    for (int i = t; i < 1024; i += 256) v += partials[i];
    s[t] = v;
    __syncthreads();
    for (int off = 128; off > 0; off >>= 1) {
        if (t < off) s[t] += s[t + off];
        __syncthreads();
    }
    if (t == 0) dst[0] = 1.25f * s[0] / 4194304.f;  // (1 + BETA) * MSE
}

// ---------------- host launcher ----------------------------------------------
extern "C" void kernel_launch(void* const* d_in, const int* in_sizes, int n_in,
                              void* d_out, int out_size)
{
    (void)in_sizes; (void)n_in; (void)out_size;
    const float* x       = (const float*)d_in[0];
    const float* enc_w1  = (const float*)d_in[1];
    const float* enc_b1  = (const float*)d_in[2];
    const float* enc_w2  = (const float*)d_in[3];
    const float* enc_b2  = (const float*)d_in[4];
    const float* enc_w3  = (const float*)d_in[5];
    const float* enc_b3  = (const float*)d_in[6];
    const float* enc_rw1 = (const float*)d_in[7];
    const float* enc_rw2 = (const float*)d_in[8];
    const float* pre_w   = (const float*)d_in[9];
    const float* pre_b   = (const float*)d_in[10];
    const float* cb      = (const float*)d_in[11];
    const float* dec_wt1 = (const float*)d_in[12];
    const float* dec_bt1 = (const float*)d_in[13];
    const float* dec_rw1 = (const float*)d_in[14];
    const float* dec_rw2 = (const float*)d_in[15];
    const float* dec_wt2 = (const float*)d_in[16];
    const float* dec_bt2 = (const float*)d_in[17];
    const float* dec_wt3 = (const float*)d_in[18];
    const float* dec_bt3 = (const float*)d_in[19];
    float* out = (float*)d_out;

    float *pA, *pB, *pB2, *pC, *pD, *pE, *pF, *pPart;
    cudaGetSymbolAddress((void**)&pA,  g_A);
    cudaGetSymbolAddress((void**)&pB,  g_B);
    cudaGetSymbolAddress((void**)&pB2, g_B2);
    cudaGetSymbolAddress((void**)&pC,  g_C);
    cudaGetSymbolAddress((void**)&pD,  g_D);
    cudaGetSymbolAddress((void**)&pE,  g_E);
    cudaGetSymbolAddress((void**)&pF,  g_F);
    cudaGetSymbolAddress((void**)&pPart, g_part);

    // encoder
    conv_fwd<4,2,false,false,4><<<dim3(2,16,16*8), 128>>>(
        x, enc_w1, enc_b1, nullptr, pA, 3, 64, 256, 256, 128, 128, 1, 8, 1);
    conv_fwd<4,2,false,false,4><<<dim3(1,8,16*16), 128>>>(
        pA, enc_w2, enc_b2, nullptr, pB, 64, 128, 128, 128, 64, 64, 1, 16, 1);
    conv_fwd<3,1,false,false,8><<<dim3(1,4,16*16), 128>>>(
        pB, enc_w3, enc_b3, nullptr, pC, 128, 128, 64, 64, 64, 64, 1, 16, 0);
    for (int i = 0; i < 2; i++) {
        conv_fwd<3,1,true,false,8><<<dim3(1,4,16*4), 128>>>(
            pC, enc_rw1, nullptr, nullptr, pD, 128, 32, 64, 64, 64, 64, 1, 4, 1);
        conv_fwd<1,1,false,false,8><<<dim3(1,4,16*16), 128>>>(
            pD, enc_rw2, nullptr, pC, pC, 32, 128, 64, 64, 64, 64, 0, 16, 0);
    }
    conv_fwd<1,1,true,false,8><<<dim3(1,4,16*8), 128>>>(
        pC, pre_w, pre_b, nullptr, pE, 128, 64, 64, 64, 64, 64, 0, 8, 0);

    // quantizer
    vq_kernel<<<1024, 256>>>(pE, cb, pF, pPart);
    finalize_loss<<<1, 256>>>(pPart, out + 3145728);

    // decoder
    conv_fwd<3,1,false,true,8><<<dim3(1,4,16*16), 128>>>(
        pF, dec_wt1, dec_bt1, nullptr, pB, 64, 128, 64, 64, 64, 64, 1, 16, 0);
    for (int i = 0; i < 32; i++) {
        const float* src = (i & 1) ? pB2 : pB;
        float*       dst = (i & 1) ? pB  : pB2;
        decres_fused<<<dim3(8,16), 256>>>(src, dec_rw1, dec_rw2, dst);
    }
    // after 32 iters result is back in pB
    convt_s2<<<dim3(2,8,16*8), 128>>>(
        pB, dec_wt2, dec_bt2, pA, 128, 64, 64, 64, 8, 1, 1);
    convt_s2<<<dim3(4,16,16*1), 128>>>(
        pA, dec_wt3, dec_bt3, out, 64, 3, 128, 128, 1, 0, 0);
}

// round 8
// speedup vs baseline: 1.2615x; 1.2615x over previous
#include <cuda_runtime.h>
#include <math.h>

typedef unsigned long long u64;

__device__ __forceinline__ u64 pk2(float v) {
    u64 r; asm("mov.b64 %0, {%1,%1};" : "=l"(r) : "f"(v)); return r;
}
__device__ __forceinline__ void fma2(u64& d, u64 a, u64 b) {
    asm("fma.rn.f32x2 %0, %1, %2, %0;" : "+l"(d) : "l"(a), "l"(b));
}
__device__ __forceinline__ float2 upk(u64 v) {
    float2 r; asm("mov.b64 {%0,%1}, %2;" : "=f"(r.x), "=f"(r.y) : "l"(v)); return r;
}
__device__ __forceinline__ u64 add2(u64 a, u64 b) {
    u64 r; asm("add.rn.f32x2 %0, %1, %2;" : "=l"(r) : "l"(a), "l"(b)); return r;
}

// ---------------- scratch (device globals: allocation-free) ------------------
__device__ float g_A [16*64*128*128];   // 67 MB
__device__ float g_B [16*128*64*64];    // 33.5 MB
__device__ float g_B2[16*128*64*64];    // 33.5 MB
__device__ float g_C [16*128*64*64];    // 33.5 MB
__device__ float g_D [16*32*64*64];     // 8.4 MB
__device__ float g_E [16*64*64*64];     // 16.8 MB (z_e)
__device__ float g_F [16*64*64*64];     // 16.8 MB (z_q)
__device__ float g_part[1024];

// ---------------- generic direct conv (f32x2, sliding window, 4 px/thread) ----
template<int K, int STRIDE, bool RELU_IN, bool TRANSPOSED>
__global__ void __launch_bounds__(128) conv_fwd(
    const float* __restrict__ in, const float* __restrict__ w,
    const float* __restrict__ bias, const float* __restrict__ resid,
    float* __restrict__ out,
    int CIN, int COUT, int H, int W, int OH, int OW, int PAD, int cgroups,
    int relu_out)
{
    constexpr int KK = K * K;
    constexpr int CICH = (K == 4) ? 64 : 128;
    constexpr int SPAN = 3 * STRIDE + K;
    __shared__ __align__(16) float sw[CICH * KK * 8];

    int t   = threadIdx.x;
    int tx  = t & 15, ty = t >> 4;
    int ox0 = blockIdx.x * 64 + tx * 4;
    int oy  = blockIdx.y * 8 + ty;
    int n   = blockIdx.z / cgroups;
    int co0 = (blockIdx.z % cgroups) * 8;
    int ixbase = ox0 * STRIDE - PAD;

    u64 acc2[4][4];
#pragma unroll
    for (int cp = 0; cp < 4; cp++)
#pragma unroll
        for (int p = 0; p < 4; p++) acc2[cp][p] = 0ull;

    for (int ci0 = 0; ci0 < CIN; ci0 += CICH) {
        int cich = min(CICH, CIN - ci0);
        int nw = cich * KK * 8;
        __syncthreads();
        for (int i = t; i < nw; i += 128) {
            int c  = i & 7;
            int r  = i >> 3;
            int ci = r / KK;
            int kk = r - ci * KK;
            int ky = kk / K, kx = kk - ky * K;
            int co = co0 + c;
            float v = 0.f;
            if (co < COUT) {
                if (TRANSPOSED)
                    v = w[(((ci0 + ci) * COUT + co) * K + (K - 1 - ky)) * K + (K - 1 - kx)];
                else
                    v = w[((co * CIN + (ci0 + ci)) * K + ky) * K + kx];
            }
            sw[i] = v;
        }
        __syncthreads();

        const float* inb = in + (n * CIN + ci0) * H * W;
        for (int ci = 0; ci < cich; ci++) {
            const float* inc = inb + ci * H * W;
            const float* wci = sw + ci * KK * 8;
#pragma unroll
            for (int ky = 0; ky < K; ky++) {
                int iy = oy * STRIDE - PAD + ky;
                if ((unsigned)iy >= (unsigned)H) continue;
                const float* rowp = inc + iy * W + ixbase;
                u64 ivs[SPAN];
#pragma unroll
                for (int q = 0; q < SPAN; q++) {
                    int ix = ixbase + q;
                    float v = ((unsigned)ix < (unsigned)W) ? __ldg(rowp + q) : 0.f;
                    if (RELU_IN) v = fmaxf(v, 0.f);
                    ivs[q] = pk2(v);
                }
#pragma unroll
                for (int kx = 0; kx < K; kx++) {
                    const float* wp = wci + (ky * K + kx) * 8;
#pragma unroll
                    for (int cp = 0; cp < 4; cp++) {
                        u64 wv2 = *(const u64*)(wp + cp * 2);
#pragma unroll
                        for (int p = 0; p < 4; p++)
                            fma2(acc2[cp][p], ivs[p * STRIDE + kx], wv2);
                    }
                }
            }
        }
    }

#pragma unroll
    for (int cp = 0; cp < 4; cp++) {
        float2 v[4];
#pragma unroll
        for (int p = 0; p < 4; p++) v[p] = upk(acc2[cp][p]);
#pragma unroll
        for (int h2 = 0; h2 < 2; h2++) {
            int co = co0 + cp * 2 + h2;
            if (co >= COUT) continue;
            float b = bias ? __ldg(bias + co) : 0.f;
            int ob = ((n * COUT + co) * OH + oy) * OW + ox0;
#pragma unroll
            for (int p = 0; p < 4; p++) {
                float val = (h2 ? v[p].y : v[p].x) + b;
                if (resid) val += resid[ob + p];
                if (relu_out) val = fmaxf(val, 0.f);
                out[ob + p] = val;
            }
        }
    }
}

// ---------------- transposed conv, stride 2, K=4, pad 1 (f32x2) ---------------
__global__ void __launch_bounds__(128) convt_s2(
    const float* __restrict__ in, const float* __restrict__ w,
    const float* __restrict__ bias, float* __restrict__ out,
    int CIN, int COUT, int H, int W, int cgroups, int relu_in, int relu_out)
{
    __shared__ __align__(16) float sw[64 * 16 * 8];
    int t = threadIdx.x;
    int tx = t & 15, tyv = t >> 4;
    int parity = blockIdx.x & 1;
    int xch    = blockIdx.x >> 1;
    int OH = 2 * H, OW = 2 * W;
    int ox0 = xch * 128 + 8 * tx + parity;
    int oy  = blockIdx.y * 8 + tyv;
    int n   = blockIdx.z / cgroups;
    int co0 = (blockIdx.z % cgroups) * 8;

    int kyp = (oy + 1) & 1;
    int kxp = (ox0 + 1) & 1;
    int ixw = ((ox0 + 1 - kxp) >> 1) - 1;

    u64 acc2[4][4];
#pragma unroll
    for (int cp = 0; cp < 4; cp++)
#pragma unroll
        for (int p = 0; p < 4; p++) acc2[cp][p] = 0ull;

    for (int ci0 = 0; ci0 < CIN; ci0 += 64) {
        int cich = min(64, CIN - ci0);
        int nw = cich * 16 * 8;
        __syncthreads();
        for (int i = t; i < nw; i += 128) {
            int c  = i & 7;
            int r  = i >> 3;
            int ci = r >> 4;
            int kk = r & 15;
            int co = co0 + c;
            sw[i] = (co < COUT) ? w[((ci0 + ci) * COUT + co) * 16 + kk] : 0.f;
        }
        __syncthreads();

        for (int ci = 0; ci < cich; ci++) {
            const float* inc = in + (n * CIN + ci0 + ci) * H * W;
            const float* wci = sw + ci * 16 * 8;
#pragma unroll
            for (int ky2 = 0; ky2 < 2; ky2++) {
                int ky = kyp + 2 * ky2;
                int iy = (oy + 1 - ky) >> 1;
                if ((unsigned)iy >= (unsigned)H) continue;
                const float* rowp = inc + iy * W + ixw;
                u64 ivs[5];
#pragma unroll
                for (int q = 0; q < 5; q++) {
                    int ix = ixw + q;
                    float v = ((unsigned)ix < (unsigned)W) ? __ldg(rowp + q) : 0.f;
                    if (relu_in) v = fmaxf(v, 0.f);
                    ivs[q] = pk2(v);
                }
#pragma unroll
                for (int kx2 = 0; kx2 < 2; kx2++) {
                    int kx  = kxp + 2 * kx2;
                    int ofs = 1 - kx2;
                    const float* wp = wci + (ky * 4 + kx) * 8;
#pragma unroll
                    for (int cp = 0; cp < 4; cp++) {
                        u64 wv2 = *(const u64*)(wp + cp * 2);
#pragma unroll
                        for (int p = 0; p < 4; p++)
                            fma2(acc2[cp][p], ivs[ofs + p], wv2);
                    }
                }
            }
        }
    }

#pragma unroll
    for (int cp = 0; cp < 4; cp++) {
        float2 v[4];
#pragma unroll
        for (int p = 0; p < 4; p++) v[p] = upk(acc2[cp][p]);
#pragma unroll
        for (int h2 = 0; h2 < 2; h2++) {
            int co = co0 + cp * 2 + h2;
            if (co >= COUT) continue;
            float b = bias ? __ldg(bias + co) : 0.f;
#pragma unroll
            for (int p = 0; p < 4; p++) {
                int ox = ox0 + 2 * p;
                int o = ((n * COUT + co) * OH + oy) * OW + ox;
                float val = (h2 ? v[p].y : v[p].x) + b;
                if (relu_out) val = fmaxf(val, 0.f);
                out[o] = val;
            }
        }
    }
}

// ---------------- fused decoder residual iteration (smem-resident stripe) -----
// x_out = x_in + W2 * relu(W1 (*) relu(x_in)), W1:[2,128,3,3], W2:[128,2,1,1]
// Block: one 4-row stripe of one image. 256 threads. Dynamic smem:
//   xs   [128][6][64] floats  (stripe + halo, raw x)      196608 B @ 0
//   sw1  u64[1152]  ch-pair weights                          9216 B @ 196608
//   sw2  float[256]                                          1024 B @ 205824
//   part u64[768]   (3 groups x 4 rows x 64 px)              6144 B @ 206848
//   h0,h1 float[4][64]                                     2x1024 B @ 212992
#define DSM_TOTAL 215040

__global__ void __launch_bounds__(256) decres_fused(
    const float* __restrict__ xin, const float* __restrict__ w1,
    const float* __restrict__ w2, float* __restrict__ xout)
{
    extern __shared__ unsigned char smraw[];
    float*  xs    = (float*)smraw;
    float4* xs4   = (float4*)smraw;
    float*  sw1f  = (float*)(smraw + 196608);
    u64*    sw1u  = (u64*)  (smraw + 196608);
    float*  sw2   = (float*)(smraw + 205824);
    u64*    part  = (u64*)  (smraw + 206848);
    float*  h0    = (float*)(smraw + 212992);   // [4][64]
    float*  h1    = (float*)(smraw + 214016);   // [4][64]

    int t   = threadIdx.x;
    int by  = blockIdx.x;     // 0..15 stripe
    int n   = blockIdx.y;     // 0..15 image
    int oy0 = by * 4;

    // weights
    for (int i = t; i < 2304; i += 256) {
        int ch = i & 1, r = i >> 1;            // r = ci*9 + k
        sw1f[i] = w1[ch * 1152 + r];
    }
    if (t < 256) sw2[t] = w2[t];

    // stage x stripe (6 rows incl halo) for all 128 channels, float4 coalesced
    const float4* xin4 = (const float4*)(xin + n * 128 * 4096);
    for (int i = t; i < 12288; i += 256) {
        int x4 = i & 15;
        int rr = (i >> 4) % 6;
        int ci = i / 96;
        int gy = oy0 - 1 + rr;
        float4 v;
        if ((unsigned)gy < 64u) v = xin4[(ci * 64 + gy) * 16 + x4];
        else { v.x = v.y = v.z = v.w = 0.f; }
        xs4[i] = v;
    }
    __syncthreads();

    // phase 1: h[2ch][4r][64x], 4 ci-groups of 64 threads
    int g   = t >> 6;
    int t64 = t & 63;
    int row = t64 >> 4;
    int xg  = t64 & 15;

    u64 a[4] = {0ull, 0ull, 0ull, 0ull};
    for (int ci = g * 32; ci < g * 32 + 32; ci++) {
        const u64* wci = sw1u + ci * 9;
#pragma unroll
        for (int ky = 0; ky < 3; ky++) {
            float4 c = xs4[(ci * 6 + row + ky) * 16 + xg];
            float l = __shfl_up_sync(0xffffffffu, c.w, 1);
            float r = __shfl_down_sync(0xffffffffu, c.x, 1);
            if (xg == 0)  l = 0.f;
            if (xg == 15) r = 0.f;
            u64 pw[6];
            pw[0] = pk2(fmaxf(l,   0.f));
            pw[1] = pk2(fmaxf(c.x, 0.f));
            pw[2] = pk2(fmaxf(c.y, 0.f));
            pw[3] = pk2(fmaxf(c.z, 0.f));
            pw[4] = pk2(fmaxf(c.w, 0.f));
            pw[5] = pk2(fmaxf(r,   0.f));
#pragma unroll
            for (int kx = 0; kx < 3; kx++) {
                u64 wv = wci[ky * 3 + kx];
                fma2(a[0], pw[kx    ], wv);
                fma2(a[1], pw[kx + 1], wv);
                fma2(a[2], pw[kx + 2], wv);
                fma2(a[3], pw[kx + 3], wv);
            }
        }
    }
    if (g > 0) {
#pragma unroll
        for (int p = 0; p < 4; p++) part[(g - 1) * 256 + t64 * 4 + p] = a[p];
    }
    __syncthreads();
    if (t < 64) {
#pragma unroll
        for (int p = 0; p < 4; p++) {
            u64 s = a[p];
            s = add2(s, part[      t * 4 + p]);
            s = add2(s, part[256 + t * 4 + p]);
            s = add2(s, part[512 + t * 4 + p]);
            float2 v = upk(s);
            h0[row * 64 + xg * 4 + p] = fmaxf(v.x, 0.f);
            h1[row * 64 + xg * 4 + p] = fmaxf(v.y, 0.f);
        }
    }
    __syncthreads();

    // phase 2: x + W2*h from smem, write gmem (float4)
    float4* xout4 = (float4*)(xout + n * 128 * 4096);
#pragma unroll 4
    for (int k = 0; k < 32; k++) {
        int e   = k * 256 + t;
        int x4  = e & 15;
        int row2= (e >> 4) & 3;
        int co  = e >> 6;
        float4 v = xs4[(co * 6 + row2 + 1) * 16 + x4];
        float w0 = sw2[co * 2], w1v = sw2[co * 2 + 1];
        const float* p0 = h0 + row2 * 64 + x4 * 4;
        const float* p1 = h1 + row2 * 64 + x4 * 4;
        v.x += w0 * p0[0] + w1v * p1[0];
        v.y += w0 * p0[1] + w1v * p1[1];
        v.z += w0 * p0[2] + w1v * p1[2];
        v.w += w0 * p0[3] + w1v * p1[3];
        xout4[(co * 64 + oy0 + row2) * 16 + x4] = v;
    }
}

// ---------------- vector quantizer -------------------------------------------
__global__ void __launch_bounds__(256) vq_kernel(
    const float* __restrict__ ze, const float* __restrict__ cb,
    float* __restrict__ zq, float* __restrict__ partials)
{
    __shared__ __align__(16) float f_s[64 * 64];
    __shared__ __align__(16) float cb_s[64 * 68];
    __shared__ float norm_s[512];
    __shared__ int   idx_s[64];
    __shared__ float red_s[64];

    int t = threadIdx.x;
    int b = blockIdx.x;
    int n = b >> 6, y = b & 63;

    for (int i = t; i < 4096; i += 256) {
        int d = i >> 6, x = i & 63;
        f_s[i] = ze[((n * 64 + d) * 64 + y) * 64 + x];
    }
    for (int c = t; c < 512; c += 256) {
        float s = 0.f;
        const float* cp = cb + c * 64;
#pragma unroll 8
        for (int d = 0; d < 64; d++) { float v = __ldg(cp + d); s = fmaf(v, v, s); }
        norm_s[c] = s;
    }
    __syncthreads();

    int cxT = t & 15, pyT = t >> 4;
    float best[4] = {3.4e38f, 3.4e38f, 3.4e38f, 3.4e38f};
    int   bidx[4] = {0, 0, 0, 0};

    for (int ch = 0; ch < 8; ch++) {
        __syncthreads();
        for (int i = t; i < 4096; i += 256) {
            int d = i & 63, c = i >> 6;
            cb_s[d * 68 + c] = __ldg(&cb[(ch * 64 + c) * 64 + d]);
        }
        __syncthreads();

        float dot[4][4];
#pragma unroll
        for (int pp = 0; pp < 4; pp++)
#pragma unroll
            for (int cc = 0; cc < 4; cc++) dot[pp][cc] = 0.f;

        for (int d = 0; d < 64; d++) {
            float4 fv4 = *(const float4*)&f_s[d * 64 + pyT * 4];
            float4 cv4 = *(const float4*)&cb_s[d * 68 + cxT * 4];
            float fv[4] = {fv4.x, fv4.y, fv4.z, fv4.w};
            float cv[4] = {cv4.x, cv4.y, cv4.z, cv4.w};
#pragma unroll
            for (int pp = 0; pp < 4; pp++)
#pragma unroll
                for (int cc = 0; cc < 4; cc++)
                    dot[pp][cc] = fmaf(fv[pp], cv[cc], dot[pp][cc]);
        }
#pragma unroll
        for (int cc = 0; cc < 4; cc++) {
            int code = ch * 64 + cxT * 4 + cc;
            float nrm = norm_s[code];
#pragma unroll
            for (int pp = 0; pp < 4; pp++) {
                float dist = fmaf(-2.f, dot[pp][cc], nrm);
                if (dist < best[pp]) { best[pp] = dist; bidx[pp] = code; }
            }
        }
    }

    for (int off = 1; off < 16; off <<= 1) {
#pragma unroll
        for (int pp = 0; pp < 4; pp++) {
            float ob = __shfl_xor_sync(0xffffffffu, best[pp], off);
            int   oi = __shfl_xor_sync(0xffffffffu, bidx[pp], off);
            if (ob < best[pp] || (ob == best[pp] && oi < bidx[pp])) {
                best[pp] = ob; bidx[pp] = oi;
            }
        }
    }
    if (cxT == 0)
#pragma unroll
        for (int pp = 0; pp < 4; pp++) idx_s[pyT * 4 + pp] = bidx[pp];
    __syncthreads();

    for (int i = t; i < 4096; i += 256) {
        int d = i >> 6, x = i & 63;
        zq[((n * 64 + d) * 64 + y) * 64 + x] = __ldg(&cb[idx_s[x] * 64 + d]);
    }

    if (t < 64) {
        int id = idx_s[t];
        const float* cp = cb + id * 64;
        float s = 0.f;
#pragma unroll 8
        for (int d = 0; d < 64; d++) {
            float diff = __ldg(cp + d) - f_s[d * 64 + t];
            s = fmaf(diff, diff, s);
        }
        red_s[t] = s;
    }
    __syncthreads();
    if (t == 0) {
        float s = 0.f;
        for (int i = 0; i < 64; i++) s += red_s[i];
        partials[b] = s;
    }
}

__global__ void __launch_bounds__(256) finalize_loss(
    const float* __restrict__ partials, float* __restrict__ dst)
{
    __shared__ float s[256];
    int t = threadIdx.x;
    float v = 0.f;
    for (int i = t; i < 1024; i += 256) v += partials[i];
    s[t] = v;
    __syncthreads();
    for (int off = 128; off > 0; off >>= 1) {
        if (t < off) s[t] += s[t + off];
        __syncthreads();
    }
    if (t == 0) dst[0] = 1.25f * s[0] / 4194304.f;  // (1 + BETA) * MSE
}

// ---------------- host launcher ----------------------------------------------
extern "C" void kernel_launch(void* const* d_in, const int* in_sizes, int n_in,
                              void* d_out, int out_size)
{
    (void)in_sizes; (void)n_in; (void)out_size;
    const float* x       = (const float*)d_in[0];
    const float* enc_w1  = (const float*)d_in[1];
    const float* enc_b1  = (const float*)d_in[2];
    const float* enc_w2  = (const float*)d_in[3];
    const float* enc_b2  = (const float*)d_in[4];
    const float* enc_w3  = (const float*)d_in[5];
    const float* enc_b3  = (const float*)d_in[6];
    const float* enc_rw1 = (const float*)d_in[7];
    const float* enc_rw2 = (const float*)d_in[8];
    const float* pre_w   = (const float*)d_in[9];
    const float* pre_b   = (const float*)d_in[10];
    const float* cb      = (const float*)d_in[11];
    const float* dec_wt1 = (const float*)d_in[12];
    const float* dec_bt1 = (const float*)d_in[13];
    const float* dec_rw1 = (const float*)d_in[14];
    const float* dec_rw2 = (const float*)d_in[15];
    const float* dec_wt2 = (const float*)d_in[16];
    const float* dec_bt2 = (const float*)d_in[17];
    const float* dec_wt3 = (const float*)d_in[18];
    const float* dec_bt3 = (const float*)d_in[19];
    float* out = (float*)d_out;

    float *pA, *pB, *pB2, *pC, *pD, *pE, *pF, *pPart;
    cudaGetSymbolAddress((void**)&pA,  g_A);
    cudaGetSymbolAddress((void**)&pB,  g_B);
    cudaGetSymbolAddress((void**)&pB2, g_B2);
    cudaGetSymbolAddress((void**)&pC,  g_C);
    cudaGetSymbolAddress((void**)&pD,  g_D);
    cudaGetSymbolAddress((void**)&pE,  g_E);
    cudaGetSymbolAddress((void**)&pF,  g_F);
    cudaGetSymbolAddress((void**)&pPart, g_part);

    cudaFuncSetAttribute(decres_fused,
                         cudaFuncAttributeMaxDynamicSharedMemorySize, DSM_TOTAL);

    // encoder
    conv_fwd<4,2,false,false><<<dim3(2,16,16*8), 128>>>(
        x, enc_w1, enc_b1, nullptr, pA, 3, 64, 256, 256, 128, 128, 1, 8, 1);
    conv_fwd<4,2,false,false><<<dim3(1,8,16*16), 128>>>(
        pA, enc_w2, enc_b2, nullptr, pB, 64, 128, 128, 128, 64, 64, 1, 16, 1);
    conv_fwd<3,1,false,false><<<dim3(1,8,16*16), 128>>>(
        pB, enc_w3, enc_b3, nullptr, pC, 128, 128, 64, 64, 64, 64, 1, 16, 0);
    for (int i = 0; i < 2; i++) {
        conv_fwd<3,1,true,false><<<dim3(1,8,16*4), 128>>>(
            pC, enc_rw1, nullptr, nullptr, pD, 128, 32, 64, 64, 64, 64, 1, 4, 1);
        conv_fwd<1,1,false,false><<<dim3(1,8,16*16), 128>>>(
            pD, enc_rw2, nullptr, pC, pC, 32, 128, 64, 64, 64, 64, 0, 16, 0);
    }
    conv_fwd<1,1,true,false><<<dim3(1,8,16*8), 128>>>(
        pC, pre_w, pre_b, nullptr, pE, 128, 64, 64, 64, 64, 64, 0, 8, 0);

    // quantizer
    vq_kernel<<<1024, 256>>>(pE, cb, pF, pPart);
    finalize_loss<<<1, 256>>>(pPart, out + 3145728);

    // decoder
    conv_fwd<3,1,false,true><<<dim3(1,8,16*16), 128>>>(
        pF, dec_wt1, dec_bt1, nullptr, pB, 64, 128, 64, 64, 64, 64, 1, 16, 0);
    for (int i = 0; i < 32; i++) {
        const float* src = (i & 1) ? pB2 : pB;
        float*       dst = (i & 1) ? pB  : pB2;
        decres_fused<<<dim3(16,16), 256, DSM_TOTAL>>>(src, dec_rw1, dec_rw2, dst);
    }
    // after 32 iters result is back in pB
    convt_s2<<<dim3(2,16,16*8), 128>>>(
        pB, dec_wt2, dec_bt2, pA, 128, 64, 64, 64, 8, 1, 1);
    convt_s2<<<dim3(4,32,16*1), 128>>>(
        pA, dec_wt3, dec_bt3, out, 64, 3, 128, 128, 1, 0, 0);
}

// round 9
// speedup vs baseline: 1.2888x; 1.0216x over previous
#include <cuda_runtime.h>
#include <math.h>

typedef unsigned long long u64;

__device__ __forceinline__ u64 pk2(float v) {
    u64 r; asm("mov.b64 %0, {%1,%1};" : "=l"(r) : "f"(v)); return r;
}
__device__ __forceinline__ void fma2(u64& d, u64 a, u64 b) {
    asm("fma.rn.f32x2 %0, %1, %2, %0;" : "+l"(d) : "l"(a), "l"(b));
}
__device__ __forceinline__ float2 upk(u64 v) {
    float2 r; asm("mov.b64 {%0,%1}, %2;" : "=f"(r.x), "=f"(r.y) : "l"(v)); return r;
}
__device__ __forceinline__ u64 add2(u64 a, u64 b) {
    u64 r; asm("add.rn.f32x2 %0, %1, %2;" : "=l"(r) : "l"(a), "l"(b)); return r;
}

// ---------------- scratch (device globals: allocation-free) ------------------
__device__ float g_A [16*64*128*128];   // 67 MB
__device__ float g_B [16*128*64*64];    // 33.5 MB
__device__ float g_B2[16*128*64*64];    // 33.5 MB
__device__ float g_C [16*128*64*64];    // 33.5 MB
__device__ float g_D [16*32*64*64];     // 8.4 MB
__device__ float g_E [16*64*64*64];     // 16.8 MB (z_e)
__device__ float g_F [16*64*64*64];     // 16.8 MB (z_q)
__device__ float g_part[1024];

// ---------------- generic direct conv (f32x2, sliding window, 4 px/thread) ----
// thread: 4 out-x x 2*CP out-channels. block 128 = 16 px-grp x 8 rows.
// smem weights: [(ci*KK+kk)*2CP + c] -> c-pairs via LDS.128.
template<int K, int STRIDE, bool RELU_IN, bool TRANSPOSED, int CP>
__global__ void __launch_bounds__(128) conv_fwd(
    const float* __restrict__ in, const float* __restrict__ w,
    const float* __restrict__ bias, const float* __restrict__ resid,
    float* __restrict__ out,
    int CIN, int COUT, int H, int W, int OH, int OW, int PAD, int cgroups,
    int relu_out)
{
    constexpr int KK = K * K;
    constexpr int CICH = (K == 4) ? 64 : 128;
    constexpr int SPAN = 3 * STRIDE + K;
    constexpr int NC   = 2 * CP;           // couts per block
    __shared__ __align__(16) float sw[CICH * KK * NC];

    int t   = threadIdx.x;
    int tx  = t & 15, ty = t >> 4;
    int ox0 = blockIdx.x * 64 + tx * 4;
    int oy  = blockIdx.y * 8 + ty;
    int n   = blockIdx.z / cgroups;
    int co0 = (blockIdx.z % cgroups) * NC;
    int ixbase = ox0 * STRIDE - PAD;

    u64 acc2[CP][4];
#pragma unroll
    for (int cp = 0; cp < CP; cp++)
#pragma unroll
        for (int p = 0; p < 4; p++) acc2[cp][p] = 0ull;

    for (int ci0 = 0; ci0 < CIN; ci0 += CICH) {
        int cich = min(CICH, CIN - ci0);
        int nw = cich * KK * NC;
        __syncthreads();
        for (int i = t; i < nw; i += 128) {
            int c  = i & (NC - 1);
            int r  = i / NC;
            int ci = r / KK;
            int kk = r - ci * KK;
            int ky = kk / K, kx = kk - ky * K;
            int co = co0 + c;
            float v = 0.f;
            if (co < COUT) {
                if (TRANSPOSED)
                    v = w[(((ci0 + ci) * COUT + co) * K + (K - 1 - ky)) * K + (K - 1 - kx)];
                else
                    v = w[((co * CIN + (ci0 + ci)) * K + ky) * K + kx];
            }
            sw[i] = v;
        }
        __syncthreads();

        const float* inb = in + (n * CIN + ci0) * H * W;
        for (int ci = 0; ci < cich; ci++) {
            const float* inc = inb + ci * H * W;
            const float* wci = sw + ci * KK * NC;
#pragma unroll
            for (int ky = 0; ky < K; ky++) {
                int iy = oy * STRIDE - PAD + ky;
                if ((unsigned)iy >= (unsigned)H) continue;
                const float* rowp = inc + iy * W + ixbase;
                u64 ivs[SPAN];
#pragma unroll
                for (int q = 0; q < SPAN; q++) {
                    int ix = ixbase + q;
                    float v = ((unsigned)ix < (unsigned)W) ? __ldg(rowp + q) : 0.f;
                    if (RELU_IN) v = fmaxf(v, 0.f);
                    ivs[q] = pk2(v);
                }
#pragma unroll
                for (int kx = 0; kx < K; kx++) {
                    const float* wp = wci + (ky * K + kx) * NC;
                    u64 wv[CP];
#pragma unroll
                    for (int q = 0; q < CP / 2; q++) {
                        ulonglong2 ww = *(const ulonglong2*)(wp + q * 4);
                        wv[2 * q] = ww.x; wv[2 * q + 1] = ww.y;
                    }
                    if (CP & 1) wv[CP - 1] = *(const u64*)(wp + (CP - 1) * 2);
#pragma unroll
                    for (int cp = 0; cp < CP; cp++)
#pragma unroll
                        for (int p = 0; p < 4; p++)
                            fma2(acc2[cp][p], ivs[p * STRIDE + kx], wv[cp]);
                }
            }
        }
    }

#pragma unroll
    for (int cp = 0; cp < CP; cp++) {
        float2 v[4];
#pragma unroll
        for (int p = 0; p < 4; p++) v[p] = upk(acc2[cp][p]);
#pragma unroll
        for (int h2 = 0; h2 < 2; h2++) {
            int co = co0 + cp * 2 + h2;
            if (co >= COUT) continue;
            float b = bias ? __ldg(bias + co) : 0.f;
            int ob = ((n * COUT + co) * OH + oy) * OW + ox0;
#pragma unroll
            for (int p = 0; p < 4; p++) {
                float val = (h2 ? v[p].y : v[p].x) + b;
                if (resid) val += resid[ob + p];
                if (relu_out) val = fmaxf(val, 0.f);
                out[ob + p] = val;
            }
        }
    }
}

// ---------------- transposed conv, stride 2, K=4, pad 1 (f32x2) ---------------
template<int CP>
__global__ void __launch_bounds__(128) convt_s2(
    const float* __restrict__ in, const float* __restrict__ w,
    const float* __restrict__ bias, float* __restrict__ out,
    int CIN, int COUT, int H, int W, int cgroups, int relu_in, int relu_out)
{
    constexpr int NC = 2 * CP;
    __shared__ __align__(16) float sw[64 * 16 * NC];
    int t = threadIdx.x;
    int tx = t & 15, tyv = t >> 4;
    int parity = blockIdx.x & 1;
    int xch    = blockIdx.x >> 1;
    int OH = 2 * H, OW = 2 * W;
    int ox0 = xch * 128 + 8 * tx + parity;
    int oy  = blockIdx.y * 8 + tyv;
    int n   = blockIdx.z / cgroups;
    int co0 = (blockIdx.z % cgroups) * NC;

    int kyp = (oy + 1) & 1;
    int kxp = (ox0 + 1) & 1;
    int ixw = ((ox0 + 1 - kxp) >> 1) - 1;

    u64 acc2[CP][4];
#pragma unroll
    for (int cp = 0; cp < CP; cp++)
#pragma unroll
        for (int p = 0; p < 4; p++) acc2[cp][p] = 0ull;

    for (int ci0 = 0; ci0 < CIN; ci0 += 64) {
        int cich = min(64, CIN - ci0);
        int nw = cich * 16 * NC;
        __syncthreads();
        for (int i = t; i < nw; i += 128) {
            int c  = i & (NC - 1);
            int r  = i / NC;
            int ci = r >> 4;
            int kk = r & 15;
            int co = co0 + c;
            sw[i] = (co < COUT) ? w[((ci0 + ci) * COUT + co) * 16 + kk] : 0.f;
        }
        __syncthreads();

        for (int ci = 0; ci < cich; ci++) {
            const float* inc = in + (n * CIN + ci0 + ci) * H * W;
            const float* wci = sw + ci * 16 * NC;
#pragma unroll
            for (int ky2 = 0; ky2 < 2; ky2++) {
                int ky = kyp + 2 * ky2;
                int iy = (oy + 1 - ky) >> 1;
                if ((unsigned)iy >= (unsigned)H) continue;
                const float* rowp = inc + iy * W + ixw;
                u64 ivs[5];
#pragma unroll
                for (int q = 0; q < 5; q++) {
                    int ix = ixw + q;
                    float v = ((unsigned)ix < (unsigned)W) ? __ldg(rowp + q) : 0.f;
                    if (relu_in) v = fmaxf(v, 0.f);
                    ivs[q] = pk2(v);
                }
#pragma unroll
                for (int kx2 = 0; kx2 < 2; kx2++) {
                    int kx  = kxp + 2 * kx2;
                    int ofs = 1 - kx2;
                    const float* wp = wci + (ky * 4 + kx) * NC;
                    u64 wv[CP];
#pragma unroll
                    for (int q = 0; q < CP / 2; q++) {
                        ulonglong2 ww = *(const ulonglong2*)(wp + q * 4);
                        wv[2 * q] = ww.x; wv[2 * q + 1] = ww.y;
                    }
                    if (CP & 1) wv[CP - 1] = *(const u64*)(wp + (CP - 1) * 2);
#pragma unroll
                    for (int cp = 0; cp < CP; cp++)
#pragma unroll
                        for (int p = 0; p < 4; p++)
                            fma2(acc2[cp][p], ivs[ofs + p], wv[cp]);
                }
            }
        }
    }

#pragma unroll
    for (int cp = 0; cp < CP; cp++) {
        float2 v[4];
#pragma unroll
        for (int p = 0; p < 4; p++) v[p] = upk(acc2[cp][p]);
#pragma unroll
        for (int h2 = 0; h2 < 2; h2++) {
            int co = co0 + cp * 2 + h2;
            if (co >= COUT) continue;
            float b = bias ? __ldg(bias + co) : 0.f;
#pragma unroll
            for (int p = 0; p < 4; p++) {
                int ox = ox0 + 2 * p;
                int o = ((n * COUT + co) * OH + oy) * OW + ox;
                float val = (h2 ? v[p].y : v[p].x) + b;
                if (relu_out) val = fmaxf(val, 0.f);
                out[o] = val;
            }
        }
    }
}

// ---------------- fused decoder residual iteration (smem-resident stripe) -----
#define DSM_TOTAL 215040

__global__ void __launch_bounds__(256) decres_fused(
    const float* __restrict__ xin, const float* __restrict__ w1,
    const float* __restrict__ w2, float* __restrict__ xout)
{
    extern __shared__ unsigned char smraw[];
    float4* xs4   = (float4*)smraw;
    float*  sw1f  = (float*)(smraw + 196608);
    u64*    sw1u  = (u64*)  (smraw + 196608);
    float*  sw2   = (float*)(smraw + 205824);
    u64*    part  = (u64*)  (smraw + 206848);
    float*  h0    = (float*)(smraw + 212992);   // [4][64]
    float*  h1    = (float*)(smraw + 214016);   // [4][64]

    int t   = threadIdx.x;
    int by  = blockIdx.x;     // 0..15 stripe
    int n   = blockIdx.y;     // 0..15 image
    int oy0 = by * 4;

    for (int i = t; i < 2304; i += 256) {
        int ch = i & 1, r = i >> 1;            // r = ci*9 + k
        sw1f[i] = w1[ch * 1152 + r];
    }
    if (t < 256) sw2[t] = w2[t];

    const float4* xin4 = (const float4*)(xin + n * 128 * 4096);
    for (int i = t; i < 12288; i += 256) {
        int x4 = i & 15;
        int rr = (i >> 4) % 6;
        int ci = i / 96;
        int gy = oy0 - 1 + rr;
        float4 v;
        if ((unsigned)gy < 64u) v = xin4[(ci * 64 + gy) * 16 + x4];
        else { v.x = v.y = v.z = v.w = 0.f; }
        xs4[i] = v;
    }
    __syncthreads();

    int g   = t >> 6;
    int t64 = t & 63;
    int row = t64 >> 4;
    int xg  = t64 & 15;

    u64 a[4] = {0ull, 0ull, 0ull, 0ull};
    for (int ci = g * 32; ci < g * 32 + 32; ci++) {
        const u64* wci = sw1u + ci * 9;
#pragma unroll
        for (int ky = 0; ky < 3; ky++) {
            float4 c = xs4[(ci * 6 + row + ky) * 16 + xg];
            float l = __shfl_up_sync(0xffffffffu, c.w, 1);
            float r = __shfl_down_sync(0xffffffffu, c.x, 1);
            if (xg == 0)  l = 0.f;
            if (xg == 15) r = 0.f;
            u64 pw[6];
            pw[0] = pk2(fmaxf(l,   0.f));
            pw[1] = pk2(fmaxf(c.x, 0.f));
            pw[2] = pk2(fmaxf(c.y, 0.f));
            pw[3] = pk2(fmaxf(c.z, 0.f));
            pw[4] = pk2(fmaxf(c.w, 0.f));
            pw[5] = pk2(fmaxf(r,   0.f));
#pragma unroll
            for (int kx = 0; kx < 3; kx++) {
                u64 wv = wci[ky * 3 + kx];
                fma2(a[0], pw[kx    ], wv);
                fma2(a[1], pw[kx + 1], wv);
                fma2(a[2], pw[kx + 2], wv);
                fma2(a[3], pw[kx + 3], wv);
            }
        }
    }
    if (g > 0) {
#pragma unroll
        for (int p = 0; p < 4; p++) part[(g - 1) * 256 + t64 * 4 + p] = a[p];
    }
    __syncthreads();
    if (t < 64) {
#pragma unroll
        for (int p = 0; p < 4; p++) {
            u64 s = a[p];
            s = add2(s, part[      t * 4 + p]);
            s = add2(s, part[256 + t * 4 + p]);
            s = add2(s, part[512 + t * 4 + p]);
            float2 v = upk(s);
            h0[row * 64 + xg * 4 + p] = fmaxf(v.x, 0.f);
            h1[row * 64 + xg * 4 + p] = fmaxf(v.y, 0.f);
        }
    }
    __syncthreads();

    float4* xout4 = (float4*)(xout + n * 128 * 4096);
#pragma unroll 4
    for (int k = 0; k < 32; k++) {
        int e   = k * 256 + t;
        int x4  = e & 15;
        int row2= (e >> 4) & 3;
        int co  = e >> 6;
        float4 v = xs4[(co * 6 + row2 + 1) * 16 + x4];
        float w0 = sw2[co * 2], w1v = sw2[co * 2 + 1];
        const float* p0 = h0 + row2 * 64 + x4 * 4;
        const float* p1 = h1 + row2 * 64 + x4 * 4;
        v.x += w0 * p0[0] + w1v * p1[0];
        v.y += w0 * p0[1] + w1v * p1[1];
        v.z += w0 * p0[2] + w1v * p1[2];
        v.w += w0 * p0[3] + w1v * p1[3];
        xout4[(co * 64 + oy0 + row2) * 16 + x4] = v;
    }
}

// ---------------- vector quantizer -------------------------------------------
__global__ void __launch_bounds__(256) vq_kernel(
    const float* __restrict__ ze, const float* __restrict__ cb,
    float* __restrict__ zq, float* __restrict__ partials)
{
    __shared__ __align__(16) float f_s[64 * 64];
    __shared__ __align__(16) float cb_s[64 * 68];
    __shared__ float norm_s[512];
    __shared__ int   idx_s[64];
    __shared__ float red_s[64];

    int t = threadIdx.x;
    int b = blockIdx.x;
    int n = b >> 6, y = b & 63;

    for (int i = t; i < 4096; i += 256) {
        int d = i >> 6, x = i & 63;
        f_s[i] = ze[((n * 64 + d) * 64 + y) * 64 + x];
    }
    for (int c = t; c < 512; c += 256) {
        float s = 0.f;
        const float* cp = cb + c * 64;
#pragma unroll 8
        for (int d = 0; d < 64; d++) { float v = __ldg(cp + d); s = fmaf(v, v, s); }
        norm_s[c] = s;
    }
    __syncthreads();

    int cxT = t & 15, pyT = t >> 4;
    float best[4] = {3.4e38f, 3.4e38f, 3.4e38f, 3.4e38f};
    int   bidx[4] = {0, 0, 0, 0};

    for (int ch = 0; ch < 8; ch++) {
        __syncthreads();
        for (int i = t; i < 4096; i += 256) {
            int d = i & 63, c = i >> 6;
            cb_s[d * 68 + c] = __ldg(&cb[(ch * 64 + c) * 64 + d]);
        }
        __syncthreads();

        float dot[4][4];
#pragma unroll
        for (int pp = 0; pp < 4; pp++)
#pragma unroll
            for (int cc = 0; cc < 4; cc++) dot[pp][cc] = 0.f;

        for (int d = 0; d < 64; d++) {
            float4 fv4 = *(const float4*)&f_s[d * 64 + pyT * 4];
            float4 cv4 = *(const float4*)&cb_s[d * 68 + cxT * 4];
            float fv[4] = {fv4.x, fv4.y, fv4.z, fv4.w};
            float cv[4] = {cv4.x, cv4.y, cv4.z, cv4.w};
#pragma unroll
            for (int pp = 0; pp < 4; pp++)
#pragma unroll
                for (int cc = 0; cc < 4; cc++)
                    dot[pp][cc] = fmaf(fv[pp], cv[cc], dot[pp][cc]);
        }
#pragma unroll
        for (int cc = 0; cc < 4; cc++) {
            int code = ch * 64 + cxT * 4 + cc;
            float nrm = norm_s[code];
#pragma unroll
            for (int pp = 0; pp < 4; pp++) {
                float dist = fmaf(-2.f, dot[pp][cc], nrm);
                if (dist < best[pp]) { best[pp] = dist; bidx[pp] = code; }
            }
        }
    }

    for (int off = 1; off < 16; off <<= 1) {
#pragma unroll
        for (int pp = 0; pp < 4; pp++) {
            float ob = __shfl_xor_sync(0xffffffffu, best[pp], off);
            int   oi = __shfl_xor_sync(0xffffffffu, bidx[pp], off);
            if (ob < best[pp] || (ob == best[pp] && oi < bidx[pp])) {
                best[pp] = ob; bidx[pp] = oi;
            }
        }
    }
    if (cxT == 0)
#pragma unroll
        for (int pp = 0; pp < 4; pp++) idx_s[pyT * 4 + pp] = bidx[pp];
    __syncthreads();

    for (int i = t; i < 4096; i += 256) {
        int d = i >> 6, x = i & 63;
        zq[((n * 64 + d) * 64 + y) * 64 + x] = __ldg(&cb[idx_s[x] * 64 + d]);
    }

    if (t < 64) {
        int id = idx_s[t];
        const float* cp = cb + id * 64;
        float s = 0.f;
#pragma unroll 8
        for (int d = 0; d < 64; d++) {
            float diff = __ldg(cp + d) - f_s[d * 64 + t];
            s = fmaf(diff, diff, s);
        }
        red_s[t] = s;
    }
    __syncthreads();
    if (t == 0) {
        float s = 0.f;
        for (int i = 0; i < 64; i++) s += red_s[i];
        partials[b] = s;
    }
}

__global__ void __launch_bounds__(256) finalize_loss(
    const float* __restrict__ partials, float* __restrict__ dst)
{
    __shared__ float s[256];
    int t = threadIdx.x;
    float v = 0.f;
    for (int i = t; i < 1024; i += 256) v += partials[i];
    s[t] = v;
    __syncthreads();
    for (int off = 128; off > 0; off >>= 1) {
        if (t < off) s[t] += s[t + off];
        __syncthreads();
    }
    if (t == 0) dst[0] = 1.25f * s[0] / 4194304.f;  // (1 + BETA) * MSE
}

// ---------------- host launcher ----------------------------------------------
extern "C" void kernel_launch(void* const* d_in, const int* in_sizes, int n_in,
                              void* d_out, int out_size)
{
    (void)in_sizes; (void)n_in; (void)out_size;
    const float* x       = (const float*)d_in[0];
    const float* enc_w1  = (const float*)d_in[1];
    const float* enc_b1  = (const float*)d_in[2];
    const float* enc_w2  = (const float*)d_in[3];
    const float* enc_b2  = (const float*)d_in[4];
    const float* enc_w3  = (const float*)d_in[5];
    const float* enc_b3  = (const float*)d_in[6];
    const float* enc_rw1 = (const float*)d_in[7];
    const float* enc_rw2 = (const float*)d_in[8];
    const float* pre_w   = (const float*)d_in[9];
    const float* pre_b   = (const float*)d_in[10];
    const float* cb      = (const float*)d_in[11];
    const float* dec_wt1 = (const float*)d_in[12];
    const float* dec_bt1 = (const float*)d_in[13];
    const float* dec_rw1 = (const float*)d_in[14];
    const float* dec_rw2 = (const float*)d_in[15];
    const float* dec_wt2 = (const float*)d_in[16];
    const float* dec_bt2 = (const float*)d_in[17];
    const float* dec_wt3 = (const float*)d_in[18];
    const float* dec_bt3 = (const float*)d_in[19];
    float* out = (float*)d_out;

    float *pA, *pB, *pB2, *pC, *pD, *pE, *pF, *pPart;
    cudaGetSymbolAddress((void**)&pA,  g_A);
    cudaGetSymbolAddress((void**)&pB,  g_B);
    cudaGetSymbolAddress((void**)&pB2, g_B2);
    cudaGetSymbolAddress((void**)&pC,  g_C);
    cudaGetSymbolAddress((void**)&pD,  g_D);
    cudaGetSymbolAddress((void**)&pE,  g_E);
    cudaGetSymbolAddress((void**)&pF,  g_F);
    cudaGetSymbolAddress((void**)&pPart, g_part);

    cudaFuncSetAttribute(decres_fused,
                         cudaFuncAttributeMaxDynamicSharedMemorySize, DSM_TOTAL);

    // encoder
    conv_fwd<4,2,false,false,4><<<dim3(2,16,16*8), 128>>>(
        x, enc_w1, enc_b1, nullptr, pA, 3, 64, 256, 256, 128, 128, 1, 8, 1);
    conv_fwd<4,2,false,false,4><<<dim3(1,8,16*16), 128>>>(
        pA, enc_w2, enc_b2, nullptr, pB, 64, 128, 128, 128, 64, 64, 1, 16, 1);
    conv_fwd<3,1,false,false,4><<<dim3(1,8,16*16), 128>>>(
        pB, enc_w3, enc_b3, nullptr, pC, 128, 128, 64, 64, 64, 64, 1, 16, 0);
    for (int i = 0; i < 2; i++) {
        // 4-cout tile -> 1024 blocks (2x occupancy for the grid-starved kernel)
        conv_fwd<3,1,true,false,2><<<dim3(1,8,16*8), 128>>>(
            pC, enc_rw1, nullptr, nullptr, pD, 128, 32, 64, 64, 64, 64, 1, 8, 1);
        conv_fwd<1,1,false,false,4><<<dim3(1,8,16*16), 128>>>(
            pD, enc_rw2, nullptr, pC, pC, 32, 128, 64, 64, 64, 64, 0, 16, 0);
    }
    conv_fwd<1,1,true,false,4><<<dim3(1,8,16*8), 128>>>(
        pC, pre_w, pre_b, nullptr, pE, 128, 64, 64, 64, 64, 64, 0, 8, 0);

    // quantizer
    vq_kernel<<<1024, 256>>>(pE, cb, pF, pPart);
    finalize_loss<<<1, 256>>>(pPart, out + 3145728);

    // decoder
    conv_fwd<3,1,false,true,4><<<dim3(1,8,16*16), 128>>>(
        pF, dec_wt1, dec_bt1, nullptr, pB, 64, 128, 64, 64, 64, 64, 1, 16, 0);
    for (int i = 0; i < 32; i++) {
        const float* src = (i & 1) ? pB2 : pB;
        float*       dst = (i & 1) ? pB  : pB2;
        decres_fused<<<dim3(16,16), 256, DSM_TOTAL>>>(src, dec_rw1, dec_rw2, dst);
    }
    // after 32 iters result is back in pB
    convt_s2<4><<<dim3(2,16,16*8), 128>>>(
        pB, dec_wt2, dec_bt2, pA, 128, 64, 64, 64, 8, 1, 1);
    // COUT=3: 4-cout tile halves wasted FFMA
    convt_s2<2><<<dim3(4,32,16*1), 128>>>(
        pA, dec_wt3, dec_bt3, out, 64, 3, 128, 128, 1, 0, 0);
}

// round 10
// speedup vs baseline: 1.4564x; 1.1301x over previous
#include <cuda_runtime.h>
#include <math.h>

typedef unsigned long long u64;

__device__ __forceinline__ u64 pk2(float v) {
    u64 r; asm("mov.b64 %0, {%1,%1};" : "=l"(r) : "f"(v)); return r;
}
__device__ __forceinline__ void fma2(u64& d, u64 a, u64 b) {
    asm("fma.rn.f32x2 %0, %1, %2, %0;" : "+l"(d) : "l"(a), "l"(b));
}
__device__ __forceinline__ float2 upk(u64 v) {
    float2 r; asm("mov.b64 {%0,%1}, %2;" : "=f"(r.x), "=f"(r.y) : "l"(v)); return r;
}
__device__ __forceinline__ u64 add2(u64 a, u64 b) {
    u64 r; asm("add.rn.f32x2 %0, %1, %2;" : "=l"(r) : "l"(a), "l"(b)); return r;
}

// ---------------- scratch (device globals: allocation-free) ------------------
__device__ float g_A [16*64*128*128];   // 67 MB
__device__ float g_B [16*128*64*64];    // 33.5 MB
__device__ float g_B2[16*128*64*64];    // 33.5 MB
__device__ float g_C [16*128*64*64];    // 33.5 MB
__device__ float g_D [16*32*64*64];     // 8.4 MB
__device__ float g_E [16*64*64*64];     // 16.8 MB (z_e)
__device__ float g_F [16*64*64*64];     // 16.8 MB (z_q)
__device__ float g_part[1024];

// ---------------- generic direct conv (f32x2, float4+shuffle window) ----------
// thread: 4 out-x x 2*CP out-channels. block 128 = 16 px-grp x 8 rows.
// smem weights: [(ci*KK+kk)*2CP + c] -> c-pairs via LDS.128.
template<int K, int STRIDE, bool RELU_IN, bool TRANSPOSED, int CP>
__global__ void __launch_bounds__(128) conv_fwd(
    const float* __restrict__ in, const float* __restrict__ w,
    const float* __restrict__ bias, const float* __restrict__ resid,
    float* __restrict__ out,
    int CIN, int COUT, int H, int W, int OH, int OW, int PAD, int cgroups,
    int relu_out)
{
    constexpr int KK = K * K;
    constexpr int CICH = (K == 4) ? 64 : 128;
    constexpr int SPAN = 3 * STRIDE + K;
    constexpr int NC   = 2 * CP;           // couts per block
    __shared__ __align__(16) float sw[CICH * KK * NC];

    int t   = threadIdx.x;
    int tx  = t & 15, ty = t >> 4;
    int ox0 = blockIdx.x * 64 + tx * 4;
    int oy  = blockIdx.y * 8 + ty;
    int n   = blockIdx.z / cgroups;
    int co0 = (blockIdx.z % cgroups) * NC;

    u64 acc2[CP][4];
#pragma unroll
    for (int cp = 0; cp < CP; cp++)
#pragma unroll
        for (int p = 0; p < 4; p++) acc2[cp][p] = 0ull;

    for (int ci0 = 0; ci0 < CIN; ci0 += CICH) {
        int cich = min(CICH, CIN - ci0);
        int nw = cich * KK * NC;
        __syncthreads();
        for (int i = t; i < nw; i += 128) {
            int c  = i & (NC - 1);
            int r  = i / NC;
            int ci = r / KK;
            int kk = r - ci * KK;
            int ky = kk / K, kx = kk - ky * K;
            int co = co0 + c;
            float v = 0.f;
            if (co < COUT) {
                if (TRANSPOSED)
                    v = w[(((ci0 + ci) * COUT + co) * K + (K - 1 - ky)) * K + (K - 1 - kx)];
                else
                    v = w[((co * CIN + (ci0 + ci)) * K + ky) * K + kx];
            }
            sw[i] = v;
        }
        __syncthreads();

        const float* inb = in + (n * CIN + ci0) * H * W;
        for (int ci = 0; ci < cich; ci++) {
            const float* inc = inb + ci * H * W;
            const float* wci = sw + ci * KK * NC;
#pragma unroll
            for (int ky = 0; ky < K; ky++) {
                int iy = oy * STRIDE - PAD + ky;
                bool vy = (unsigned)iy < (unsigned)H;
                const float* rowp = inc + (vy ? iy : 0) * W;
                u64 ivs[SPAN];

                if constexpr (STRIDE == 1 && K == 3) {
                    float4 c = make_float4(0.f, 0.f, 0.f, 0.f);
                    if (vy) c = *(const float4*)(rowp + ox0);
                    float l = __shfl_up_sync(0xffffffffu, c.w, 1);
                    float r = __shfl_down_sync(0xffffffffu, c.x, 1);
                    if (tx == 0)  l = (vy && ox0 > 0)       ? __ldg(rowp + ox0 - 1) : 0.f;
                    if (tx == 15) r = (vy && ox0 + 4 < W)   ? __ldg(rowp + ox0 + 4) : 0.f;
                    float vv[6] = {l, c.x, c.y, c.z, c.w, r};
#pragma unroll
                    for (int q = 0; q < 6; q++) {
                        float v = vv[q];
                        if (RELU_IN) v = fmaxf(v, 0.f);
                        ivs[q] = pk2(v);
                    }
                } else if constexpr (K == 1) {
                    float4 c = make_float4(0.f, 0.f, 0.f, 0.f);
                    if (vy) c = *(const float4*)(rowp + ox0);
                    float vv[4] = {c.x, c.y, c.z, c.w};
#pragma unroll
                    for (int q = 0; q < 4; q++) {
                        float v = vv[q];
                        if (RELU_IN) v = fmaxf(v, 0.f);
                        ivs[q] = pk2(v);
                    }
                } else {  // K == 4, STRIDE == 2
                    int a0 = 2 * ox0;
                    float4 f0 = make_float4(0.f, 0.f, 0.f, 0.f);
                    float4 f1 = make_float4(0.f, 0.f, 0.f, 0.f);
                    if (vy) {
                        f0 = *(const float4*)(rowp + a0);
                        f1 = *(const float4*)(rowp + a0 + 4);
                    }
                    float l = __shfl_up_sync(0xffffffffu, f1.w, 1);
                    float r = __shfl_down_sync(0xffffffffu, f0.x, 1);
                    if (tx == 0)  l = (vy && a0 > 0)      ? __ldg(rowp + a0 - 1) : 0.f;
                    if (tx == 15) r = (vy && a0 + 8 < W)  ? __ldg(rowp + a0 + 8) : 0.f;
                    float vv[10] = {l, f0.x, f0.y, f0.z, f0.w, f1.x, f1.y, f1.z, f1.w, r};
#pragma unroll
                    for (int q = 0; q < 10; q++) {
                        float v = vv[q];
                        if (RELU_IN) v = fmaxf(v, 0.f);
                        ivs[q] = pk2(v);
                    }
                }

#pragma unroll
                for (int kx = 0; kx < K; kx++) {
                    const float* wp = wci + (ky * K + kx) * NC;
                    u64 wv[CP];
#pragma unroll
                    for (int q = 0; q < CP / 2; q++) {
                        ulonglong2 ww = *(const ulonglong2*)(wp + q * 4);
                        wv[2 * q] = ww.x; wv[2 * q + 1] = ww.y;
                    }
                    if (CP & 1) wv[CP - 1] = *(const u64*)(wp + (CP - 1) * 2);
#pragma unroll
                    for (int cp = 0; cp < CP; cp++)
#pragma unroll
                        for (int p = 0; p < 4; p++)
                            fma2(acc2[cp][p], ivs[p * STRIDE + kx], wv[cp]);
                }
            }
        }
    }

#pragma unroll
    for (int cp = 0; cp < CP; cp++) {
        float2 v[4];
#pragma unroll
        for (int p = 0; p < 4; p++) v[p] = upk(acc2[cp][p]);
#pragma unroll
        for (int h2 = 0; h2 < 2; h2++) {
            int co = co0 + cp * 2 + h2;
            if (co >= COUT) continue;
            float b = bias ? __ldg(bias + co) : 0.f;
            int ob = ((n * COUT + co) * OH + oy) * OW + ox0;
#pragma unroll
            for (int p = 0; p < 4; p++) {
                float val = (h2 ? v[p].y : v[p].x) + b;
                if (resid) val += resid[ob + p];
                if (relu_out) val = fmaxf(val, 0.f);
                out[ob + p] = val;
            }
        }
    }
}

// ---------------- transposed conv, stride 2, K=4, pad 1 (f32x2, f4+shuffle) ---
template<int CP>
__global__ void __launch_bounds__(128) convt_s2(
    const float* __restrict__ in, const float* __restrict__ w,
    const float* __restrict__ bias, float* __restrict__ out,
    int CIN, int COUT, int H, int W, int cgroups, int relu_in, int relu_out)
{
    constexpr int NC = 2 * CP;
    __shared__ __align__(16) float sw[64 * 16 * NC];
    int t = threadIdx.x;
    int tx = t & 15, tyv = t >> 4;
    int parity = blockIdx.x & 1;
    int xch    = blockIdx.x >> 1;
    int OH = 2 * H, OW = 2 * W;
    int ox0 = xch * 128 + 8 * tx + parity;
    int oy  = blockIdx.y * 8 + tyv;
    int n   = blockIdx.z / cgroups;
    int co0 = (blockIdx.z % cgroups) * NC;

    int kyp = (oy + 1) & 1;
    int kxp = (ox0 + 1) & 1;          // = 1 - parity (uniform per block)
    int a0  = (ox0 - parity) >> 1;    // aligned float4 base in input x

    u64 acc2[CP][4];
#pragma unroll
    for (int cp = 0; cp < CP; cp++)
#pragma unroll
        for (int p = 0; p < 4; p++) acc2[cp][p] = 0ull;

    for (int ci0 = 0; ci0 < CIN; ci0 += 64) {
        int cich = min(64, CIN - ci0);
        int nw = cich * 16 * NC;
        __syncthreads();
        for (int i = t; i < nw; i += 128) {
            int c  = i & (NC - 1);
            int r  = i / NC;
            int ci = r >> 4;
            int kk = r & 15;
            int co = co0 + c;
            sw[i] = (co < COUT) ? w[((ci0 + ci) * COUT + co) * 16 + kk] : 0.f;
        }
        __syncthreads();

        for (int ci = 0; ci < cich; ci++) {
            const float* inc = in + (n * CIN + ci0 + ci) * H * W;
            const float* wci = sw + ci * 16 * NC;
#pragma unroll
            for (int ky2 = 0; ky2 < 2; ky2++) {
                int ky = kyp + 2 * ky2;
                int iy = (oy + 1 - ky) >> 1;
                bool vy = (unsigned)iy < (unsigned)H;
                const float* rowp = inc + (vy ? iy : 0) * W;
                float4 c = make_float4(0.f, 0.f, 0.f, 0.f);
                if (vy) c = *(const float4*)(rowp + a0);
                u64 ivs[5];
                if (parity == 0) {
                    float l = __shfl_up_sync(0xffffffffu, c.w, 1);
                    if (tx == 0) l = (vy && a0 > 0) ? __ldg(rowp + a0 - 1) : 0.f;
                    float vv[5] = {l, c.x, c.y, c.z, c.w};
#pragma unroll
                    for (int q = 0; q < 5; q++) {
                        float v = vv[q];
                        if (relu_in) v = fmaxf(v, 0.f);
                        ivs[q] = pk2(v);
                    }
                } else {
                    float r = __shfl_down_sync(0xffffffffu, c.x, 1);
                    if (tx == 15) r = (vy && a0 + 4 < W) ? __ldg(rowp + a0 + 4) : 0.f;
                    float vv[5] = {c.x, c.y, c.z, c.w, r};
#pragma unroll
                    for (int q = 0; q < 5; q++) {
                        float v = vv[q];
                        if (relu_in) v = fmaxf(v, 0.f);
                        ivs[q] = pk2(v);
                    }
                }
#pragma unroll
                for (int kx2 = 0; kx2 < 2; kx2++) {
                    int kx  = kxp + 2 * kx2;
                    int ofs = 1 - kx2;
                    const float* wp = wci + (ky * 4 + kx) * NC;
                    u64 wv[CP];
#pragma unroll
                    for (int q = 0; q < CP / 2; q++) {
                        ulonglong2 ww = *(const ulonglong2*)(wp + q * 4);
                        wv[2 * q] = ww.x; wv[2 * q + 1] = ww.y;
                    }
                    if (CP & 1) wv[CP - 1] = *(const u64*)(wp + (CP - 1) * 2);
#pragma unroll
                    for (int cp = 0; cp < CP; cp++)
#pragma unroll
                        for (int p = 0; p < 4; p++)
                            fma2(acc2[cp][p], ivs[ofs + p], wv[cp]);
                }
            }
        }
    }

#pragma unroll
    for (int cp = 0; cp < CP; cp++) {
        float2 v[4];
#pragma unroll
        for (int p = 0; p < 4; p++) v[p] = upk(acc2[cp][p]);
#pragma unroll
        for (int h2 = 0; h2 < 2; h2++) {
            int co = co0 + cp * 2 + h2;
            if (co >= COUT) continue;
            float b = bias ? __ldg(bias + co) : 0.f;
#pragma unroll
            for (int p = 0; p < 4; p++) {
                int ox = ox0 + 2 * p;
                int o = ((n * COUT + co) * OH + oy) * OW + ox;
                float val = (h2 ? v[p].y : v[p].x) + b;
                if (relu_out) val = fmaxf(val, 0.f);
                out[o] = val;
            }
        }
    }
}

// ---------------- fused decoder residual iteration (smem-resident stripe) -----
#define DSM_TOTAL 215040

__global__ void __launch_bounds__(256) decres_fused(
    const float* __restrict__ xin, const float* __restrict__ w1,
    const float* __restrict__ w2, float* __restrict__ xout)
{
    extern __shared__ unsigned char smraw[];
    float4* xs4   = (float4*)smraw;
    float*  sw1f  = (float*)(smraw + 196608);
    u64*    sw1u  = (u64*)  (smraw + 196608);
    float*  sw2   = (float*)(smraw + 205824);
    u64*    part  = (u64*)  (smraw + 206848);
    float*  h0    = (float*)(smraw + 212992);   // [4][64]
    float*  h1    = (float*)(smraw + 214016);   // [4][64]

    int t   = threadIdx.x;
    int by  = blockIdx.x;     // 0..15 stripe
    int n   = blockIdx.y;     // 0..15 image
    int oy0 = by * 4;

    for (int i = t; i < 2304; i += 256) {
        int ch = i & 1, r = i >> 1;            // r = ci*9 + k
        sw1f[i] = w1[ch * 1152 + r];
    }
    if (t < 256) sw2[t] = w2[t];

    const float4* xin4 = (const float4*)(xin + n * 128 * 4096);
    for (int i = t; i < 12288; i += 256) {
        int x4 = i & 15;
        int rr = (i >> 4) % 6;
        int ci = i / 96;
        int gy = oy0 - 1 + rr;
        float4 v;
        if ((unsigned)gy < 64u) v = xin4[(ci * 64 + gy) * 16 + x4];
        else { v.x = v.y = v.z = v.w = 0.f; }
        xs4[i] = v;
    }
    __syncthreads();

    int g   = t >> 6;
    int t64 = t & 63;
    int row = t64 >> 4;
    int xg  = t64 & 15;

    u64 a[4] = {0ull, 0ull, 0ull, 0ull};
    for (int ci = g * 32; ci < g * 32 + 32; ci++) {
        const u64* wci = sw1u + ci * 9;
#pragma unroll
        for (int ky = 0; ky < 3; ky++) {
            float4 c = xs4[(ci * 6 + row + ky) * 16 + xg];
            float l = __shfl_up_sync(0xffffffffu, c.w, 1);
            float r = __shfl_down_sync(0xffffffffu, c.x, 1);
            if (xg == 0)  l = 0.f;
            if (xg == 15) r = 0.f;
            u64 pw[6];
            pw[0] = pk2(fmaxf(l,   0.f));
            pw[1] = pk2(fmaxf(c.x, 0.f));
            pw[2] = pk2(fmaxf(c.y, 0.f));
            pw[3] = pk2(fmaxf(c.z, 0.f));
            pw[4] = pk2(fmaxf(c.w, 0.f));
            pw[5] = pk2(fmaxf(r,   0.f));
#pragma unroll
            for (int kx = 0; kx < 3; kx++) {
                u64 wv = wci[ky * 3 + kx];
                fma2(a[0], pw[kx    ], wv);
                fma2(a[1], pw[kx + 1], wv);
                fma2(a[2], pw[kx + 2], wv);
                fma2(a[3], pw[kx + 3], wv);
            }
        }
    }
    if (g > 0) {
#pragma unroll
        for (int p = 0; p < 4; p++) part[(g - 1) * 256 + t64 * 4 + p] = a[p];
    }
    __syncthreads();
    if (t < 64) {
#pragma unroll
        for (int p = 0; p < 4; p++) {
            u64 s = a[p];
            s = add2(s, part[      t * 4 + p]);
            s = add2(s, part[256 + t * 4 + p]);
            s = add2(s, part[512 + t * 4 + p]);
            float2 v = upk(s);
            h0[row * 64 + xg * 4 + p] = fmaxf(v.x, 0.f);
            h1[row * 64 + xg * 4 + p] = fmaxf(v.y, 0.f);
        }
    }
    __syncthreads();

    float4* xout4 = (float4*)(xout + n * 128 * 4096);
#pragma unroll 4
    for (int k = 0; k < 32; k++) {
        int e   = k * 256 + t;
        int x4  = e & 15;
        int row2= (e >> 4) & 3;
        int co  = e >> 6;
        float4 v = xs4[(co * 6 + row2 + 1) * 16 + x4];
        float w0 = sw2[co * 2], w1v = sw2[co * 2 + 1];
        const float* p0 = h0 + row2 * 64 + x4 * 4;
        const float* p1 = h1 + row2 * 64 + x4 * 4;
        v.x += w0 * p0[0] + w1v * p1[0];
        v.y += w0 * p0[1] + w1v * p1[1];
        v.z += w0 * p0[2] + w1v * p1[2];
        v.w += w0 * p0[3] + w1v * p1[3];
        xout4[(co * 64 + oy0 + row2) * 16 + x4] = v;
    }
}

// ---------------- vector quantizer -------------------------------------------
__global__ void __launch_bounds__(256) vq_kernel(
    const float* __restrict__ ze, const float* __restrict__ cb,
    float* __restrict__ zq, float* __restrict__ partials)
{
    __shared__ __align__(16) float f_s[64 * 64];
    __shared__ __align__(16) float cb_s[64 * 68];
    __shared__ float norm_s[512];
    __shared__ int   idx_s[64];
    __shared__ float red_s[64];

    int t = threadIdx.x;
    int b = blockIdx.x;
    int n = b >> 6, y = b & 63;

    for (int i = t; i < 4096; i += 256) {
        int d = i >> 6, x = i & 63;
        f_s[i] = ze[((n * 64 + d) * 64 + y) * 64 + x];
    }
    for (int c = t; c < 512; c += 256) {
        float s = 0.f;
        const float* cp = cb + c * 64;
#pragma unroll 8
        for (int d = 0; d < 64; d++) { float v = __ldg(cp + d); s = fmaf(v, v, s); }
        norm_s[c] = s;
    }
    __syncthreads();

    int cxT = t & 15, pyT = t >> 4;
    float best[4] = {3.4e38f, 3.4e38f, 3.4e38f, 3.4e38f};
    int   bidx[4] = {0, 0, 0, 0};

    for (int ch = 0; ch < 8; ch++) {
        __syncthreads();
        for (int i = t; i < 4096; i += 256) {
            int d = i & 63, c = i >> 6;
            cb_s[d * 68 + c] = __ldg(&cb[(ch * 64 + c) * 64 + d]);
        }
        __syncthreads();

        float dot[4][4];
#pragma unroll
        for (int pp = 0; pp < 4; pp++)
#pragma unroll
            for (int cc = 0; cc < 4; cc++) dot[pp][cc] = 0.f;

        for (int d = 0; d < 64; d++) {
            float4 fv4 = *(const float4*)&f_s[d * 64 + pyT * 4];
            float4 cv4 = *(const float4*)&cb_s[d * 68 + cxT * 4];
            float fv[4] = {fv4.x, fv4.y, fv4.z, fv4.w};
            float cv[4] = {cv4.x, cv4.y, cv4.z, cv4.w};
#pragma unroll
            for (int pp = 0; pp < 4; pp++)
#pragma unroll
                for (int cc = 0; cc < 4; cc++)
                    dot[pp][cc] = fmaf(fv[pp], cv[cc], dot[pp][cc]);
        }
#pragma unroll
        for (int cc = 0; cc < 4; cc++) {
            int code = ch * 64 + cxT * 4 + cc;
            float nrm = norm_s[code];
#pragma unroll
            for (int pp = 0; pp < 4; pp++) {
                float dist = fmaf(-2.f, dot[pp][cc], nrm);
                if (dist < best[pp]) { best[pp] = dist; bidx[pp] = code; }
            }
        }
    }

    for (int off = 1; off < 16; off <<= 1) {
#pragma unroll
        for (int pp = 0; pp < 4; pp++) {
            float ob = __shfl_xor_sync(0xffffffffu, best[pp], off);
            int   oi = __shfl_xor_sync(0xffffffffu, bidx[pp], off);
            if (ob < best[pp] || (ob == best[pp] && oi < bidx[pp])) {
                best[pp] = ob; bidx[pp] = oi;
            }
        }
    }
    if (cxT == 0)
#pragma unroll
        for (int pp = 0; pp < 4; pp++) idx_s[pyT * 4 + pp] = bidx[pp];
    __syncthreads();

    for (int i = t; i < 4096; i += 256) {
        int d = i >> 6, x = i & 63;
        zq[((n * 64 + d) * 64 + y) * 64 + x] = __ldg(&cb[idx_s[x] * 64 + d]);
    }

    if (t < 64) {
        int id = idx_s[t];
        const float* cp = cb + id * 64;
        float s = 0.f;
#pragma unroll 8
        for (int d = 0; d < 64; d++) {
            float diff = __ldg(cp + d) - f_s[d * 64 + t];
            s = fmaf(diff, diff, s);
        }
        red_s[t] = s;
    }
    __syncthreads();
    if (t == 0) {
        float s = 0.f;
        for (int i = 0; i < 64; i++) s += red_s[i];
        partials[b] = s;
    }
}

__global__ void __launch_bounds__(256) finalize_loss(
    const float* __restrict__ partials, float* __restrict__ dst)
{
    __shared__ float s[256];
    int t = threadIdx.x;
    float v = 0.f;
    for (int i = t; i < 1024; i += 256) v += partials[i];
    s[t] = v;
    __syncthreads();
    for (int off = 128; off > 0; off >>= 1) {
        if (t < off) s[t] += s[t + off];
        __syncthreads();
    }
    if (t == 0) dst[0] = 1.25f * s[0] / 4194304.f;  // (1 + BETA) * MSE
}

// ---------------- host launcher ----------------------------------------------
extern "C" void kernel_launch(void* const* d_in, const int* in_sizes, int n_in,
                              void* d_out, int out_size)
{
    (void)in_sizes; (void)n_in; (void)out_size;
    const float* x       = (const float*)d_in[0];
    const float* enc_w1  = (const float*)d_in[1];
    const float* enc_b1  = (const float*)d_in[2];
    const float* enc_w2  = (const float*)d_in[3];
    const float* enc_b2  = (const float*)d_in[4];
    const float* enc_w3  = (const float*)d_in[5];
    const float* enc_b3  = (const float*)d_in[6];
    const float* enc_rw1 = (const float*)d_in[7];
    const float* enc_rw2 = (const float*)d_in[8];
    const float* pre_w   = (const float*)d_in[9];
    const float* pre_b   = (const float*)d_in[10];
    const float* cb      = (const float*)d_in[11];
    const float* dec_wt1 = (const float*)d_in[12];
    const float* dec_bt1 = (const float*)d_in[13];
    const float* dec_rw1 = (const float*)d_in[14];
    const float* dec_rw2 = (const float*)d_in[15];
    const float* dec_wt2 = (const float*)d_in[16];
    const float* dec_bt2 = (const float*)d_in[17];
    const float* dec_wt3 = (const float*)d_in[18];
    const float* dec_bt3 = (const float*)d_in[19];
    float* out = (float*)d_out;

    float *pA, *pB, *pB2, *pC, *pD, *pE, *pF, *pPart;
    cudaGetSymbolAddress((void**)&pA,  g_A);
    cudaGetSymbolAddress((void**)&pB,  g_B);
    cudaGetSymbolAddress((void**)&pB2, g_B2);
    cudaGetSymbolAddress((void**)&pC,  g_C);
    cudaGetSymbolAddress((void**)&pD,  g_D);
    cudaGetSymbolAddress((void**)&pE,  g_E);
    cudaGetSymbolAddress((void**)&pF,  g_F);
    cudaGetSymbolAddress((void**)&pPart, g_part);

    cudaFuncSetAttribute(decres_fused,
                         cudaFuncAttributeMaxDynamicSharedMemorySize, DSM_TOTAL);

    // encoder
    conv_fwd<4,2,false,false,4><<<dim3(2,16,16*8), 128>>>(
        x, enc_w1, enc_b1, nullptr, pA, 3, 64, 256, 256, 128, 128, 1, 8, 1);
    conv_fwd<4,2,false,false,4><<<dim3(1,8,16*16), 128>>>(
        pA, enc_w2, enc_b2, nullptr, pB, 64, 128, 128, 128, 64, 64, 1, 16, 1);
    conv_fwd<3,1,false,false,4><<<dim3(1,8,16*16), 128>>>(
        pB, enc_w3, enc_b3, nullptr, pC, 128, 128, 64, 64, 64, 64, 1, 16, 0);
    for (int i = 0; i < 2; i++) {
        conv_fwd<3,1,true,false,2><<<dim3(1,8,16*8), 128>>>(
            pC, enc_rw1, nullptr, nullptr, pD, 128, 32, 64, 64, 64, 64, 1, 8, 1);
        conv_fwd<1,1,false,false,4><<<dim3(1,8,16*16), 128>>>(
            pD, enc_rw2, nullptr, pC, pC, 32, 128, 64, 64, 64, 64, 0, 16, 0);
    }
    conv_fwd<1,1,true,false,4><<<dim3(1,8,16*8), 128>>>(
        pC, pre_w, pre_b, nullptr, pE, 128, 64, 64, 64, 64, 64, 0, 8, 0);

    // quantizer
    vq_kernel<<<1024, 256>>>(pE, cb, pF, pPart);
    finalize_loss<<<1, 256>>>(pPart, out + 3145728);

    // decoder
    conv_fwd<3,1,false,true,4><<<dim3(1,8,16*16), 128>>>(
        pF, dec_wt1, dec_bt1, nullptr, pB, 64, 128, 64, 64, 64, 64, 1, 16, 0);
    for (int i = 0; i < 32; i++) {
        const float* src = (i & 1) ? pB2 : pB;
        float*       dst = (i & 1) ? pB  : pB2;
        decres_fused<<<dim3(16,16), 256, DSM_TOTAL>>>(src, dec_rw1, dec_rw2, dst);
    }
    // after 32 iters result is back in pB
    convt_s2<4><<<dim3(2,16,16*8), 128>>>(
        pB, dec_wt2, dec_bt2, pA, 128, 64, 64, 64, 8, 1, 1);
    convt_s2<2><<<dim3(4,32,16*1), 128>>>(
        pA, dec_wt3, dec_bt3, out, 64, 3, 128, 128, 1, 0, 0);
}

// round 11
// speedup vs baseline: 1.4625x; 1.0041x over previous
#include <cuda_runtime.h>
#include <math.h>

typedef unsigned long long u64;

__device__ __forceinline__ u64 pk2(float v) {
    u64 r; asm("mov.b64 %0, {%1,%1};" : "=l"(r) : "f"(v)); return r;
}
__device__ __forceinline__ void fma2(u64& d, u64 a, u64 b) {
    asm("fma.rn.f32x2 %0, %1, %2, %0;" : "+l"(d) : "l"(a), "l"(b));
}
__device__ __forceinline__ float2 upk(u64 v) {
    float2 r; asm("mov.b64 {%0,%1}, %2;" : "=f"(r.x), "=f"(r.y) : "l"(v)); return r;
}
__device__ __forceinline__ u64 add2(u64 a, u64 b) {
    u64 r; asm("add.rn.f32x2 %0, %1, %2;" : "=l"(r) : "l"(a), "l"(b)); return r;
}

// ---------------- scratch (device globals: allocation-free) ------------------
__device__ float g_A [16*64*128*128];   // 67 MB
__device__ float g_B [16*128*64*64];    // 33.5 MB
__device__ float g_B2[16*128*64*64];    // 33.5 MB
__device__ float g_C [16*128*64*64];    // 33.5 MB
__device__ float g_E [16*64*64*64];     // 16.8 MB (z_e)
__device__ float g_F [16*64*64*64];     // 16.8 MB (z_q)
__device__ __align__(16) float g_W1T[128*9*32];  // transposed enc_rw1
__device__ float g_part[1024];

// ---------------- generic direct conv (f32x2, float4+shuffle window) ----------
template<int K, int STRIDE, bool RELU_IN, bool TRANSPOSED, int CP>
__global__ void __launch_bounds__(128) conv_fwd(
    const float* __restrict__ in, const float* __restrict__ w,
    const float* __restrict__ bias, const float* __restrict__ resid,
    float* __restrict__ out,
    int CIN, int COUT, int H, int W, int OH, int OW, int PAD, int cgroups,
    int relu_out)
{
    constexpr int KK = K * K;
    constexpr int CICH = (K == 4) ? 64 : 128;
    constexpr int SPAN = 3 * STRIDE + K;
    constexpr int NC   = 2 * CP;           // couts per block
    __shared__ __align__(16) float sw[CICH * KK * NC];

    int t   = threadIdx.x;
    int tx  = t & 15, ty = t >> 4;
    int ox0 = blockIdx.x * 64 + tx * 4;
    int oy  = blockIdx.y * 8 + ty;
    int n   = blockIdx.z / cgroups;
    int co0 = (blockIdx.z % cgroups) * NC;

    u64 acc2[CP][4];
#pragma unroll
    for (int cp = 0; cp < CP; cp++)
#pragma unroll
        for (int p = 0; p < 4; p++) acc2[cp][p] = 0ull;

    for (int ci0 = 0; ci0 < CIN; ci0 += CICH) {
        int cich = min(CICH, CIN - ci0);
        int nw = cich * KK * NC;
        __syncthreads();
        for (int i = t; i < nw; i += 128) {
            int c  = i & (NC - 1);
            int r  = i / NC;
            int ci = r / KK;
            int kk = r - ci * KK;
            int ky = kk / K, kx = kk - ky * K;
            int co = co0 + c;
            float v = 0.f;
            if (co < COUT) {
                if (TRANSPOSED)
                    v = w[(((ci0 + ci) * COUT + co) * K + (K - 1 - ky)) * K + (K - 1 - kx)];
                else
                    v = w[((co * CIN + (ci0 + ci)) * K + ky) * K + kx];
            }
            sw[i] = v;
        }
        __syncthreads();

        const float* inb = in + (n * CIN + ci0) * H * W;
        for (int ci = 0; ci < cich; ci++) {
            const float* inc = inb + ci * H * W;
            const float* wci = sw + ci * KK * NC;
#pragma unroll
            for (int ky = 0; ky < K; ky++) {
                int iy = oy * STRIDE - PAD + ky;
                bool vy = (unsigned)iy < (unsigned)H;
                const float* rowp = inc + (vy ? iy : 0) * W;
                u64 ivs[SPAN];

                if constexpr (STRIDE == 1 && K == 3) {
                    float4 c = make_float4(0.f, 0.f, 0.f, 0.f);
                    if (vy) c = *(const float4*)(rowp + ox0);
                    float l = __shfl_up_sync(0xffffffffu, c.w, 1);
                    float r = __shfl_down_sync(0xffffffffu, c.x, 1);
                    if (tx == 0)  l = (vy && ox0 > 0)       ? __ldg(rowp + ox0 - 1) : 0.f;
                    if (tx == 15) r = (vy && ox0 + 4 < W)   ? __ldg(rowp + ox0 + 4) : 0.f;
                    float vv[6] = {l, c.x, c.y, c.z, c.w, r};
#pragma unroll
                    for (int q = 0; q < 6; q++) {
                        float v = vv[q];
                        if (RELU_IN) v = fmaxf(v, 0.f);
                        ivs[q] = pk2(v);
                    }
                } else if constexpr (K == 1) {
                    float4 c = make_float4(0.f, 0.f, 0.f, 0.f);
                    if (vy) c = *(const float4*)(rowp + ox0);
                    float vv[4] = {c.x, c.y, c.z, c.w};
#pragma unroll
                    for (int q = 0; q < 4; q++) {
                        float v = vv[q];
                        if (RELU_IN) v = fmaxf(v, 0.f);
                        ivs[q] = pk2(v);
                    }
                } else {  // K == 4, STRIDE == 2
                    int a0 = 2 * ox0;
                    float4 f0 = make_float4(0.f, 0.f, 0.f, 0.f);
                    float4 f1 = make_float4(0.f, 0.f, 0.f, 0.f);
                    if (vy) {
                        f0 = *(const float4*)(rowp + a0);
                        f1 = *(const float4*)(rowp + a0 + 4);
                    }
                    float l = __shfl_up_sync(0xffffffffu, f1.w, 1);
                    float r = __shfl_down_sync(0xffffffffu, f0.x, 1);
                    if (tx == 0)  l = (vy && a0 > 0)      ? __ldg(rowp + a0 - 1) : 0.f;
                    if (tx == 15) r = (vy && a0 + 8 < W)  ? __ldg(rowp + a0 + 8) : 0.f;
                    float vv[10] = {l, f0.x, f0.y, f0.z, f0.w, f1.x, f1.y, f1.z, f1.w, r};
#pragma unroll
                    for (int q = 0; q < 10; q++) {
                        float v = vv[q];
                        if (RELU_IN) v = fmaxf(v, 0.f);
                        ivs[q] = pk2(v);
                    }
                }

#pragma unroll
                for (int kx = 0; kx < K; kx++) {
                    const float* wp = wci + (ky * K + kx) * NC;
                    u64 wv[CP];
#pragma unroll
                    for (int q = 0; q < CP / 2; q++) {
                        ulonglong2 ww = *(const ulonglong2*)(wp + q * 4);
                        wv[2 * q] = ww.x; wv[2 * q + 1] = ww.y;
                    }
                    if (CP & 1) wv[CP - 1] = *(const u64*)(wp + (CP - 1) * 2);
#pragma unroll
                    for (int cp = 0; cp < CP; cp++)
#pragma unroll
                        for (int p = 0; p < 4; p++)
                            fma2(acc2[cp][p], ivs[p * STRIDE + kx], wv[cp]);
                }
            }
        }
    }

#pragma unroll
    for (int cp = 0; cp < CP; cp++) {
        float2 v[4];
#pragma unroll
        for (int p = 0; p < 4; p++) v[p] = upk(acc2[cp][p]);
#pragma unroll
        for (int h2 = 0; h2 < 2; h2++) {
            int co = co0 + cp * 2 + h2;
            if (co >= COUT) continue;
            float b = bias ? __ldg(bias + co) : 0.f;
            int ob = ((n * COUT + co) * OH + oy) * OW + ox0;
#pragma unroll
            for (int p = 0; p < 4; p++) {
                float val = (h2 ? v[p].y : v[p].x) + b;
                if (resid) val += resid[ob + p];
                if (relu_out) val = fmaxf(val, 0.f);
                out[ob + p] = val;
            }
        }
    }
}

// ---------------- transposed conv, stride 2, K=4, pad 1 (f32x2, f4+shuffle) ---
template<int CP>
__global__ void __launch_bounds__(128) convt_s2(
    const float* __restrict__ in, const float* __restrict__ w,
    const float* __restrict__ bias, float* __restrict__ out,
    int CIN, int COUT, int H, int W, int cgroups, int relu_in, int relu_out)
{
    constexpr int NC = 2 * CP;
    __shared__ __align__(16) float sw[64 * 16 * NC];
    int t = threadIdx.x;
    int tx = t & 15, tyv = t >> 4;
    int parity = blockIdx.x & 1;
    int xch    = blockIdx.x >> 1;
    int OH = 2 * H, OW = 2 * W;
    int ox0 = xch * 128 + 8 * tx + parity;
    int oy  = blockIdx.y * 8 + tyv;
    int n   = blockIdx.z / cgroups;
    int co0 = (blockIdx.z % cgroups) * NC;

    int kyp = (oy + 1) & 1;
    int kxp = (ox0 + 1) & 1;          // = 1 - parity (uniform per block)
    int a0  = (ox0 - parity) >> 1;    // aligned float4 base in input x

    u64 acc2[CP][4];
#pragma unroll
    for (int cp = 0; cp < CP; cp++)
#pragma unroll
        for (int p = 0; p < 4; p++) acc2[cp][p] = 0ull;

    for (int ci0 = 0; ci0 < CIN; ci0 += 64) {
        int cich = min(64, CIN - ci0);
        int nw = cich * 16 * NC;
        __syncthreads();
        for (int i = t; i < nw; i += 128) {
            int c  = i & (NC - 1);
            int r  = i / NC;
            int ci = r >> 4;
            int kk = r & 15;
            int co = co0 + c;
            sw[i] = (co < COUT) ? w[((ci0 + ci) * COUT + co) * 16 + kk] : 0.f;
        }
        __syncthreads();

        for (int ci = 0; ci < cich; ci++) {
            const float* inc = in + (n * CIN + ci0 + ci) * H * W;
            const float* wci = sw + ci * 16 * NC;
#pragma unroll
            for (int ky2 = 0; ky2 < 2; ky2++) {
                int ky = kyp + 2 * ky2;
                int iy = (oy + 1 - ky) >> 1;
                bool vy = (unsigned)iy < (unsigned)H;
                const float* rowp = inc + (vy ? iy : 0) * W;
                float4 c = make_float4(0.f, 0.f, 0.f, 0.f);
                if (vy) c = *(const float4*)(rowp + a0);
                u64 ivs[5];
                if (parity == 0) {
                    float l = __shfl_up_sync(0xffffffffu, c.w, 1);
                    if (tx == 0) l = (vy && a0 > 0) ? __ldg(rowp + a0 - 1) : 0.f;
                    float vv[5] = {l, c.x, c.y, c.z, c.w};
#pragma unroll
                    for (int q = 0; q < 5; q++) {
                        float v = vv[q];
                        if (relu_in) v = fmaxf(v, 0.f);
                        ivs[q] = pk2(v);
                    }
                } else {
                    float r = __shfl_down_sync(0xffffffffu, c.x, 1);
                    if (tx == 15) r = (vy && a0 + 4 < W) ? __ldg(rowp + a0 + 4) : 0.f;
                    float vv[5] = {c.x, c.y, c.z, c.w, r};
#pragma unroll
                    for (int q = 0; q < 5; q++) {
                        float v = vv[q];
                        if (relu_in) v = fmaxf(v, 0.f);
                        ivs[q] = pk2(v);
                    }
                }
#pragma unroll
                for (int kx2 = 0; kx2 < 2; kx2++) {
                    int kx  = kxp + 2 * kx2;
                    int ofs = 1 - kx2;
                    const float* wp = wci + (ky * 4 + kx) * NC;
                    u64 wv[CP];
#pragma unroll
                    for (int q = 0; q < CP / 2; q++) {
                        ulonglong2 ww = *(const ulonglong2*)(wp + q * 4);
                        wv[2 * q] = ww.x; wv[2 * q + 1] = ww.y;
                    }
                    if (CP & 1) wv[CP - 1] = *(const u64*)(wp + (CP - 1) * 2);
#pragma unroll
                    for (int cp = 0; cp < CP; cp++)
#pragma unroll
                        for (int p = 0; p < 4; p++)
                            fma2(acc2[cp][p], ivs[ofs + p], wv[cp]);
                }
            }
        }
    }

#pragma unroll
    for (int cp = 0; cp < CP; cp++) {
        float2 v[4];
#pragma unroll
        for (int p = 0; p < 4; p++) v[p] = upk(acc2[cp][p]);
#pragma unroll
        for (int h2 = 0; h2 < 2; h2++) {
            int co = co0 + cp * 2 + h2;
            if (co >= COUT) continue;
            float b = bias ? __ldg(bias + co) : 0.f;
#pragma unroll
            for (int p = 0; p < 4; p++) {
                int ox = ox0 + 2 * p;
                int o = ((n * COUT + co) * OH + oy) * OW + ox;
                float val = (h2 ? v[p].y : v[p].x) + b;
                if (relu_out) val = fmaxf(val, 0.f);
                out[o] = val;
            }
        }
    }
}

// ---------------- W1 transpose for fused encoder res block --------------------
// w1t[(ci*9+tap)*32 + co] = w1[co*1152 + ci*9 + tap]
__global__ void __launch_bounds__(256) transpose_w1(
    const float* __restrict__ w1, float* __restrict__ w1t)
{
    int i = blockIdx.x * 256 + threadIdx.x;
    if (i < 36864) {
        int co = i & 31;
        int r  = i >> 5;
        w1t[i] = w1[co * 1152 + r];
    }
}

// ---------------- fused ENCODER residual iteration (smem-resident stripe) -----
// x_out = x_in + W2 * relu(W1 (*) relu(x_in)), W1:[32,128,3,3], W2:[128,32,1,1]
// Block: 4-row stripe x image. smem: xsr (relu'd x, 128ch x 6 rows) 196608B @0;
// h_s [32][4][64] 32768B @196608. Total 229376.
#define ESM_TOTAL 229376

__global__ void __launch_bounds__(256) encres_fused(
    const float* __restrict__ xin, const float* __restrict__ w1t,
    const float* __restrict__ w2g, float* __restrict__ xout)
{
    extern __shared__ unsigned char smraw[];
    float4* xs4 = (float4*)smraw;             // [128][6][16] relu'd
    float*  h_s = (float*)(smraw + 196608);   // [32][4][64]

    int t   = threadIdx.x;
    int by  = blockIdx.x;     // 0..15 stripe
    int n   = blockIdx.y;     // 0..15 image
    int oy0 = by * 4;

    const float4* xin4 = (const float4*)(xin + n * 128 * 4096);

    // stage relu'd x stripe (6 rows incl halo), float4 coalesced
    for (int i = t; i < 12288; i += 256) {
        int x4 = i & 15;
        int rr = (i >> 4) % 6;
        int ci = i / 96;
        int gy = oy0 - 1 + rr;
        float4 v = make_float4(0.f, 0.f, 0.f, 0.f);
        if ((unsigned)gy < 64u) v = xin4[(ci * 64 + gy) * 16 + x4];
        v.x = fmaxf(v.x, 0.f); v.y = fmaxf(v.y, 0.f);
        v.z = fmaxf(v.z, 0.f); v.w = fmaxf(v.w, 0.f);
        xs4[(ci * 6 + rr) * 16 + x4] = v;
    }
    __syncthreads();

    // phase 1: 16 cout-pairs x 16 x-groups
    int cp = t >> 4, xg = t & 15;
    const u64* w1tu = (const u64*)w1t;

    u64 acc2[4][4];
#pragma unroll
    for (int rr = 0; rr < 4; rr++)
#pragma unroll
        for (int p = 0; p < 4; p++) acc2[rr][p] = 0ull;

    u64 wreg[9];
#pragma unroll
    for (int tap = 0; tap < 9; tap++)
        wreg[tap] = __ldg(w1tu + tap * 16 + cp);

    for (int ci = 0; ci < 128; ci++) {
        u64 wnxt[9];
        if (ci < 127) {
#pragma unroll
            for (int tap = 0; tap < 9; tap++)
                wnxt[tap] = __ldg(w1tu + ((ci + 1) * 9 + tap) * 16 + cp);
        }
#pragma unroll
        for (int iy = 0; iy < 6; iy++) {
            float4 c = xs4[(ci * 6 + iy) * 16 + xg];
            float l = __shfl_up_sync(0xffffffffu, c.w, 1);
            float r = __shfl_down_sync(0xffffffffu, c.x, 1);
            if (xg == 0)  l = 0.f;
            if (xg == 15) r = 0.f;
            u64 p[6];
            p[0] = pk2(l);   p[1] = pk2(c.x); p[2] = pk2(c.y);
            p[3] = pk2(c.z); p[4] = pk2(c.w); p[5] = pk2(r);
#pragma unroll
            for (int ky = 0; ky < 3; ky++) {
                int rr = iy - ky;
                if (rr < 0 || rr > 3) continue;
#pragma unroll
                for (int kx = 0; kx < 3; kx++) {
                    u64 wv = wreg[ky * 3 + kx];
                    fma2(acc2[rr][0], p[kx    ], wv);
                    fma2(acc2[rr][1], p[kx + 1], wv);
                    fma2(acc2[rr][2], p[kx + 2], wv);
                    fma2(acc2[rr][3], p[kx + 3], wv);
                }
            }
        }
#pragma unroll
        for (int tap = 0; tap < 9; tap++) wreg[tap] = wnxt[tap];
    }

    // write relu'd h
#pragma unroll
    for (int rr = 0; rr < 4; rr++)
#pragma unroll
        for (int p = 0; p < 4; p++) {
            float2 v = upk(acc2[rr][p]);
            h_s[((2 * cp)     * 4 + rr) * 64 + xg * 4 + p] = fmaxf(v.x, 0.f);
            h_s[((2 * cp + 1) * 4 + rr) * 64 + xg * 4 + p] = fmaxf(v.y, 0.f);
        }
    __syncthreads();

    // phase 2: x + W2*h. 8192 quads / 256 threads.
    float4* xout4 = (float4*)(xout + n * 128 * 4096);
#pragma unroll 2
    for (int k = 0; k < 32; k++) {
        int e   = k * 256 + t;
        int x4  = e & 15;
        int row = (e >> 4) & 3;
        int co  = e >> 6;
        int gi  = (co * 64 + oy0 + row) * 16 + x4;
        float4 s = xin4[gi];  // raw residual
        const float* wrow = w2g + co * 32;
#pragma unroll 8
        for (int ci = 0; ci < 32; ci++) {
            float wv = __ldg(wrow + ci);
            const float* hp = h_s + (ci * 4 + row) * 64 + x4 * 4;
            s.x += wv * hp[0]; s.y += wv * hp[1];
            s.z += wv * hp[2]; s.w += wv * hp[3];
        }
        xout4[gi] = s;
    }
}

// ---------------- fused decoder residual iteration (smem-resident stripe) -----
#define DSM_TOTAL 215040

__global__ void __launch_bounds__(256) decres_fused(
    const float* __restrict__ xin, const float* __restrict__ w1,
    const float* __restrict__ w2, float* __restrict__ xout)
{
    extern __shared__ unsigned char smraw[];
    float4* xs4   = (float4*)smraw;
    float*  sw1f  = (float*)(smraw + 196608);
    u64*    sw1u  = (u64*)  (smraw + 196608);
    float*  sw2   = (float*)(smraw + 205824);
    u64*    part  = (u64*)  (smraw + 206848);
    float*  h0    = (float*)(smraw + 212992);   // [4][64]
    float*  h1    = (float*)(smraw + 214016);   // [4][64]

    int t   = threadIdx.x;
    int by  = blockIdx.x;     // 0..15 stripe
    int n   = blockIdx.y;     // 0..15 image
    int oy0 = by * 4;

    for (int i = t; i < 2304; i += 256) {
        int ch = i & 1, r = i >> 1;            // r = ci*9 + k
        sw1f[i] = w1[ch * 1152 + r];
    }
    if (t < 256) sw2[t] = w2[t];

    const float4* xin4 = (const float4*)(xin + n * 128 * 4096);
    for (int i = t; i < 12288; i += 256) {
        int x4 = i & 15;
        int rr = (i >> 4) % 6;
        int ci = i / 96;
        int gy = oy0 - 1 + rr;
        float4 v;
        if ((unsigned)gy < 64u) v = xin4[(ci * 64 + gy) * 16 + x4];
        else { v.x = v.y = v.z = v.w = 0.f; }
        xs4[i] = v;
    }
    __syncthreads();

    int g   = t >> 6;
    int t64 = t & 63;
    int row = t64 >> 4;
    int xg  = t64 & 15;

    u64 a[4] = {0ull, 0ull, 0ull, 0ull};
    for (int ci = g * 32; ci < g * 32 + 32; ci++) {
        const u64* wci = sw1u + ci * 9;
#pragma unroll
        for (int ky = 0; ky < 3; ky++) {
            float4 c = xs4[(ci * 6 + row + ky) * 16 + xg];
            float l = __shfl_up_sync(0xffffffffu, c.w, 1);
            float r = __shfl_down_sync(0xffffffffu, c.x, 1);
            if (xg == 0)  l = 0.f;
            if (xg == 15) r = 0.f;
            u64 pw[6];
            pw[0] = pk2(fmaxf(l,   0.f));
            pw[1] = pk2(fmaxf(c.x, 0.f));
            pw[2] = pk2(fmaxf(c.y, 0.f));
            pw[3] = pk2(fmaxf(c.z, 0.f));
            pw[4] = pk2(fmaxf(c.w, 0.f));
            pw[5] = pk2(fmaxf(r,   0.f));
#pragma unroll
            for (int kx = 0; kx < 3; kx++) {
                u64 wv = wci[ky * 3 + kx];
                fma2(a[0], pw[kx    ], wv);
                fma2(a[1], pw[kx + 1], wv);
                fma2(a[2], pw[kx + 2], wv);
                fma2(a[3], pw[kx + 3], wv);
            }
        }
    }
    if (g > 0) {
#pragma unroll
        for (int p = 0; p < 4; p++) part[(g - 1) * 256 + t64 * 4 + p] = a[p];
    }
    __syncthreads();
    if (t < 64) {
#pragma unroll
        for (int p = 0; p < 4; p++) {
            u64 s = a[p];
            s = add2(s, part[      t * 4 + p]);
            s = add2(s, part[256 + t * 4 + p]);
            s = add2(s, part[512 + t * 4 + p]);
            float2 v = upk(s);
            h0[row * 64 + xg * 4 + p] = fmaxf(v.x, 0.f);
            h1[row * 64 + xg * 4 + p] = fmaxf(v.y, 0.f);
        }
    }
    __syncthreads();

    float4* xout4 = (float4*)(xout + n * 128 * 4096);
#pragma unroll 4
    for (int k = 0; k < 32; k++) {
        int e   = k * 256 + t;
        int x4  = e & 15;
        int row2= (e >> 4) & 3;
        int co  = e >> 6;
        int gi = (co * 64 + oy0 + row2) * 16 + x4;
        float4 v = xs4[(co * 6 + row2 + 1) * 16 + x4];
        float w0 = sw2[co * 2], w1v = sw2[co * 2 + 1];
        const float* p0 = h0 + row2 * 64 + x4 * 4;
        const float* p1 = h1 + row2 * 64 + x4 * 4;
        v.x += w0 * p0[0] + w1v * p1[0];
        v.y += w0 * p0[1] + w1v * p1[1];
        v.z += w0 * p0[2] + w1v * p1[2];
        v.w += w0 * p0[3] + w1v * p1[3];
        xout4[gi] = v;
    }
}

// ---------------- vector quantizer -------------------------------------------
__global__ void __launch_bounds__(256) vq_kernel(
    const float* __restrict__ ze, const float* __restrict__ cb,
    float* __restrict__ zq, float* __restrict__ partials)
{
    __shared__ __align__(16) float f_s[64 * 64];
    __shared__ __align__(16) float cb_s[64 * 68];
    __shared__ float norm_s[512];
    __shared__ int   idx_s[64];
    __shared__ float red_s[64];

    int t = threadIdx.x;
    int b = blockIdx.x;
    int n = b >> 6, y = b & 63;

    for (int i = t; i < 4096; i += 256) {
        int d = i >> 6, x = i & 63;
        f_s[i] = ze[((n * 64 + d) * 64 + y) * 64 + x];
    }
    for (int c = t; c < 512; c += 256) {
        float s = 0.f;
        const float* cp = cb + c * 64;
#pragma unroll 8
        for (int d = 0; d < 64; d++) { float v = __ldg(cp + d); s = fmaf(v, v, s); }
        norm_s[c] = s;
    }
    __syncthreads();

    int cxT = t & 15, pyT = t >> 4;
    float best[4] = {3.4e38f, 3.4e38f, 3.4e38f, 3.4e38f};
    int   bidx[4] = {0, 0, 0, 0};

    for (int ch = 0; ch < 8; ch++) {
        __syncthreads();
        for (int i = t; i < 4096; i += 256) {
            int d = i & 63, c = i >> 6;
            cb_s[d * 68 + c] = __ldg(&cb[(ch * 64 + c) * 64 + d]);
        }
        __syncthreads();

        float dot[4][4];
#pragma unroll
        for (int pp = 0; pp < 4; pp++)
#pragma unroll
            for (int cc = 0; cc < 4; cc++) dot[pp][cc] = 0.f;

        for (int d = 0; d < 64; d++) {
            float4 fv4 = *(const float4*)&f_s[d * 64 + pyT * 4];
            float4 cv4 = *(const float4*)&cb_s[d * 68 + cxT * 4];
            float fv[4] = {fv4.x, fv4.y, fv4.z, fv4.w};
            float cv[4] = {cv4.x, cv4.y, cv4.z, cv4.w};
#pragma unroll
            for (int pp = 0; pp < 4; pp++)
#pragma unroll
                for (int cc = 0; cc < 4; cc++)
                    dot[pp][cc] = fmaf(fv[pp], cv[cc], dot[pp][cc]);
        }
#pragma unroll
        for (int cc = 0; cc < 4; cc++) {
            int code = ch * 64 + cxT * 4 + cc;
            float nrm = norm_s[code];
#pragma unroll
            for (int pp = 0; pp < 4; pp++) {
                float dist = fmaf(-2.f, dot[pp][cc], nrm);
                if (dist < best[pp]) { best[pp] = dist; bidx[pp] = code; }
            }
        }
    }

    for (int off = 1; off < 16; off <<= 1) {
#pragma unroll
        for (int pp = 0; pp < 4; pp++) {
            float ob = __shfl_xor_sync(0xffffffffu, best[pp], off);
            int   oi = __shfl_xor_sync(0xffffffffu, bidx[pp], off);
            if (ob < best[pp] || (ob == best[pp] && oi < bidx[pp])) {
                best[pp] = ob; bidx[pp] = oi;
            }
        }
    }
    if (cxT == 0)
#pragma unroll
        for (int pp = 0; pp < 4; pp++) idx_s[pyT * 4 + pp] = bidx[pp];
    __syncthreads();

    for (int i = t; i < 4096; i += 256) {
        int d = i >> 6, x = i & 63;
        zq[((n * 64 + d) * 64 + y) * 64 + x] = __ldg(&cb[idx_s[x] * 64 + d]);
    }

    if (t < 64) {
        int id = idx_s[t];
        const float* cp = cb + id * 64;
        float s = 0.f;
#pragma unroll 8
        for (int d = 0; d < 64; d++) {
            float diff = __ldg(cp + d) - f_s[d * 64 + t];
            s = fmaf(diff, diff, s);
        }
        red_s[t] = s;
    }
    __syncthreads();
    if (t == 0) {
        float s = 0.f;
        for (int i = 0; i < 64; i++) s += red_s[i];
        partials[b] = s;
    }
}

__global__ void __launch_bounds__(256) finalize_loss(
    const float* __restrict__ partials, float* __restrict__ dst)
{
    __shared__ float s[256];
    int t = threadIdx.x;
    float v = 0.f;
    for (int i = t; i < 1024; i += 256) v += partials[i];
    s[t] = v;
    __syncthreads();
    for (int off = 128; off > 0; off >>= 1) {
        if (t < off) s[t] += s[t + off];
        __syncthreads();
    }
    if (t == 0) dst[0] = 1.25f * s[0] / 4194304.f;  // (1 + BETA) * MSE
}

// ---------------- host launcher ----------------------------------------------
extern "C" void kernel_launch(void* const* d_in, const int* in_sizes, int n_in,
                              void* d_out, int out_size)
{
    (void)in_sizes; (void)n_in; (void)out_size;
    const float* x       = (const float*)d_in[0];
    const float* enc_w1  = (const float*)d_in[1];
    const float* enc_b1  = (const float*)d_in[2];
    const float* enc_w2  = (const float*)d_in[3];
    const float* enc_b2  = (const float*)d_in[4];
    const float* enc_w3  = (const float*)d_in[5];
    const float* enc_b3  = (const float*)d_in[6];
    const float* enc_rw1 = (const float*)d_in[7];
    const float* enc_rw2 = (const float*)d_in[8];
    const float* pre_w   = (const float*)d_in[9];
    const float* pre_b   = (const float*)d_in[10];
    const float* cb      = (const float*)d_in[11];
    const float* dec_wt1 = (const float*)d_in[12];
    const float* dec_bt1 = (const float*)d_in[13];
    const float* dec_rw1 = (const float*)d_in[14];
    const float* dec_rw2 = (const float*)d_in[15];
    const float* dec_wt2 = (const float*)d_in[16];
    const float* dec_bt2 = (const float*)d_in[17];
    const float* dec_wt3 = (const float*)d_in[18];
    const float* dec_bt3 = (const float*)d_in[19];
    float* out = (float*)d_out;

    float *pA, *pB, *pB2, *pC, *pE, *pF, *pW1T, *pPart;
    cudaGetSymbolAddress((void**)&pA,  g_A);
    cudaGetSymbolAddress((void**)&pB,  g_B);
    cudaGetSymbolAddress((void**)&pB2, g_B2);
    cudaGetSymbolAddress((void**)&pC,  g_C);
    cudaGetSymbolAddress((void**)&pE,  g_E);
    cudaGetSymbolAddress((void**)&pF,  g_F);
    cudaGetSymbolAddress((void**)&pW1T, g_W1T);
    cudaGetSymbolAddress((void**)&pPart, g_part);

    cudaFuncSetAttribute(decres_fused,
                         cudaFuncAttributeMaxDynamicSharedMemorySize, DSM_TOTAL);
    cudaFuncSetAttribute(encres_fused,
                         cudaFuncAttributeMaxDynamicSharedMemorySize, ESM_TOTAL);

    // encoder
    conv_fwd<4,2,false,false,4><<<dim3(2,16,16*8), 128>>>(
        x, enc_w1, enc_b1, nullptr, pA, 3, 64, 256, 256, 128, 128, 1, 8, 1);
    conv_fwd<4,2,false,false,4><<<dim3(1,8,16*16), 128>>>(
        pA, enc_w2, enc_b2, nullptr, pB, 64, 128, 128, 128, 64, 64, 1, 16, 1);
    conv_fwd<3,1,false,false,4><<<dim3(1,8,16*16), 128>>>(
        pB, enc_w3, enc_b3, nullptr, pC, 128, 128, 64, 64, 64, 64, 1, 16, 0);

    // fused encoder res stack (2 shared-weight iterations), ping-pong pC<->pB
    transpose_w1<<<144, 256>>>(enc_rw1, pW1T);
    encres_fused<<<dim3(16,16), 256, ESM_TOTAL>>>(pC, pW1T, enc_rw2, pB);
    encres_fused<<<dim3(16,16), 256, ESM_TOTAL>>>(pB, pW1T, enc_rw2, pC);

    conv_fwd<1,1,true,false,4><<<dim3(1,8,16*8), 128>>>(
        pC, pre_w, pre_b, nullptr, pE, 128, 64, 64, 64, 64, 64, 0, 8, 0);

    // quantizer
    vq_kernel<<<1024, 256>>>(pE, cb, pF, pPart);
    finalize_loss<<<1, 256>>>(pPart, out + 3145728);

    // decoder
    conv_fwd<3,1,false,true,4><<<dim3(1,8,16*16), 128>>>(
        pF, dec_wt1, dec_bt1, nullptr, pB, 64, 128, 64, 64, 64, 64, 1, 16, 0);
    for (int i = 0; i < 32; i++) {
        const float* src = (i & 1) ? pB2 : pB;
        float*       dst = (i & 1) ? pB  : pB2;
        decres_fused<<<dim3(16,16), 256, DSM_TOTAL>>>(src, dec_rw1, dec_rw2, dst);
    }
    // after 32 iters result is back in pB
    convt_s2<4><<<dim3(2,16,16*8), 128>>>(
        pB, dec_wt2, dec_bt2, pA, 128, 64, 64, 64, 8, 1, 1);
    convt_s2<2><<<dim3(4,32,16*1), 128>>>(
        pA, dec_wt3, dec_bt3, out, 64, 3, 128, 128, 1, 0, 0);
}

// round 13
// speedup vs baseline: 1.4853x; 1.0156x over previous
#include <cuda_runtime.h>
#include <math.h>

typedef unsigned long long u64;

__device__ __forceinline__ u64 pk2(float v) {
    u64 r; asm("mov.b64 %0, {%1,%1};" : "=l"(r) : "f"(v)); return r;
}
__device__ __forceinline__ void fma2(u64& d, u64 a, u64 b) {
    asm("fma.rn.f32x2 %0, %1, %2, %0;" : "+l"(d) : "l"(a), "l"(b));
}
__device__ __forceinline__ float2 upk(u64 v) {
    float2 r; asm("mov.b64 {%0,%1}, %2;" : "=f"(r.x), "=f"(r.y) : "l"(v)); return r;
}
__device__ __forceinline__ u64 add2(u64 a, u64 b) {
    u64 r; asm("add.rn.f32x2 %0, %1, %2;" : "=l"(r) : "l"(a), "l"(b)); return r;
}

// ---------------- scratch (device globals: allocation-free) ------------------
__device__ float g_A [16*64*128*128];   // 67 MB
__device__ float g_B [16*128*64*64];    // 33.5 MB
__device__ float g_B2[16*128*64*64];    // 33.5 MB
__device__ float g_C [16*128*64*64];    // 33.5 MB
__device__ float g_E [16*64*64*64];     // 16.8 MB (z_e)
__device__ float g_F [16*64*64*64];     // 16.8 MB (z_q)
__device__ __align__(16) float g_W1T[128*9*32];  // transposed enc_rw1
__device__ float g_part[1024];

// ---------------- row-tiled 3x3 stride-1 conv, 64x64, COUT=128 ----------------
// thread: 4 rows x 4 px x 4 couts. block 128 = 16 xg x 8 ty (32 rows).
// grid: y = 2 (row halves), z = n*32 + cgroup.
template<bool RELU_IN, bool TRANSPOSED>
__global__ void __launch_bounds__(128) conv3_rt(
    const float* __restrict__ in, const float* __restrict__ w,
    const float* __restrict__ bias, float* __restrict__ out,
    int CIN, int COUT, int relu_out)
{
    __shared__ __align__(16) float sw[128 * 9 * 4];   // [(ci*9+kk)*4 + c]

    int t   = threadIdx.x;
    int tx  = t & 15, ty = t >> 4;
    int ox0 = tx * 4;
    int oy0 = blockIdx.y * 32 + ty * 4;
    int n   = blockIdx.z >> 5;
    int co0 = (blockIdx.z & 31) * 4;

    int nw = CIN * 36;
    for (int i = t; i < nw; i += 128) {
        int c  = i & 3;
        int r  = i >> 2;              // ci*9 + kk
        int ci = r / 9;
        int kk = r - ci * 9;
        int ky = kk / 3, kx = kk - ky * 3;
        int co = co0 + c;
        float v;
        if (TRANSPOSED)
            v = w[((ci * COUT + co) * 3 + (2 - ky)) * 3 + (2 - kx)];
        else
            v = w[((co * CIN + ci) * 3 + ky) * 3 + kx];
        sw[i] = v;
    }
    __syncthreads();

    u64 acc[2][4][4];                 // [cp][row][px]
#pragma unroll
    for (int cp = 0; cp < 2; cp++)
#pragma unroll
        for (int rr = 0; rr < 4; rr++)
#pragma unroll
            for (int p = 0; p < 4; p++) acc[cp][rr][p] = 0ull;

    const float* inb = in + n * CIN * 4096;
    for (int ci = 0; ci < CIN; ci++) {
        const float* inc = inb + ci * 4096;
        const float* wci = sw + ci * 36;
        u64 wv[9][2];
#pragma unroll
        for (int tap = 0; tap < 9; tap++) {
            ulonglong2 ww = *(const ulonglong2*)(wci + tap * 4);
            wv[tap][0] = ww.x; wv[tap][1] = ww.y;
        }
#pragma unroll
        for (int iy6 = 0; iy6 < 6; iy6++) {
            int iy = oy0 - 1 + iy6;
            bool vy = (unsigned)iy < 64u;
            float4 c = make_float4(0.f, 0.f, 0.f, 0.f);
            if (vy) c = *(const float4*)(inc + iy * 64 + ox0);
            float l = __shfl_up_sync(0xffffffffu, c.w, 1);
            float r = __shfl_down_sync(0xffffffffu, c.x, 1);
            if (tx == 0)  l = 0.f;
            if (tx == 15) r = 0.f;
            if (RELU_IN) {
                l = fmaxf(l, 0.f);     r = fmaxf(r, 0.f);
                c.x = fmaxf(c.x, 0.f); c.y = fmaxf(c.y, 0.f);
                c.z = fmaxf(c.z, 0.f); c.w = fmaxf(c.w, 0.f);
            }
            u64 p[6];
            p[0] = pk2(l);   p[1] = pk2(c.x); p[2] = pk2(c.y);
            p[3] = pk2(c.z); p[4] = pk2(c.w); p[5] = pk2(r);
#pragma unroll
            for (int ky = 0; ky < 3; ky++) {
                int rr = iy6 - ky;
                if (rr < 0 || rr > 3) continue;
#pragma unroll
                for (int kx = 0; kx < 3; kx++) {
                    u64 w0 = wv[ky * 3 + kx][0];
                    u64 w1 = wv[ky * 3 + kx][1];
#pragma unroll
                    for (int q = 0; q < 4; q++) {
                        fma2(acc[0][rr][q], p[kx + q], w0);
                        fma2(acc[1][rr][q], p[kx + q], w1);
                    }
                }
            }
        }
    }

#pragma unroll
    for (int cp = 0; cp < 2; cp++)
#pragma unroll
        for (int h2 = 0; h2 < 2; h2++) {
            int co = co0 + cp * 2 + h2;
            float b = bias ? __ldg(bias + co) : 0.f;
#pragma unroll
            for (int rr = 0; rr < 4; rr++) {
                float4 o;
                float2 v0 = upk(acc[cp][rr][0]);
                float2 v1 = upk(acc[cp][rr][1]);
                float2 v2 = upk(acc[cp][rr][2]);
                float2 v3 = upk(acc[cp][rr][3]);
                o.x = (h2 ? v0.y : v0.x) + b;
                o.y = (h2 ? v1.y : v1.x) + b;
                o.z = (h2 ? v2.y : v2.x) + b;
                o.w = (h2 ? v3.y : v3.x) + b;
                if (relu_out) {
                    o.x = fmaxf(o.x, 0.f); o.y = fmaxf(o.y, 0.f);
                    o.z = fmaxf(o.z, 0.f); o.w = fmaxf(o.w, 0.f);
                }
                *(float4*)(out + ((n * COUT + co) * 64 + oy0 + rr) * 64 + ox0) = o;
            }
        }
}

// ---------------- generic direct conv (f32x2, float4+shuffle window) ----------
template<int K, int STRIDE, bool RELU_IN, bool TRANSPOSED, int CP>
__global__ void __launch_bounds__(128) conv_fwd(
    const float* __restrict__ in, const float* __restrict__ w,
    const float* __restrict__ bias, const float* __restrict__ resid,
    float* __restrict__ out,
    int CIN, int COUT, int H, int W, int OH, int OW, int PAD, int cgroups,
    int relu_out)
{
    constexpr int KK = K * K;
    constexpr int CICH = (K == 4) ? 64 : 128;
    constexpr int SPAN = 3 * STRIDE + K;
    constexpr int NC   = 2 * CP;
    __shared__ __align__(16) float sw[CICH * KK * NC];

    int t   = threadIdx.x;
    int tx  = t & 15, ty = t >> 4;
    int ox0 = blockIdx.x * 64 + tx * 4;
    int oy  = blockIdx.y * 8 + ty;
    int n   = blockIdx.z / cgroups;
    int co0 = (blockIdx.z % cgroups) * NC;

    u64 acc2[CP][4];
#pragma unroll
    for (int cp = 0; cp < CP; cp++)
#pragma unroll
        for (int p = 0; p < 4; p++) acc2[cp][p] = 0ull;

    for (int ci0 = 0; ci0 < CIN; ci0 += CICH) {
        int cich = min(CICH, CIN - ci0);
        int nw = cich * KK * NC;
        __syncthreads();
        for (int i = t; i < nw; i += 128) {
            int c  = i & (NC - 1);
            int r  = i / NC;
            int ci = r / KK;
            int kk = r - ci * KK;
            int ky = kk / K, kx = kk - ky * K;
            int co = co0 + c;
            float v = 0.f;
            if (co < COUT) {
                if (TRANSPOSED)
                    v = w[(((ci0 + ci) * COUT + co) * K + (K - 1 - ky)) * K + (K - 1 - kx)];
                else
                    v = w[((co * CIN + (ci0 + ci)) * K + ky) * K + kx];
            }
            sw[i] = v;
        }
        __syncthreads();

        const float* inb = in + (n * CIN + ci0) * H * W;
        for (int ci = 0; ci < cich; ci++) {
            const float* inc = inb + ci * H * W;
            const float* wci = sw + ci * KK * NC;
#pragma unroll
            for (int ky = 0; ky < K; ky++) {
                int iy = oy * STRIDE - PAD + ky;
                bool vy = (unsigned)iy < (unsigned)H;
                const float* rowp = inc + (vy ? iy : 0) * W;
                u64 ivs[SPAN];

                if constexpr (STRIDE == 1 && K == 3) {
                    float4 c = make_float4(0.f, 0.f, 0.f, 0.f);
                    if (vy) c = *(const float4*)(rowp + ox0);
                    float l = __shfl_up_sync(0xffffffffu, c.w, 1);
                    float r = __shfl_down_sync(0xffffffffu, c.x, 1);
                    if (tx == 0)  l = (vy && ox0 > 0)       ? __ldg(rowp + ox0 - 1) : 0.f;
                    if (tx == 15) r = (vy && ox0 + 4 < W)   ? __ldg(rowp + ox0 + 4) : 0.f;
                    float vv[6] = {l, c.x, c.y, c.z, c.w, r};
#pragma unroll
                    for (int q = 0; q < 6; q++) {
                        float v = vv[q];
                        if (RELU_IN) v = fmaxf(v, 0.f);
                        ivs[q] = pk2(v);
                    }
                } else if constexpr (K == 1) {
                    float4 c = make_float4(0.f, 0.f, 0.f, 0.f);
                    if (vy) c = *(const float4*)(rowp + ox0);
                    float vv[4] = {c.x, c.y, c.z, c.w};
#pragma unroll
                    for (int q = 0; q < 4; q++) {
                        float v = vv[q];
                        if (RELU_IN) v = fmaxf(v, 0.f);
                        ivs[q] = pk2(v);
                    }
                } else {  // K == 4, STRIDE == 2
                    int a0 = 2 * ox0;
                    float4 f0 = make_float4(0.f, 0.f, 0.f, 0.f);
                    float4 f1 = make_float4(0.f, 0.f, 0.f, 0.f);
                    if (vy) {
                        f0 = *(const float4*)(rowp + a0);
                        f1 = *(const float4*)(rowp + a0 + 4);
                    }
                    float l = __shfl_up_sync(0xffffffffu, f1.w, 1);
                    float r = __shfl_down_sync(0xffffffffu, f0.x, 1);
                    if (tx == 0)  l = (vy && a0 > 0)      ? __ldg(rowp + a0 - 1) : 0.f;
                    if (tx == 15) r = (vy && a0 + 8 < W)  ? __ldg(rowp + a0 + 8) : 0.f;
                    float vv[10] = {l, f0.x, f0.y, f0.z, f0.w, f1.x, f1.y, f1.z, f1.w, r};
#pragma unroll
                    for (int q = 0; q < 10; q++) {
                        float v = vv[q];
                        if (RELU_IN) v = fmaxf(v, 0.f);
                        ivs[q] = pk2(v);
                    }
                }

#pragma unroll
                for (int kx = 0; kx < K; kx++) {
                    const float* wp = wci + (ky * K + kx) * NC;
                    u64 wv[CP];
#pragma unroll
                    for (int q = 0; q < CP / 2; q++) {
                        ulonglong2 ww = *(const ulonglong2*)(wp + q * 4);
                        wv[2 * q] = ww.x; wv[2 * q + 1] = ww.y;
                    }
                    if (CP & 1) wv[CP - 1] = *(const u64*)(wp + (CP - 1) * 2);
#pragma unroll
                    for (int cp = 0; cp < CP; cp++)
#pragma unroll
                        for (int p = 0; p < 4; p++)
                            fma2(acc2[cp][p], ivs[p * STRIDE + kx], wv[cp]);
                }
            }
        }
    }

#pragma unroll
    for (int cp = 0; cp < CP; cp++) {
        float2 v[4];
#pragma unroll
        for (int p = 0; p < 4; p++) v[p] = upk(acc2[cp][p]);
#pragma unroll
        for (int h2 = 0; h2 < 2; h2++) {
            int co = co0 + cp * 2 + h2;
            if (co >= COUT) continue;
            float b = bias ? __ldg(bias + co) : 0.f;
            int ob = ((n * COUT + co) * OH + oy) * OW + ox0;
#pragma unroll
            for (int p = 0; p < 4; p++) {
                float val = (h2 ? v[p].y : v[p].x) + b;
                if (resid) val += resid[ob + p];
                if (relu_out) val = fmaxf(val, 0.f);
                out[ob + p] = val;
            }
        }
    }
}

// ---------------- transposed conv, stride 2, K=4, pad 1 (f32x2, f4+shuffle) ---
template<int CP>
__global__ void __launch_bounds__(128) convt_s2(
    const float* __restrict__ in, const float* __restrict__ w,
    const float* __restrict__ bias, float* __restrict__ out,
    int CIN, int COUT, int H, int W, int cgroups, int relu_in, int relu_out)
{
    constexpr int NC = 2 * CP;
    __shared__ __align__(16) float sw[64 * 16 * NC];
    int t = threadIdx.x;
    int tx = t & 15, tyv = t >> 4;
    int parity = blockIdx.x & 1;
    int xch    = blockIdx.x >> 1;
    int OH = 2 * H, OW = 2 * W;
    int ox0 = xch * 128 + 8 * tx + parity;
    int oy  = blockIdx.y * 8 + tyv;
    int n   = blockIdx.z / cgroups;
    int co0 = (blockIdx.z % cgroups) * NC;

    int kyp = (oy + 1) & 1;
    int kxp = (ox0 + 1) & 1;
    int a0  = (ox0 - parity) >> 1;

    u64 acc2[CP][4];
#pragma unroll
    for (int cp = 0; cp < CP; cp++)
#pragma unroll
        for (int p = 0; p < 4; p++) acc2[cp][p] = 0ull;

    for (int ci0 = 0; ci0 < CIN; ci0 += 64) {
        int cich = min(64, CIN - ci0);
        int nw = cich * 16 * NC;
        __syncthreads();
        for (int i = t; i < nw; i += 128) {
            int c  = i & (NC - 1);
            int r  = i / NC;
            int ci = r >> 4;
            int kk = r & 15;
            int co = co0 + c;
            sw[i] = (co < COUT) ? w[((ci0 + ci) * COUT + co) * 16 + kk] : 0.f;
        }
        __syncthreads();

        for (int ci = 0; ci < cich; ci++) {
            const float* inc = in + (n * CIN + ci0 + ci) * H * W;
            const float* wci = sw + ci * 16 * NC;
#pragma unroll
            for (int ky2 = 0; ky2 < 2; ky2++) {
                int ky = kyp + 2 * ky2;
                int iy = (oy + 1 - ky) >> 1;
                bool vy = (unsigned)iy < (unsigned)H;
                const float* rowp = inc + (vy ? iy : 0) * W;
                float4 c = make_float4(0.f, 0.f, 0.f, 0.f);
                if (vy) c = *(const float4*)(rowp + a0);
                u64 ivs[5];
                if (parity == 0) {
                    float l = __shfl_up_sync(0xffffffffu, c.w, 1);
                    if (tx == 0) l = (vy && a0 > 0) ? __ldg(rowp + a0 - 1) : 0.f;
                    float vv[5] = {l, c.x, c.y, c.z, c.w};
#pragma unroll
                    for (int q = 0; q < 5; q++) {
                        float v = vv[q];
                        if (relu_in) v = fmaxf(v, 0.f);
                        ivs[q] = pk2(v);
                    }
                } else {
                    float r = __shfl_down_sync(0xffffffffu, c.x, 1);
                    if (tx == 15) r = (vy && a0 + 4 < W) ? __ldg(rowp + a0 + 4) : 0.f;
                    float vv[5] = {c.x, c.y, c.z, c.w, r};
#pragma unroll
                    for (int q = 0; q < 5; q++) {
                        float v = vv[q];
                        if (relu_in) v = fmaxf(v, 0.f);
                        ivs[q] = pk2(v);
                    }
                }
#pragma unroll
                for (int kx2 = 0; kx2 < 2; kx2++) {
                    int kx  = kxp + 2 * kx2;
                    int ofs = 1 - kx2;
                    const float* wp = wci + (ky * 4 + kx) * NC;
                    u64 wv[CP];
#pragma unroll
                    for (int q = 0; q < CP / 2; q++) {
                        ulonglong2 ww = *(const ulonglong2*)(wp + q * 4);
                        wv[2 * q] = ww.x; wv[2 * q + 1] = ww.y;
                    }
                    if (CP & 1) wv[CP - 1] = *(const u64*)(wp + (CP - 1) * 2);
#pragma unroll
                    for (int cp = 0; cp < CP; cp++)
#pragma unroll
                        for (int p = 0; p < 4; p++)
                            fma2(acc2[cp][p], ivs[ofs + p], wv[cp]);
                }
            }
        }
    }

#pragma unroll
    for (int cp = 0; cp < CP; cp++) {
        float2 v[4];
#pragma unroll
        for (int p = 0; p < 4; p++) v[p] = upk(acc2[cp][p]);
#pragma unroll
        for (int h2 = 0; h2 < 2; h2++) {
            int co = co0 + cp * 2 + h2;
            if (co >= COUT) continue;
            float b = bias ? __ldg(bias + co) : 0.f;
#pragma unroll
            for (int p = 0; p < 4; p++) {
                int ox = ox0 + 2 * p;
                int o = ((n * COUT + co) * OH + oy) * OW + ox;
                float val = (h2 ? v[p].y : v[p].x) + b;
                if (relu_out) val = fmaxf(val, 0.f);
                out[o] = val;
            }
        }
    }
}

// ---------------- W1 transpose for fused encoder res block --------------------
__global__ void __launch_bounds__(256) transpose_w1(
    const float* __restrict__ w1, float* __restrict__ w1t)
{
    int i = blockIdx.x * 256 + threadIdx.x;
    if (i < 36864) {
        int co = i & 31;
        int r  = i >> 5;
        w1t[i] = w1[co * 1152 + r];
    }
}

// ---------------- fused ENCODER residual iteration (smem-resident stripe) -----
#define ESM_TOTAL 229376

__global__ void __launch_bounds__(256) encres_fused(
    const float* __restrict__ xin, const float* __restrict__ w1t,
    const float* __restrict__ w2g, float* __restrict__ xout)
{
    extern __shared__ unsigned char smraw[];
    float4* xs4 = (float4*)smraw;             // [128][6][16] relu'd
    float*  h_s = (float*)(smraw + 196608);   // [32][4][64]

    int t   = threadIdx.x;
    int by  = blockIdx.x;
    int n   = blockIdx.y;
    int oy0 = by * 4;

    const float4* xin4 = (const float4*)(xin + n * 128 * 4096);

    for (int i = t; i < 12288; i += 256) {
        int x4 = i & 15;
        int rr = (i >> 4) % 6;
        int ci = i / 96;
        int gy = oy0 - 1 + rr;
        float4 v = make_float4(0.f, 0.f, 0.f, 0.f);
        if ((unsigned)gy < 64u) v = xin4[(ci * 64 + gy) * 16 + x4];
        v.x = fmaxf(v.x, 0.f); v.y = fmaxf(v.y, 0.f);
        v.z = fmaxf(v.z, 0.f); v.w = fmaxf(v.w, 0.f);
        xs4[(ci * 6 + rr) * 16 + x4] = v;
    }
    __syncthreads();

    int cp = t >> 4, xg = t & 15;
    const u64* w1tu = (const u64*)w1t;

    u64 acc2[4][4];
#pragma unroll
    for (int rr = 0; rr < 4; rr++)
#pragma unroll
        for (int p = 0; p < 4; p++) acc2[rr][p] = 0ull;

    u64 wreg[9];
#pragma unroll
    for (int tap = 0; tap < 9; tap++)
        wreg[tap] = __ldg(w1tu + tap * 16 + cp);

    for (int ci = 0; ci < 128; ci++) {
        u64 wnxt[9];
        if (ci < 127) {
#pragma unroll
            for (int tap = 0; tap < 9; tap++)
                wnxt[tap] = __ldg(w1tu + ((ci + 1) * 9 + tap) * 16 + cp);
        }
#pragma unroll
        for (int iy = 0; iy < 6; iy++) {
            float4 c = xs4[(ci * 6 + iy) * 16 + xg];
            float l = __shfl_up_sync(0xffffffffu, c.w, 1);
            float r = __shfl_down_sync(0xffffffffu, c.x, 1);
            if (xg == 0)  l = 0.f;
            if (xg == 15) r = 0.f;
            u64 p[6];
            p[0] = pk2(l);   p[1] = pk2(c.x); p[2] = pk2(c.y);
            p[3] = pk2(c.z); p[4] = pk2(c.w); p[5] = pk2(r);
#pragma unroll
            for (int ky = 0; ky < 3; ky++) {
                int rr = iy - ky;
                if (rr < 0 || rr > 3) continue;
#pragma unroll
                for (int kx = 0; kx < 3; kx++) {
                    u64 wv = wreg[ky * 3 + kx];
                    fma2(acc2[rr][0], p[kx    ], wv);
                    fma2(acc2[rr][1], p[kx + 1], wv);
                    fma2(acc2[rr][2], p[kx + 2], wv);
                    fma2(acc2[rr][3], p[kx + 3], wv);
                }
            }
        }
#pragma unroll
        for (int tap = 0; tap < 9; tap++) wreg[tap] = wnxt[tap];
    }

#pragma unroll
    for (int rr = 0; rr < 4; rr++)
#pragma unroll
        for (int p = 0; p < 4; p++) {
            float2 v = upk(acc2[rr][p]);
            h_s[((2 * cp)     * 4 + rr) * 64 + xg * 4 + p] = fmaxf(v.x, 0.f);
            h_s[((2 * cp + 1) * 4 + rr) * 64 + xg * 4 + p] = fmaxf(v.y, 0.f);
        }
    __syncthreads();

    float4* xout4 = (float4*)(xout + n * 128 * 4096);
#pragma unroll 2
    for (int k = 0; k < 32; k++) {
        int e   = k * 256 + t;
        int x4  = e & 15;
        int row = (e >> 4) & 3;
        int co  = e >> 6;
        int gi  = (co * 64 + oy0 + row) * 16 + x4;
        float4 s = xin4[gi];
        const float* wrow = w2g + co * 32;
#pragma unroll 8
        for (int ci = 0; ci < 32; ci++) {
            float wv = __ldg(wrow + ci);
            const float* hp = h_s + (ci * 4 + row) * 64 + x4 * 4;
            s.x += wv * hp[0]; s.y += wv * hp[1];
            s.z += wv * hp[2]; s.w += wv * hp[3];
        }
        xout4[gi] = s;
    }
}

// ---------------- fused decoder residual iteration (smem-resident stripe) -----
#define DSM_TOTAL 215040

__global__ void __launch_bounds__(256) decres_fused(
    const float* __restrict__ xin, const float* __restrict__ w1,
    const float* __restrict__ w2, float* __restrict__ xout)
{
    extern __shared__ unsigned char smraw[];
    float4* xs4   = (float4*)smraw;
    float*  sw1f  = (float*)(smraw + 196608);
    u64*    sw1u  = (u64*)  (smraw + 196608);
    float*  sw2   = (float*)(smraw + 205824);
    u64*    part  = (u64*)  (smraw + 206848);
    float*  h0    = (float*)(smraw + 212992);
    float*  h1    = (float*)(smraw + 214016);

    int t   = threadIdx.x;
    int by  = blockIdx.x;
    int n   = blockIdx.y;
    int oy0 = by * 4;

    for (int i = t; i < 2304; i += 256) {
        int ch = i & 1, r = i >> 1;
        sw1f[i] = w1[ch * 1152 + r];
    }
    if (t < 256) sw2[t] = w2[t];

    const float4* xin4 = (const float4*)(xin + n * 128 * 4096);
    for (int i = t; i < 12288; i += 256) {
        int x4 = i & 15;
        int rr = (i >> 4) % 6;
        int ci = i / 96;
        int gy = oy0 - 1 + rr;
        float4 v;
        if ((unsigned)gy < 64u) v = xin4[(ci * 64 + gy) * 16 + x4];
        else { v.x = v.y = v.z = v.w = 0.f; }
        xs4[i] = v;
    }
    __syncthreads();

    int g   = t >> 6;
    int t64 = t & 63;
    int row = t64 >> 4;
    int xg  = t64 & 15;

    u64 a[4] = {0ull, 0ull, 0ull, 0ull};
    for (int ci = g * 32; ci < g * 32 + 32; ci++) {
        const u64* wci = sw1u + ci * 9;
#pragma unroll
        for (int ky = 0; ky < 3; ky++) {
            float4 c = xs4[(ci * 6 + row + ky) * 16 + xg];
            float l = __shfl_up_sync(0xffffffffu, c.w, 1);
            float r = __shfl_down_sync(0xffffffffu, c.x, 1);
            if (xg == 0)  l = 0.f;
            if (xg == 15) r = 0.f;
            u64 pw[6];
            pw[0] = pk2(fmaxf(l,   0.f));
            pw[1] = pk2(fmaxf(c.x, 0.f));
            pw[2] = pk2(fmaxf(c.y, 0.f));
            pw[3] = pk2(fmaxf(c.z, 0.f));
            pw[4] = pk2(fmaxf(c.w, 0.f));
            pw[5] = pk2(fmaxf(r,   0.f));
#pragma unroll
            for (int kx = 0; kx < 3; kx++) {
                u64 wv = wci[ky * 3 + kx];
                fma2(a[0], pw[kx    ], wv);
                fma2(a[1], pw[kx + 1], wv);
                fma2(a[2], pw[kx + 2], wv);
                fma2(a[3], pw[kx + 3], wv);
            }
        }
    }
    if (g > 0) {
#pragma unroll
        for (int p = 0; p < 4; p++) part[(g - 1) * 256 + t64 * 4 + p] = a[p];
    }
    __syncthreads();
    if (t < 64) {
#pragma unroll
        for (int p = 0; p < 4; p++) {
            u64 s = a[p];
            s = add2(s, part[      t * 4 + p]);
            s = add2(s, part[256 + t * 4 + p]);
            s = add2(s, part[512 + t * 4 + p]);
            float2 v = upk(s);
            h0[row * 64 + xg * 4 + p] = fmaxf(v.x, 0.f);
            h1[row * 64 + xg * 4 + p] = fmaxf(v.y, 0.f);
        }
    }
    __syncthreads();

    float4* xout4 = (float4*)(xout + n * 128 * 4096);
#pragma unroll 4
    for (int k = 0; k < 32; k++) {
        int e   = k * 256 + t;
        int x4  = e & 15;
        int row2= (e >> 4) & 3;
        int co  = e >> 6;
        int gi = (co * 64 + oy0 + row2) * 16 + x4;
        float4 v = xs4[(co * 6 + row2 + 1) * 16 + x4];
        float w0 = sw2[co * 2], w1v = sw2[co * 2 + 1];
        const float* p0 = h0 + row2 * 64 + x4 * 4;
        const float* p1 = h1 + row2 * 64 + x4 * 4;
        v.x += w0 * p0[0] + w1v * p1[0];
        v.y += w0 * p0[1] + w1v * p1[1];
        v.z += w0 * p0[2] + w1v * p1[2];
        v.w += w0 * p0[3] + w1v * p1[3];
        xout4[gi] = v;
    }
}

// ---------------- vector quantizer -------------------------------------------
__global__ void __launch_bounds__(256) vq_kernel(
    const float* __restrict__ ze, const float* __restrict__ cb,
    float* __restrict__ zq, float* __restrict__ partials)
{
    __shared__ __align__(16) float f_s[64 * 64];
    __shared__ __align__(16) float cb_s[64 * 68];
    __shared__ float norm_s[512];
    __shared__ int   idx_s[64];
    __shared__ float red_s[64];

    int t = threadIdx.x;
    int b = blockIdx.x;
    int n = b >> 6, y = b & 63;

    for (int i = t; i < 4096; i += 256) {
        int d = i >> 6, x = i & 63;
        f_s[i] = ze[((n * 64 + d) * 64 + y) * 64 + x];
    }
    for (int c = t; c < 512; c += 256) {
        float s = 0.f;
        const float* cp = cb + c * 64;
#pragma unroll 8
        for (int d = 0; d < 64; d++) { float v = __ldg(cp + d); s = fmaf(v, v, s); }
        norm_s[c] = s;
    }
    __syncthreads();

    int cxT = t & 15, pyT = t >> 4;
    float best[4] = {3.4e38f, 3.4e38f, 3.4e38f, 3.4e38f};
    int   bidx[4] = {0, 0, 0, 0};

    for (int ch = 0; ch < 8; ch++) {
        __syncthreads();
        for (int i = t; i < 4096; i += 256) {
            int d = i & 63, c = i >> 6;
            cb_s[d * 68 + c] = __ldg(&cb[(ch * 64 + c) * 64 + d]);
        }
        __syncthreads();

        float dot[4][4];
#pragma unroll
        for (int pp = 0; pp < 4; pp++)
#pragma unroll
            for (int cc = 0; cc < 4; cc++) dot[pp][cc] = 0.f;

        for (int d = 0; d < 64; d++) {
            float4 fv4 = *(const float4*)&f_s[d * 64 + pyT * 4];
            float4 cv4 = *(const float4*)&cb_s[d * 68 + cxT * 4];
            float fv[4] = {fv4.x, fv4.y, fv4.z, fv4.w};
            float cv[4] = {cv4.x, cv4.y, cv4.z, cv4.w};
#pragma unroll
            for (int pp = 0; pp < 4; pp++)
#pragma unroll
                for (int cc = 0; cc < 4; cc++)
                    dot[pp][cc] = fmaf(fv[pp], cv[cc], dot[pp][cc]);
        }
#pragma unroll
        for (int cc = 0; cc < 4; cc++) {
            int code = ch * 64 + cxT * 4 + cc;
            float nrm = norm_s[code];
#pragma unroll
            for (int pp = 0; pp < 4; pp++) {
                float dist = fmaf(-2.f, dot[pp][cc], nrm);
                if (dist < best[pp]) { best[pp] = dist; bidx[pp] = code; }
            }
        }
    }

    for (int off = 1; off < 16; off <<= 1) {
#pragma unroll
        for (int pp = 0; pp < 4; pp++) {
            float ob = __shfl_xor_sync(0xffffffffu, best[pp], off);
            int   oi = __shfl_xor_sync(0xffffffffu, bidx[pp], off);
            if (ob < best[pp] || (ob == best[pp] && oi < bidx[pp])) {
                best[pp] = ob; bidx[pp] = oi;
            }
        }
    }
    if (cxT == 0)
#pragma unroll
        for (int pp = 0; pp < 4; pp++) idx_s[pyT * 4 + pp] = bidx[pp];
    __syncthreads();

    for (int i = t; i < 4096; i += 256) {
        int d = i >> 6, x = i & 63;
        zq[((n * 64 + d) * 64 + y) * 64 + x] = __ldg(&cb[idx_s[x] * 64 + d]);
    }

    if (t < 64) {
        int id = idx_s[t];
        const float* cp = cb + id * 64;
        float s = 0.f;
#pragma unroll 8
        for (int d = 0; d < 64; d++) {
            float diff = __ldg(cp + d) - f_s[d * 64 + t];
            s = fmaf(diff, diff, s);
        }
        red_s[t] = s;
    }
    __syncthreads();
    if (t == 0) {
        float s = 0.f;
        for (int i = 0; i < 64; i++) s += red_s[i];
        partials[b] = s;
    }
}

__global__ void __launch_bounds__(256) finalize_loss(
    const float* __restrict__ partials, float* __restrict__ dst)
{
    __shared__ float s[256];
    int t = threadIdx.x;
    float v = 0.f;
    for (int i = t; i < 1024; i += 256) v += partials[i];
    s[t] = v;
    __syncthreads();
    for (int off = 128; off > 0; off >>= 1) {
        if (t < off) s[t] += s[t + off];
        __syncthreads();
    }
    if (t == 0) dst[0] = 1.25f * s[0] / 4194304.f;  // (1 + BETA) * MSE
}

// ---------------- host launcher ----------------------------------------------
extern "C" void kernel_launch(void* const* d_in, const int* in_sizes, int n_in,
                              void* d_out, int out_size)
{
    (void)in_sizes; (void)n_in; (void)out_size;
    const float* x       = (const float*)d_in[0];
    const float* enc_w1  = (const float*)d_in[1];
    const float* enc_b1  = (const float*)d_in[2];
    const float* enc_w2  = (const float*)d_in[3];
    const float* enc_b2  = (const float*)d_in[4];
    const float* enc_w3  = (const float*)d_in[5];
    const float* enc_b3  = (const float*)d_in[6];
    const float* enc_rw1 = (const float*)d_in[7];
    const float* enc_rw2 = (const float*)d_in[8];
    const float* pre_w   = (const float*)d_in[9];
    const float* pre_b   = (const float*)d_in[10];
    const float* cb      = (const float*)d_in[11];
    const float* dec_wt1 = (const float*)d_in[12];
    const float* dec_bt1 = (const float*)d_in[13];
    const float* dec_rw1 = (const float*)d_in[14];
    const float* dec_rw2 = (const float*)d_in[15];
    const float* dec_wt2 = (const float*)d_in[16];
    const float* dec_bt2 = (const float*)d_in[17];
    const float* dec_wt3 = (const float*)d_in[18];
    const float* dec_bt3 = (const float*)d_in[19];
    float* out = (float*)d_out;

    float *pA, *pB, *pB2, *pC, *pE, *pF, *pW1T, *pPart;
    cudaGetSymbolAddress((void**)&pA,  g_A);
    cudaGetSymbolAddress((void**)&pB,  g_B);
    cudaGetSymbolAddress((void**)&pB2, g_B2);
    cudaGetSymbolAddress((void**)&pC,  g_C);
    cudaGetSymbolAddress((void**)&pE,  g_E);
    cudaGetSymbolAddress((void**)&pF,  g_F);
    cudaGetSymbolAddress((void**)&pW1T, g_W1T);
    cudaGetSymbolAddress((void**)&pPart, g_part);

    cudaFuncSetAttribute(decres_fused,
                         cudaFuncAttributeMaxDynamicSharedMemorySize, DSM_TOTAL);
    cudaFuncSetAttribute(encres_fused,
                         cudaFuncAttributeMaxDynamicSharedMemorySize, ESM_TOTAL);

    // encoder
    conv_fwd<4,2,false,false,4><<<dim3(2,16,16*8), 128>>>(
        x, enc_w1, enc_b1, nullptr, pA, 3, 64, 256, 256, 128, 128, 1, 8, 1);
    conv_fwd<4,2,false,false,4><<<dim3(1,8,16*16), 128>>>(
        pA, enc_w2, enc_b2, nullptr, pB, 64, 128, 128, 128, 64, 64, 1, 16, 1);
    // enc3: row-tiled 3x3
    conv3_rt<false,false><<<dim3(1,2,16*32), 128>>>(
        pB, enc_w3, enc_b3, pC, 128, 128, 0);

    // fused encoder res stack (2 shared-weight iterations), ping-pong pC<->pB
    transpose_w1<<<144, 256>>>(enc_rw1, pW1T);
    encres_fused<<<dim3(16,16), 256, ESM_TOTAL>>>(pC, pW1T, enc_rw2, pB);
    encres_fused<<<dim3(16,16), 256, ESM_TOTAL>>>(pB, pW1T, enc_rw2, pC);

    conv_fwd<1,1,true,false,4><<<dim3(1,8,16*8), 128>>>(
        pC, pre_w, pre_b, nullptr, pE, 128, 64, 64, 64, 64, 64, 0, 8, 0);

    // quantizer
    vq_kernel<<<1024, 256>>>(pE, cb, pF, pPart);
    finalize_loss<<<1, 256>>>(pPart, out + 3145728);

    // decoder: dec_t1 row-tiled (stride-1 transposed 3x3 == flipped conv)
    conv3_rt<false,true><<<dim3(1,2,16*32), 128>>>(
        pF, dec_wt1, dec_bt1, pB, 64, 128, 0);
    for (int i = 0; i < 32; i++) {
        const float* src = (i & 1) ? pB2 : pB;
        float*       dst = (i & 1) ? pB  : pB2;
        decres_fused<<<dim3(16,16), 256, DSM_TOTAL>>>(src, dec_rw1, dec_rw2, dst);
    }
    // after 32 iters result is back in pB
    convt_s2<4><<<dim3(2,16,16*8), 128>>>(
        pB, dec_wt2, dec_bt2, pA, 128, 64, 64, 64, 8, 1, 1);
    convt_s2<2><<<dim3(4,32,16*1), 128>>>(
        pA, dec_wt3, dec_bt3, out, 64, 3, 128, 128, 1, 0, 0);
}

// round 14
// speedup vs baseline: 1.5181x; 1.0221x over previous
#include <cuda_runtime.h>
#include <math.h>

typedef unsigned long long u64;

__device__ __forceinline__ u64 pk2(float v) {
    u64 r; asm("mov.b64 %0, {%1,%1};" : "=l"(r) : "f"(v)); return r;
}
__device__ __forceinline__ void fma2(u64& d, u64 a, u64 b) {
    asm("fma.rn.f32x2 %0, %1, %2, %0;" : "+l"(d) : "l"(a), "l"(b));
}
__device__ __forceinline__ float2 upk(u64 v) {
    float2 r; asm("mov.b64 {%0,%1}, %2;" : "=f"(r.x), "=f"(r.y) : "l"(v)); return r;
}
__device__ __forceinline__ u64 add2(u64 a, u64 b) {
    u64 r; asm("add.rn.f32x2 %0, %1, %2;" : "=l"(r) : "l"(a), "l"(b)); return r;
}

// ---------------- scratch (device globals: allocation-free) ------------------
__device__ float g_A [16*64*128*128];   // 67 MB
__device__ float g_B [16*128*64*64];    // 33.5 MB
__device__ float g_B2[16*128*64*64];    // 33.5 MB
__device__ float g_C [16*128*64*64];    // 33.5 MB
__device__ float g_E [16*64*64*64];     // 16.8 MB (z_e)
__device__ float g_F [16*64*64*64];     // 16.8 MB (z_q)
__device__ __align__(16) float g_W1T[128*9*32];  // transposed enc_rw1
__device__ float g_part[1024];

// ---------------- enc2: K=4 S=2 conv, CIN=64 COUT=128, in 128^2 out 64^2 ------
// thread: 8 out-px x 8 couts. block 128 = 8 xg x 16 rows. grid (1,4,256).
__global__ void __launch_bounds__(128) conv4s2_px8(
    const float* __restrict__ in, const float* __restrict__ w,
    const float* __restrict__ bias, float* __restrict__ out)
{
    __shared__ __align__(16) float sw[64 * 16 * 8];   // [(ci*16+kk)*8 + c]
    int t  = threadIdx.x;
    int tx = t & 7, ty = t >> 3;
    int ox0 = tx * 8;
    int oy  = blockIdx.y * 16 + ty;
    int n   = blockIdx.z >> 4;
    int co0 = (blockIdx.z & 15) * 8;
    int a0  = 2 * ox0;

    for (int i = t; i < 8192; i += 128) {
        int c  = i & 7;
        int r  = i >> 3;
        int ci = r >> 4;
        int kk = r & 15;
        sw[i] = w[((co0 + c) * 64 + ci) * 16 + kk];
    }
    __syncthreads();

    u64 acc[4][8];
#pragma unroll
    for (int cp = 0; cp < 4; cp++)
#pragma unroll
        for (int p = 0; p < 8; p++) acc[cp][p] = 0ull;

    const float* inb = in + n * 64 * 16384;
    for (int ci = 0; ci < 64; ci++) {
        const float* inc = inb + ci * 16384;
        const float* wci = sw + ci * 128;
#pragma unroll
        for (int ky = 0; ky < 4; ky++) {
            int iy = oy * 2 - 1 + ky;
            bool vy = (unsigned)iy < 128u;
            const float* rowp = inc + (vy ? iy : 0) * 128;
            float4 f0 = make_float4(0.f,0.f,0.f,0.f), f1 = f0, f2 = f0, f3 = f0;
            if (vy) {
                f0 = *(const float4*)(rowp + a0);
                f1 = *(const float4*)(rowp + a0 + 4);
                f2 = *(const float4*)(rowp + a0 + 8);
                f3 = *(const float4*)(rowp + a0 + 12);
            }
            float l = __shfl_up_sync(0xffffffffu, f3.w, 1);
            float r = __shfl_down_sync(0xffffffffu, f0.x, 1);
            if (tx == 0) l = 0.f;                 // a0-1 < 0
            if (tx == 7) r = 0.f;                 // a0+16 >= 128
            u64 ivs[18];
            ivs[0]  = pk2(l);
            ivs[1]  = pk2(f0.x); ivs[2]  = pk2(f0.y); ivs[3]  = pk2(f0.z); ivs[4]  = pk2(f0.w);
            ivs[5]  = pk2(f1.x); ivs[6]  = pk2(f1.y); ivs[7]  = pk2(f1.z); ivs[8]  = pk2(f1.w);
            ivs[9]  = pk2(f2.x); ivs[10] = pk2(f2.y); ivs[11] = pk2(f2.z); ivs[12] = pk2(f2.w);
            ivs[13] = pk2(f3.x); ivs[14] = pk2(f3.y); ivs[15] = pk2(f3.z); ivs[16] = pk2(f3.w);
            ivs[17] = pk2(r);
#pragma unroll
            for (int kx = 0; kx < 4; kx++) {
                const float* wp = wci + (ky * 4 + kx) * 8;
                ulonglong2 wa = *(const ulonglong2*)(wp);
                ulonglong2 wb = *(const ulonglong2*)(wp + 4);
                u64 wv[4] = {wa.x, wa.y, wb.x, wb.y};
#pragma unroll
                for (int cp = 0; cp < 4; cp++)
#pragma unroll
                    for (int p = 0; p < 8; p++)
                        fma2(acc[cp][p], ivs[2 * p + kx], wv[cp]);
            }
        }
    }

#pragma unroll
    for (int cp = 0; cp < 4; cp++)
#pragma unroll
        for (int h2 = 0; h2 < 2; h2++) {
            int co = co0 + cp * 2 + h2;
            float b = __ldg(bias + co);
            float* op = out + ((n * 128 + co) * 64 + oy) * 64 + ox0;
#pragma unroll
            for (int p = 0; p < 8; p++) {
                float2 v = upk(acc[cp][p]);
                op[p] = fmaxf((h2 ? v.y : v.x) + b, 0.f);
            }
        }
}

// ---------------- dec_t2: transposed conv s2 K4, CIN=128 COUT=64, out 128^2 ---
// thread: 8 out-px (one parity) x 8 couts. block 128 = 8 xg x 16 rows.
// grid (2, 8, 128). relu_in + relu_out hardcoded.
__global__ void __launch_bounds__(128) convt8_dec(
    const float* __restrict__ in, const float* __restrict__ w,
    const float* __restrict__ bias, float* __restrict__ out)
{
    __shared__ __align__(16) float sw[64 * 16 * 8];
    int t  = threadIdx.x;
    int tx = t & 7, tyv = t >> 3;
    int parity = blockIdx.x;
    int ox0 = 16 * tx + parity;
    int oy  = blockIdx.y * 16 + tyv;
    int n   = blockIdx.z >> 3;
    int co0 = (blockIdx.z & 7) * 8;
    int kyp = (oy + 1) & 1;
    int kxp = 1 - parity;
    int a0  = 8 * tx;

    u64 acc[4][8];
#pragma unroll
    for (int cp = 0; cp < 4; cp++)
#pragma unroll
        for (int p = 0; p < 8; p++) acc[cp][p] = 0ull;

    for (int ci0 = 0; ci0 < 128; ci0 += 64) {
        __syncthreads();
        for (int i = t; i < 8192; i += 128) {
            int c  = i & 7;
            int r  = i >> 3;
            int ci = r >> 4;
            int kk = r & 15;
            sw[i] = w[((ci0 + ci) * 64 + co0 + c) * 16 + kk];
        }
        __syncthreads();

        for (int ci = 0; ci < 64; ci++) {
            const float* inc = in + (n * 128 + ci0 + ci) * 4096;
            const float* wci = sw + ci * 128;
#pragma unroll
            for (int ky2 = 0; ky2 < 2; ky2++) {
                int ky = kyp + 2 * ky2;
                int iy = (oy + 1 - ky) >> 1;
                bool vy = (unsigned)iy < 64u;
                const float* rowp = inc + (vy ? iy : 0) * 64;
                float4 f0 = make_float4(0.f,0.f,0.f,0.f), f1 = f0;
                if (vy) {
                    f0 = *(const float4*)(rowp + a0);
                    f1 = *(const float4*)(rowp + a0 + 4);
                }
                u64 ivs[9];
                if (parity == 0) {
                    float l = __shfl_up_sync(0xffffffffu, f1.w, 1);
                    if (tx == 0) l = 0.f;
                    ivs[0] = pk2(fmaxf(l, 0.f));
                    ivs[1] = pk2(fmaxf(f0.x, 0.f)); ivs[2] = pk2(fmaxf(f0.y, 0.f));
                    ivs[3] = pk2(fmaxf(f0.z, 0.f)); ivs[4] = pk2(fmaxf(f0.w, 0.f));
                    ivs[5] = pk2(fmaxf(f1.x, 0.f)); ivs[6] = pk2(fmaxf(f1.y, 0.f));
                    ivs[7] = pk2(fmaxf(f1.z, 0.f)); ivs[8] = pk2(fmaxf(f1.w, 0.f));
                } else {
                    float r = __shfl_down_sync(0xffffffffu, f0.x, 1);
                    if (tx == 7) r = 0.f;
                    ivs[0] = pk2(fmaxf(f0.x, 0.f)); ivs[1] = pk2(fmaxf(f0.y, 0.f));
                    ivs[2] = pk2(fmaxf(f0.z, 0.f)); ivs[3] = pk2(fmaxf(f0.w, 0.f));
                    ivs[4] = pk2(fmaxf(f1.x, 0.f)); ivs[5] = pk2(fmaxf(f1.y, 0.f));
                    ivs[6] = pk2(fmaxf(f1.z, 0.f)); ivs[7] = pk2(fmaxf(f1.w, 0.f));
                    ivs[8] = pk2(fmaxf(r, 0.f));
                }
#pragma unroll
                for (int kx2 = 0; kx2 < 2; kx2++) {
                    int kx  = kxp + 2 * kx2;
                    int ofs = 1 - kx2;
                    const float* wp = wci + (ky * 4 + kx) * 8;
                    ulonglong2 wa = *(const ulonglong2*)(wp);
                    ulonglong2 wb = *(const ulonglong2*)(wp + 4);
                    u64 wv[4] = {wa.x, wa.y, wb.x, wb.y};
#pragma unroll
                    for (int cp = 0; cp < 4; cp++)
#pragma unroll
                        for (int p = 0; p < 8; p++)
                            fma2(acc[cp][p], ivs[ofs + p], wv[cp]);
                }
            }
        }
    }

#pragma unroll
    for (int cp = 0; cp < 4; cp++)
#pragma unroll
        for (int h2 = 0; h2 < 2; h2++) {
            int co = co0 + cp * 2 + h2;
            float b = __ldg(bias + co);
            float* op = out + ((n * 64 + co) * 128 + oy) * 128;
#pragma unroll
            for (int p = 0; p < 8; p++) {
                float2 v = upk(acc[cp][p]);
                op[ox0 + 2 * p] = fmaxf((h2 ? v.y : v.x) + b, 0.f);
            }
        }
}

// ---------------- generic direct conv (f32x2, float4+shuffle, 4 px) -----------
template<int K, int STRIDE, bool RELU_IN, bool TRANSPOSED, int CP>
__global__ void __launch_bounds__(128) conv_fwd(
    const float* __restrict__ in, const float* __restrict__ w,
    const float* __restrict__ bias, const float* __restrict__ resid,
    float* __restrict__ out,
    int CIN, int COUT, int H, int W, int OH, int OW, int PAD, int cgroups,
    int relu_out)
{
    constexpr int KK = K * K;
    constexpr int CICH = (K == 4) ? 64 : 128;
    constexpr int SPAN = 3 * STRIDE + K;
    constexpr int NC   = 2 * CP;
    __shared__ __align__(16) float sw[CICH * KK * NC];

    int t   = threadIdx.x;
    int tx  = t & 15, ty = t >> 4;
    int ox0 = blockIdx.x * 64 + tx * 4;
    int oy  = blockIdx.y * 8 + ty;
    int n   = blockIdx.z / cgroups;
    int co0 = (blockIdx.z % cgroups) * NC;

    u64 acc2[CP][4];
#pragma unroll
    for (int cp = 0; cp < CP; cp++)
#pragma unroll
        for (int p = 0; p < 4; p++) acc2[cp][p] = 0ull;

    for (int ci0 = 0; ci0 < CIN; ci0 += CICH) {
        int cich = min(CICH, CIN - ci0);
        int nw = cich * KK * NC;
        __syncthreads();
        for (int i = t; i < nw; i += 128) {
            int c  = i & (NC - 1);
            int r  = i / NC;
            int ci = r / KK;
            int kk = r - ci * KK;
            int ky = kk / K, kx = kk - ky * K;
            int co = co0 + c;
            float v = 0.f;
            if (co < COUT) {
                if (TRANSPOSED)
                    v = w[(((ci0 + ci) * COUT + co) * K + (K - 1 - ky)) * K + (K - 1 - kx)];
                else
                    v = w[((co * CIN + (ci0 + ci)) * K + ky) * K + kx];
            }
            sw[i] = v;
        }
        __syncthreads();

        const float* inb = in + (n * CIN + ci0) * H * W;
        for (int ci = 0; ci < cich; ci++) {
            const float* inc = inb + ci * H * W;
            const float* wci = sw + ci * KK * NC;
#pragma unroll
            for (int ky = 0; ky < K; ky++) {
                int iy = oy * STRIDE - PAD + ky;
                bool vy = (unsigned)iy < (unsigned)H;
                const float* rowp = inc + (vy ? iy : 0) * W;
                u64 ivs[SPAN];

                if constexpr (STRIDE == 1 && K == 3) {
                    float4 c = make_float4(0.f, 0.f, 0.f, 0.f);
                    if (vy) c = *(const float4*)(rowp + ox0);
                    float l = __shfl_up_sync(0xffffffffu, c.w, 1);
                    float r = __shfl_down_sync(0xffffffffu, c.x, 1);
                    if (tx == 0)  l = (vy && ox0 > 0)       ? __ldg(rowp + ox0 - 1) : 0.f;
                    if (tx == 15) r = (vy && ox0 + 4 < W)   ? __ldg(rowp + ox0 + 4) : 0.f;
                    float vv[6] = {l, c.x, c.y, c.z, c.w, r};
#pragma unroll
                    for (int q = 0; q < 6; q++) {
                        float v = vv[q];
                        if (RELU_IN) v = fmaxf(v, 0.f);
                        ivs[q] = pk2(v);
                    }
                } else if constexpr (K == 1) {
                    float4 c = make_float4(0.f, 0.f, 0.f, 0.f);
                    if (vy) c = *(const float4*)(rowp + ox0);
                    float vv[4] = {c.x, c.y, c.z, c.w};
#pragma unroll
                    for (int q = 0; q < 4; q++) {
                        float v = vv[q];
                        if (RELU_IN) v = fmaxf(v, 0.f);
                        ivs[q] = pk2(v);
                    }
                } else {  // K == 4, STRIDE == 2
                    int a0 = 2 * ox0;
                    float4 f0 = make_float4(0.f, 0.f, 0.f, 0.f);
                    float4 f1 = make_float4(0.f, 0.f, 0.f, 0.f);
                    if (vy) {
                        f0 = *(const float4*)(rowp + a0);
                        f1 = *(const float4*)(rowp + a0 + 4);
                    }
                    float l = __shfl_up_sync(0xffffffffu, f1.w, 1);
                    float r = __shfl_down_sync(0xffffffffu, f0.x, 1);
                    if (tx == 0)  l = (vy && a0 > 0)      ? __ldg(rowp + a0 - 1) : 0.f;
                    if (tx == 15) r = (vy && a0 + 8 < W)  ? __ldg(rowp + a0 + 8) : 0.f;
                    float vv[10] = {l, f0.x, f0.y, f0.z, f0.w, f1.x, f1.y, f1.z, f1.w, r};
#pragma unroll
                    for (int q = 0; q < 10; q++) {
                        float v = vv[q];
                        if (RELU_IN) v = fmaxf(v, 0.f);
                        ivs[q] = pk2(v);
                    }
                }

#pragma unroll
                for (int kx = 0; kx < K; kx++) {
                    const float* wp = wci + (ky * K + kx) * NC;
                    u64 wv[CP];
#pragma unroll
                    for (int q = 0; q < CP / 2; q++) {
                        ulonglong2 ww = *(const ulonglong2*)(wp + q * 4);
                        wv[2 * q] = ww.x; wv[2 * q + 1] = ww.y;
                    }
                    if (CP & 1) wv[CP - 1] = *(const u64*)(wp + (CP - 1) * 2);
#pragma unroll
                    for (int cp = 0; cp < CP; cp++)
#pragma unroll
                        for (int p = 0; p < 4; p++)
                            fma2(acc2[cp][p], ivs[p * STRIDE + kx], wv[cp]);
                }
            }
        }
    }

#pragma unroll
    for (int cp = 0; cp < CP; cp++) {
        float2 v[4];
#pragma unroll
        for (int p = 0; p < 4; p++) v[p] = upk(acc2[cp][p]);
#pragma unroll
        for (int h2 = 0; h2 < 2; h2++) {
            int co = co0 + cp * 2 + h2;
            if (co >= COUT) continue;
            float b = bias ? __ldg(bias + co) : 0.f;
            int ob = ((n * COUT + co) * OH + oy) * OW + ox0;
#pragma unroll
            for (int p = 0; p < 4; p++) {
                float val = (h2 ? v[p].y : v[p].x) + b;
                if (resid) val += resid[ob + p];
                if (relu_out) val = fmaxf(val, 0.f);
                out[ob + p] = val;
            }
        }
    }
}

// ---------------- row-tiled 3x3 stride-1 conv, 64x64, COUT=128 ----------------
template<bool RELU_IN, bool TRANSPOSED>
__global__ void __launch_bounds__(128) conv3_rt(
    const float* __restrict__ in, const float* __restrict__ w,
    const float* __restrict__ bias, float* __restrict__ out,
    int CIN, int COUT, int relu_out)
{
    __shared__ __align__(16) float sw[128 * 9 * 4];

    int t   = threadIdx.x;
    int tx  = t & 15, ty = t >> 4;
    int ox0 = tx * 4;
    int oy0 = blockIdx.y * 32 + ty * 4;
    int n   = blockIdx.z >> 5;
    int co0 = (blockIdx.z & 31) * 4;

    int nw = CIN * 36;
    for (int i = t; i < nw; i += 128) {
        int c  = i & 3;
        int r  = i >> 2;
        int ci = r / 9;
        int kk = r - ci * 9;
        int ky = kk / 3, kx = kk - ky * 3;
        int co = co0 + c;
        float v;
        if (TRANSPOSED)
            v = w[((ci * COUT + co) * 3 + (2 - ky)) * 3 + (2 - kx)];
        else
            v = w[((co * CIN + ci) * 3 + ky) * 3 + kx];
        sw[i] = v;
    }
    __syncthreads();

    u64 acc[2][4][4];
#pragma unroll
    for (int cp = 0; cp < 2; cp++)
#pragma unroll
        for (int rr = 0; rr < 4; rr++)
#pragma unroll
            for (int p = 0; p < 4; p++) acc[cp][rr][p] = 0ull;

    const float* inb = in + n * CIN * 4096;
    for (int ci = 0; ci < CIN; ci++) {
        const float* inc = inb + ci * 4096;
        const float* wci = sw + ci * 36;
        u64 wv[9][2];
#pragma unroll
        for (int tap = 0; tap < 9; tap++) {
            ulonglong2 ww = *(const ulonglong2*)(wci + tap * 4);
            wv[tap][0] = ww.x; wv[tap][1] = ww.y;
        }
#pragma unroll
        for (int iy6 = 0; iy6 < 6; iy6++) {
            int iy = oy0 - 1 + iy6;
            bool vy = (unsigned)iy < 64u;
            float4 c = make_float4(0.f, 0.f, 0.f, 0.f);
            if (vy) c = *(const float4*)(inc + iy * 64 + ox0);
            float l = __shfl_up_sync(0xffffffffu, c.w, 1);
            float r = __shfl_down_sync(0xffffffffu, c.x, 1);
            if (tx == 0)  l = 0.f;
            if (tx == 15) r = 0.f;
            if (RELU_IN) {
                l = fmaxf(l, 0.f);     r = fmaxf(r, 0.f);
                c.x = fmaxf(c.x, 0.f); c.y = fmaxf(c.y, 0.f);
                c.z = fmaxf(c.z, 0.f); c.w = fmaxf(c.w, 0.f);
            }
            u64 p[6];
            p[0] = pk2(l);   p[1] = pk2(c.x); p[2] = pk2(c.y);
            p[3] = pk2(c.z); p[4] = pk2(c.w); p[5] = pk2(r);
#pragma unroll
            for (int ky = 0; ky < 3; ky++) {
                int rr = iy6 - ky;
                if (rr < 0 || rr > 3) continue;
#pragma unroll
                for (int kx = 0; kx < 3; kx++) {
                    u64 w0 = wv[ky * 3 + kx][0];
                    u64 w1 = wv[ky * 3 + kx][1];
#pragma unroll
                    for (int q = 0; q < 4; q++) {
                        fma2(acc[0][rr][q], p[kx + q], w0);
                        fma2(acc[1][rr][q], p[kx + q], w1);
                    }
                }
            }
        }
    }

#pragma unroll
    for (int cp = 0; cp < 2; cp++)
#pragma unroll
        for (int h2 = 0; h2 < 2; h2++) {
            int co = co0 + cp * 2 + h2;
            float b = bias ? __ldg(bias + co) : 0.f;
#pragma unroll
            for (int rr = 0; rr < 4; rr++) {
                float4 o;
                float2 v0 = upk(acc[cp][rr][0]);
                float2 v1 = upk(acc[cp][rr][1]);
                float2 v2 = upk(acc[cp][rr][2]);
                float2 v3 = upk(acc[cp][rr][3]);
                o.x = (h2 ? v0.y : v0.x) + b;
                o.y = (h2 ? v1.y : v1.x) + b;
                o.z = (h2 ? v2.y : v2.x) + b;
                o.w = (h2 ? v3.y : v3.x) + b;
                if (relu_out) {
                    o.x = fmaxf(o.x, 0.f); o.y = fmaxf(o.y, 0.f);
                    o.z = fmaxf(o.z, 0.f); o.w = fmaxf(o.w, 0.f);
                }
                *(float4*)(out + ((n * COUT + co) * 64 + oy0 + rr) * 64 + ox0) = o;
            }
        }
}

// ---------------- transposed conv s2 K4, 4-px (dec_t3 only) -------------------
template<int CP>
__global__ void __launch_bounds__(128) convt_s2(
    const float* __restrict__ in, const float* __restrict__ w,
    const float* __restrict__ bias, float* __restrict__ out,
    int CIN, int COUT, int H, int W, int cgroups, int relu_in, int relu_out)
{
    constexpr int NC = 2 * CP;
    __shared__ __align__(16) float sw[64 * 16 * NC];
    int t = threadIdx.x;
    int tx = t & 15, tyv = t >> 4;
    int parity = blockIdx.x & 1;
    int xch    = blockIdx.x >> 1;
    int OH = 2 * H, OW = 2 * W;
    int ox0 = xch * 128 + 8 * tx + parity;
    int oy  = blockIdx.y * 8 + tyv;
    int n   = blockIdx.z / cgroups;
    int co0 = (blockIdx.z % cgroups) * NC;

    int kyp = (oy + 1) & 1;
    int kxp = (ox0 + 1) & 1;
    int a0  = (ox0 - parity) >> 1;

    u64 acc2[CP][4];
#pragma unroll
    for (int cp = 0; cp < CP; cp++)
#pragma unroll
        for (int p = 0; p < 4; p++) acc2[cp][p] = 0ull;

    for (int ci0 = 0; ci0 < CIN; ci0 += 64) {
        int cich = min(64, CIN - ci0);
        int nw = cich * 16 * NC;
        __syncthreads();
        for (int i = t; i < nw; i += 128) {
            int c  = i & (NC - 1);
            int r  = i / NC;
            int ci = r >> 4;
            int kk = r & 15;
            int co = co0 + c;
            sw[i] = (co < COUT) ? w[((ci0 + ci) * COUT + co) * 16 + kk] : 0.f;
        }
        __syncthreads();

        for (int ci = 0; ci < cich; ci++) {
            const float* inc = in + (n * CIN + ci0 + ci) * H * W;
            const float* wci = sw + ci * 16 * NC;
#pragma unroll
            for (int ky2 = 0; ky2 < 2; ky2++) {
                int ky = kyp + 2 * ky2;
                int iy = (oy + 1 - ky) >> 1;
                bool vy = (unsigned)iy < (unsigned)H;
                const float* rowp = inc + (vy ? iy : 0) * W;
                float4 c = make_float4(0.f, 0.f, 0.f, 0.f);
                if (vy) c = *(const float4*)(rowp + a0);
                u64 ivs[5];
                if (parity == 0) {
                    float l = __shfl_up_sync(0xffffffffu, c.w, 1);
                    if (tx == 0) l = (vy && a0 > 0) ? __ldg(rowp + a0 - 1) : 0.f;
                    float vv[5] = {l, c.x, c.y, c.z, c.w};
#pragma unroll
                    for (int q = 0; q < 5; q++) {
                        float v = vv[q];
                        if (relu_in) v = fmaxf(v, 0.f);
                        ivs[q] = pk2(v);
                    }
                } else {
                    float r = __shfl_down_sync(0xffffffffu, c.x, 1);
                    if (tx == 15) r = (vy && a0 + 4 < W) ? __ldg(rowp + a0 + 4) : 0.f;
                    float vv[5] = {c.x, c.y, c.z, c.w, r};
#pragma unroll
                    for (int q = 0; q < 5; q++) {
                        float v = vv[q];
                        if (relu_in) v = fmaxf(v, 0.f);
                        ivs[q] = pk2(v);
                    }
                }
#pragma unroll
                for (int kx2 = 0; kx2 < 2; kx2++) {
                    int kx  = kxp + 2 * kx2;
                    int ofs = 1 - kx2;
                    const float* wp = wci + (ky * 4 + kx) * NC;
                    u64 wv[CP];
#pragma unroll
                    for (int q = 0; q < CP / 2; q++) {
                        ulonglong2 ww = *(const ulonglong2*)(wp + q * 4);
                        wv[2 * q] = ww.x; wv[2 * q + 1] = ww.y;
                    }
                    if (CP & 1) wv[CP - 1] = *(const u64*)(wp + (CP - 1) * 2);
#pragma unroll
                    for (int cp = 0; cp < CP; cp++)
#pragma unroll
                        for (int p = 0; p < 4; p++)
                            fma2(acc2[cp][p], ivs[ofs + p], wv[cp]);
                }
            }
        }
    }

#pragma unroll
    for (int cp = 0; cp < CP; cp++) {
        float2 v[4];
#pragma unroll
        for (int p = 0; p < 4; p++) v[p] = upk(acc2[cp][p]);
#pragma unroll
        for (int h2 = 0; h2 < 2; h2++) {
            int co = co0 + cp * 2 + h2;
            if (co >= COUT) continue;
            float b = bias ? __ldg(bias + co) : 0.f;
#pragma unroll
            for (int p = 0; p < 4; p++) {
                int ox = ox0 + 2 * p;
                int o = ((n * COUT + co) * OH + oy) * OW + ox;
                float val = (h2 ? v[p].y : v[p].x) + b;
                if (relu_out) val = fmaxf(val, 0.f);
                out[o] = val;
            }
        }
    }
}

// ---------------- W1 transpose for fused encoder res block --------------------
__global__ void __launch_bounds__(256) transpose_w1(
    const float* __restrict__ w1, float* __restrict__ w1t)
{
    int i = blockIdx.x * 256 + threadIdx.x;
    if (i < 36864) {
        int co = i & 31;
        int r  = i >> 5;
        w1t[i] = w1[co * 1152 + r];
    }
}

// ---------------- fused ENCODER residual iteration (smem-resident stripe) -----
// FUSE_PRE: additionally computes z_e = pre_w * relu(x_out) + pre_b, skipping
// the x_out gmem write (x_out is only consumed by the 1x1 pre conv).
#define ESM_TOTAL 229376

template<bool FUSE_PRE>
__global__ void __launch_bounds__(256) encres_fused(
    const float* __restrict__ xin, const float* __restrict__ w1t,
    const float* __restrict__ w2g, float* __restrict__ xout,
    const float* __restrict__ pre_w, const float* __restrict__ pre_b,
    float* __restrict__ ze)
{
    extern __shared__ unsigned char smraw[];
    float4* xs4 = (float4*)smraw;             // phase1: [128][6][16] relu'd
    float*  h_s = (float*)(smraw + 196608);   // [32][4][64]
    float4* s4  = (float4*)smraw;             // phase2(FUSE): [128][4][16] relu(s)
    u64*    wp2 = (u64*)(smraw + 131072);     // [ci][64] pk2(pre_w)

    int t   = threadIdx.x;
    int by  = blockIdx.x;
    int n   = blockIdx.y;
    int oy0 = by * 4;

    const float4* xin4 = (const float4*)(xin + n * 128 * 4096);

    for (int i = t; i < 12288; i += 256) {
        int x4 = i & 15;
        int rr = (i >> 4) % 6;
        int ci = i / 96;
        int gy = oy0 - 1 + rr;
        float4 v = make_float4(0.f, 0.f, 0.f, 0.f);
        if ((unsigned)gy < 64u) v = xin4[(ci * 64 + gy) * 16 + x4];
        v.x = fmaxf(v.x, 0.f); v.y = fmaxf(v.y, 0.f);
        v.z = fmaxf(v.z, 0.f); v.w = fmaxf(v.w, 0.f);
        xs4[(ci * 6 + rr) * 16 + x4] = v;
    }
    __syncthreads();

    int cp = t >> 4, xg = t & 15;
    const u64* w1tu = (const u64*)w1t;

    u64 acc2[4][4];
#pragma unroll
    for (int rr = 0; rr < 4; rr++)
#pragma unroll
        for (int p = 0; p < 4; p++) acc2[rr][p] = 0ull;

    u64 wreg[9];
#pragma unroll
    for (int tap = 0; tap < 9; tap++)
        wreg[tap] = __ldg(w1tu + tap * 16 + cp);

    for (int ci = 0; ci < 128; ci++) {
        u64 wnxt[9];
        if (ci < 127) {
#pragma unroll
            for (int tap = 0; tap < 9; tap++)
                wnxt[tap] = __ldg(w1tu + ((ci + 1) * 9 + tap) * 16 + cp);
        }
#pragma unroll
        for (int iy = 0; iy < 6; iy++) {
            float4 c = xs4[(ci * 6 + iy) * 16 + xg];
            float l = __shfl_up_sync(0xffffffffu, c.w, 1);
            float r = __shfl_down_sync(0xffffffffu, c.x, 1);
            if (xg == 0)  l = 0.f;
            if (xg == 15) r = 0.f;
            u64 p[6];
            p[0] = pk2(l);   p[1] = pk2(c.x); p[2] = pk2(c.y);
            p[3] = pk2(c.z); p[4] = pk2(c.w); p[5] = pk2(r);
#pragma unroll
            for (int ky = 0; ky < 3; ky++) {
                int rr = iy - ky;
                if (rr < 0 || rr > 3) continue;
#pragma unroll
                for (int kx = 0; kx < 3; kx++) {
                    u64 wv = wreg[ky * 3 + kx];
                    fma2(acc2[rr][0], p[kx    ], wv);
                    fma2(acc2[rr][1], p[kx + 1], wv);
                    fma2(acc2[rr][2], p[kx + 2], wv);
                    fma2(acc2[rr][3], p[kx + 3], wv);
                }
            }
        }
#pragma unroll
        for (int tap = 0; tap < 9; tap++) wreg[tap] = wnxt[tap];
    }

#pragma unroll
    for (int rr = 0; rr < 4; rr++)
#pragma unroll
        for (int p = 0; p < 4; p++) {
            float2 v = upk(acc2[rr][p]);
            h_s[((2 * cp)     * 4 + rr) * 64 + xg * 4 + p] = fmaxf(v.x, 0.f);
            h_s[((2 * cp + 1) * 4 + rr) * 64 + xg * 4 + p] = fmaxf(v.y, 0.f);
        }
    __syncthreads();

    // phase 2: s = x + W2*h; either write to gmem, or stash relu(s) in smem.
    if (FUSE_PRE) {
        // stage pk2(pre_w) into wp2 (coalesced gmem read)
        for (int i = t; i < 8192; i += 256) {
            int d  = i >> 7;
            int ci = i & 127;
            wp2[ci * 64 + d] = pk2(__ldg(pre_w + d * 128 + ci));
        }
    }
    float4* xout4 = FUSE_PRE ? nullptr : (float4*)(xout + n * 128 * 4096);
#pragma unroll 2
    for (int k = 0; k < 32; k++) {
        int e   = k * 256 + t;
        int x4  = e & 15;
        int row = (e >> 4) & 3;
        int co  = e >> 6;
        int gi  = (co * 64 + oy0 + row) * 16 + x4;
        float4 s = xin4[gi];
        const float* wrow = w2g + co * 32;
#pragma unroll 8
        for (int ci = 0; ci < 32; ci++) {
            float wv = __ldg(wrow + ci);
            const float* hp = h_s + (ci * 4 + row) * 64 + x4 * 4;
            s.x += wv * hp[0]; s.y += wv * hp[1];
            s.z += wv * hp[2]; s.w += wv * hp[3];
        }
        if (FUSE_PRE) {
            s.x = fmaxf(s.x, 0.f); s.y = fmaxf(s.y, 0.f);
            s.z = fmaxf(s.z, 0.f); s.w = fmaxf(s.w, 0.f);
            s4[(co * 4 + row) * 16 + x4] = s;
        } else {
            xout4[gi] = s;
        }
    }

    if (FUSE_PRE) {
        __syncthreads();
        // phase 3: z_e[d] = pre_b[d] + sum_ci pre_w[d][ci] * relu(s[ci])
        int dd  = t >> 2;
        int row = t & 3;
        u64 acc[16][2];
        u64 binit = pk2(__ldg(pre_b + dd));
#pragma unroll
        for (int x4 = 0; x4 < 16; x4++) { acc[x4][0] = binit; acc[x4][1] = binit; }
        for (int ci = 0; ci < 128; ci++) {
            u64 wv = wp2[ci * 64 + dd];
            const ulonglong2* sp = (const ulonglong2*)(s4 + (ci * 4 + row) * 16);
#pragma unroll
            for (int x4 = 0; x4 < 16; x4++) {
                ulonglong2 sv = sp[x4];
                fma2(acc[x4][0], sv.x, wv);
                fma2(acc[x4][1], sv.y, wv);
            }
        }
        float4* ze4 = (float4*)(ze + n * 64 * 4096);
#pragma unroll
        for (int x4 = 0; x4 < 16; x4++) {
            float2 a = upk(acc[x4][0]);
            float2 b = upk(acc[x4][1]);
            float4 o; o.x = a.x; o.y = a.y; o.z = b.x; o.w = b.y;
            ze4[(dd * 64 + oy0 + row) * 16 + x4] = o;
        }
    }
}

// ---------------- fused decoder residual iteration (smem-resident stripe) -----
#define DSM_TOTAL 215040

__global__ void __launch_bounds__(256) decres_fused(
    const float* __restrict__ xin, const float* __restrict__ w1,
    const float* __restrict__ w2, float* __restrict__ xout)
{
    extern __shared__ unsigned char smraw[];
    float4* xs4   = (float4*)smraw;
    float*  sw1f  = (float*)(smraw + 196608);
    u64*    sw1u  = (u64*)  (smraw + 196608);
    float*  sw2   = (float*)(smraw + 205824);
    u64*    part  = (u64*)  (smraw + 206848);
    float*  h0    = (float*)(smraw + 212992);
    float*  h1    = (float*)(smraw + 214016);

    int t   = threadIdx.x;
    int by  = blockIdx.x;
    int n   = blockIdx.y;
    int oy0 = by * 4;

    for (int i = t; i < 2304; i += 256) {
        int ch = i & 1, r = i >> 1;
        sw1f[i] = w1[ch * 1152 + r];
    }
    if (t < 256) sw2[t] = w2[t];

    const float4* xin4 = (const float4*)(xin + n * 128 * 4096);
    for (int i = t; i < 12288; i += 256) {
        int x4 = i & 15;
        int rr = (i >> 4) % 6;
        int ci = i / 96;
        int gy = oy0 - 1 + rr;
        float4 v;
        if ((unsigned)gy < 64u) v = xin4[(ci * 64 + gy) * 16 + x4];
        else { v.x = v.y = v.z = v.w = 0.f; }
        xs4[i] = v;
    }
    __syncthreads();

    int g   = t >> 6;
    int t64 = t & 63;
    int row = t64 >> 4;
    int xg  = t64 & 15;

    u64 a[4] = {0ull, 0ull, 0ull, 0ull};
    for (int ci = g * 32; ci < g * 32 + 32; ci++) {
        const u64* wci = sw1u + ci * 9;
#pragma unroll
        for (int ky = 0; ky < 3; ky++) {
            float4 c = xs4[(ci * 6 + row + ky) * 16 + xg];
            float l = __shfl_up_sync(0xffffffffu, c.w, 1);
            float r = __shfl_down_sync(0xffffffffu, c.x, 1);
            if (xg == 0)  l = 0.f;
            if (xg == 15) r = 0.f;
            u64 pw[6];
            pw[0] = pk2(fmaxf(l,   0.f));
            pw[1] = pk2(fmaxf(c.x, 0.f));
            pw[2] = pk2(fmaxf(c.y, 0.f));
            pw[3] = pk2(fmaxf(c.z, 0.f));
            pw[4] = pk2(fmaxf(c.w, 0.f));
            pw[5] = pk2(fmaxf(r,   0.f));
#pragma unroll
            for (int kx = 0; kx < 3; kx++) {
                u64 wv = wci[ky * 3 + kx];
                fma2(a[0], pw[kx    ], wv);
                fma2(a[1], pw[kx + 1], wv);
                fma2(a[2], pw[kx + 2], wv);
                fma2(a[3], pw[kx + 3], wv);
            }
        }
    }
    if (g > 0) {
#pragma unroll
        for (int p = 0; p < 4; p++) part[(g - 1) * 256 + t64 * 4 + p] = a[p];
    }
    __syncthreads();
    if (t < 64) {
#pragma unroll
        for (int p = 0; p < 4; p++) {
            u64 s = a[p];
            s = add2(s, part[      t * 4 + p]);
            s = add2(s, part[256 + t * 4 + p]);
            s = add2(s, part[512 + t * 4 + p]);
            float2 v = upk(s);
            h0[row * 64 + xg * 4 + p] = fmaxf(v.x, 0.f);
            h1[row * 64 + xg * 4 + p] = fmaxf(v.y, 0.f);
        }
    }
    __syncthreads();

    float4* xout4 = (float4*)(xout + n * 128 * 4096);
#pragma unroll 4
    for (int k = 0; k < 32; k++) {
        int e   = k * 256 + t;
        int x4  = e & 15;
        int row2= (e >> 4) & 3;
        int co  = e >> 6;
        int gi = (co * 64 + oy0 + row2) * 16 + x4;
        float4 v = xs4[(co * 6 + row2 + 1) * 16 + x4];
        float w0 = sw2[co * 2], w1v = sw2[co * 2 + 1];
        const float* p0 = h0 + row2 * 64 + x4 * 4;
        const float* p1 = h1 + row2 * 64 + x4 * 4;
        v.x += w0 * p0[0] + w1v * p1[0];
        v.y += w0 * p0[1] + w1v * p1[1];
        v.z += w0 * p0[2] + w1v * p1[2];
        v.w += w0 * p0[3] + w1v * p1[3];
        xout4[gi] = v;
    }
}

// ---------------- vector quantizer -------------------------------------------
__global__ void __launch_bounds__(256) vq_kernel(
    const float* __restrict__ ze, const float* __restrict__ cb,
    float* __restrict__ zq, float* __restrict__ partials)
{
    __shared__ __align__(16) float f_s[64 * 64];
    __shared__ __align__(16) float cb_s[64 * 68];
    __shared__ float norm_s[512];
    __shared__ int   idx_s[64];
    __shared__ float red_s[64];

    int t = threadIdx.x;
    int b = blockIdx.x;
    int n = b >> 6, y = b & 63;

    for (int i = t; i < 4096; i += 256) {
        int d = i >> 6, x = i & 63;
        f_s[i] = ze[((n * 64 + d) * 64 + y) * 64 + x];
    }
    for (int c = t; c < 512; c += 256) {
        float s = 0.f;
        const float* cp = cb + c * 64;
#pragma unroll 8
        for (int d = 0; d < 64; d++) { float v = __ldg(cp + d); s = fmaf(v, v, s); }
        norm_s[c] = s;
    }
    __syncthreads();

    int cxT = t & 15, pyT = t >> 4;
    float best[4] = {3.4e38f, 3.4e38f, 3.4e38f, 3.4e38f};
    int   bidx[4] = {0, 0, 0, 0};

    for (int ch = 0; ch < 8; ch++) {
        __syncthreads();
        for (int i = t; i < 4096; i += 256) {
            int d = i & 63, c = i >> 6;
            cb_s[d * 68 + c] = __ldg(&cb[(ch * 64 + c) * 64 + d]);
        }
        __syncthreads();

        float dot[4][4];
#pragma unroll
        for (int pp = 0; pp < 4; pp++)
#pragma unroll
            for (int cc = 0; cc < 4; cc++) dot[pp][cc] = 0.f;

        for (int d = 0; d < 64; d++) {
            float4 fv4 = *(const float4*)&f_s[d * 64 + pyT * 4];
            float4 cv4 = *(const float4*)&cb_s[d * 68 + cxT * 4];
            float fv[4] = {fv4.x, fv4.y, fv4.z, fv4.w};
            float cv[4] = {cv4.x, cv4.y, cv4.z, cv4.w};
#pragma unroll
            for (int pp = 0; pp < 4; pp++)
#pragma unroll
                for (int cc = 0; cc < 4; cc++)
                    dot[pp][cc] = fmaf(fv[pp], cv[cc], dot[pp][cc]);
        }
#pragma unroll
        for (int cc = 0; cc < 4; cc++) {
            int code = ch * 64 + cxT * 4 + cc;
            float nrm = norm_s[code];
#pragma unroll
            for (int pp = 0; pp < 4; pp++) {
                float dist = fmaf(-2.f, dot[pp][cc], nrm);
                if (dist < best[pp]) { best[pp] = dist; bidx[pp] = code; }
            }
        }
    }

    for (int off = 1; off < 16; off <<= 1) {
#pragma unroll
        for (int pp = 0; pp < 4; pp++) {
            float ob = __shfl_xor_sync(0xffffffffu, best[pp], off);
            int   oi = __shfl_xor_sync(0xffffffffu, bidx[pp], off);
            if (ob < best[pp] || (ob == best[pp] && oi < bidx[pp])) {
                best[pp] = ob; bidx[pp] = oi;
            }
        }
    }
    if (cxT == 0)
#pragma unroll
        for (int pp = 0; pp < 4; pp++) idx_s[pyT * 4 + pp] = bidx[pp];
    __syncthreads();

    for (int i = t; i < 4096; i += 256) {
        int d = i >> 6, x = i & 63;
        zq[((n * 64 + d) * 64 + y) * 64 + x] = __ldg(&cb[idx_s[x] * 64 + d]);
    }

    if (t < 64) {
        int id = idx_s[t];
        const float* cp = cb + id * 64;
        float s = 0.f;
#pragma unroll 8
        for (int d = 0; d < 64; d++) {
            float diff = __ldg(cp + d) - f_s[d * 64 + t];
            s = fmaf(diff, diff, s);
        }
        red_s[t] = s;
    }
    __syncthreads();
    if (t == 0) {
        float s = 0.f;
        for (int i = 0; i < 64; i++) s += red_s[i];
        partials[b] = s;
    }
}

__global__ void __launch_bounds__(256) finalize_loss(
    const float* __restrict__ partials, float* __restrict__ dst)
{
    __shared__ float s[256];
    int t = threadIdx.x;
    float v = 0.f;
    for (int i = t; i < 1024; i += 256) v += partials[i];
    s[t] = v;
    __syncthreads();
    for (int off = 128; off > 0; off >>= 1) {
        if (t < off) s[t] += s[t + off];
        __syncthreads();
    }
    if (t == 0) dst[0] = 1.25f * s[0] / 4194304.f;  // (1 + BETA) * MSE
}

// ---------------- host launcher ----------------------------------------------
extern "C" void kernel_launch(void* const* d_in, const int* in_sizes, int n_in,
                              void* d_out, int out_size)
{
    (void)in_sizes; (void)n_in; (void)out_size;
    const float* x       = (const float*)d_in[0];
    const float* enc_w1  = (const float*)d_in[1];
    const float* enc_b1  = (const float*)d_in[2];
    const float* enc_w2  = (const float*)d_in[3];
    const float* enc_b2  = (const float*)d_in[4];
    const float* enc_w3  = (const float*)d_in[5];
    const float* enc_b3  = (const float*)d_in[6];
    const float* enc_rw1 = (const float*)d_in[7];
    const float* enc_rw2 = (const float*)d_in[8];
    const float* pre_w   = (const float*)d_in[9];
    const float* pre_b   = (const float*)d_in[10];
    const float* cb      = (const float*)d_in[11];
    const float* dec_wt1 = (const float*)d_in[12];
    const float* dec_bt1 = (const float*)d_in[13];
    const float* dec_rw1 = (const float*)d_in[14];
    const float* dec_rw2 = (const float*)d_in[15];
    const float* dec_wt2 = (const float*)d_in[16];
    const float* dec_bt2 = (const float*)d_in[17];
    const float* dec_wt3 = (const float*)d_in[18];
    const float* dec_bt3 = (const float*)d_in[19];
    float* out = (float*)d_out;

    float *pA, *pB, *pB2, *pC, *pE, *pF, *pW1T, *pPart;
    cudaGetSymbolAddress((void**)&pA,  g_A);
    cudaGetSymbolAddress((void**)&pB,  g_B);
    cudaGetSymbolAddress((void**)&pB2, g_B2);
    cudaGetSymbolAddress((void**)&pC,  g_C);
    cudaGetSymbolAddress((void**)&pE,  g_E);
    cudaGetSymbolAddress((void**)&pF,  g_F);
    cudaGetSymbolAddress((void**)&pW1T, g_W1T);
    cudaGetSymbolAddress((void**)&pPart, g_part);

    cudaFuncSetAttribute(decres_fused,
                         cudaFuncAttributeMaxDynamicSharedMemorySize, DSM_TOTAL);
    cudaFuncSetAttribute(encres_fused<false>,
                         cudaFuncAttributeMaxDynamicSharedMemorySize, ESM_TOTAL);
    cudaFuncSetAttribute(encres_fused<true>,
                         cudaFuncAttributeMaxDynamicSharedMemorySize, ESM_TOTAL);

    // encoder
    conv_fwd<4,2,false,false,4><<<dim3(2,16,16*8), 128>>>(
        x, enc_w1, enc_b1, nullptr, pA, 3, 64, 256, 256, 128, 128, 1, 8, 1);
    conv4s2_px8<<<dim3(1,4,16*16), 128>>>(pA, enc_w2, enc_b2, pB);
    conv3_rt<false,false><<<dim3(1,2,16*32), 128>>>(
        pB, enc_w3, enc_b3, pC, 128, 128, 0);

    // fused encoder res stack; iteration 2 also computes z_e (pre 1x1 fused)
    transpose_w1<<<144, 256>>>(enc_rw1, pW1T);
    encres_fused<false><<<dim3(16,16), 256, ESM_TOTAL>>>(
        pC, pW1T, enc_rw2, pB, nullptr, nullptr, nullptr);
    encres_fused<true><<<dim3(16,16), 256, ESM_TOTAL>>>(
        pB, pW1T, enc_rw2, nullptr, pre_w, pre_b, pE);

    // quantizer
    vq_kernel<<<1024, 256>>>(pE, cb, pF, pPart);
    finalize_loss<<<1, 256>>>(pPart, out + 3145728);

    // decoder
    conv3_rt<false,true><<<dim3(1,2,16*32), 128>>>(
        pF, dec_wt1, dec_bt1, pB, 64, 128, 0);
    for (int i = 0; i < 32; i++) {
        const float* src = (i & 1) ? pB2 : pB;
        float*       dst = (i & 1) ? pB  : pB2;
        decres_fused<<<dim3(16,16), 256, DSM_TOTAL>>>(src, dec_rw1, dec_rw2, dst);
    }
    // after 32 iters result is back in pB
    convt8_dec<<<dim3(2,8,16*8), 128>>>(pB, dec_wt2, dec_bt2, pA);
    convt_s2<2><<<dim3(4,32,16*1), 128>>>(
        pA, dec_wt3, dec_bt3, out, 64, 3, 128, 128, 1, 0, 0);
}